// round 7
// baseline (speedup 1.0000x reference)
#include <cuda_runtime.h>
#include <cuda_bf16.h>
#include <math.h>

// ---------------- problem constants ----------------
#define B_      2
#define F_      16
#define NJx     24
#define NPATCH  196          // 14*14
#define NSP     3136         // F_*NPATCH
#define NTOK    3160         // NJx + NSP
#define DIMC    512
#define ROWS    (B_*NTOK)    // 6320

// ---------------- scratch (device globals; no runtime alloc) ----------------
__device__ float g_x   [B_*NTOK*DIMC];
__device__ float g_xn  [B_*NTOK*DIMC];
__device__ float g_qkv [B_*NTOK*1536];
__device__ float g_attn[B_*NTOK*DIMC];
__device__ float g_h1  [(size_t)B_*NTOK*4096];
__device__ float g_hg  [(size_t)B_*NTOK*2048];
__device__ float g_tok [B_*NSP*DIMC];
__device__ float g_pat [B_*NSP*DIMC];
__device__ float g_sin [NPATCH*32];
__device__ float g_cos [NPATCH*32];
__device__ float g_jt  [48*DIMC];

// ---------------- block reductions (blockDim.x == 256) ----------------
__device__ __forceinline__ float warp_sum(float v) {
    #pragma unroll
    for (int o = 16; o > 0; o >>= 1) v += __shfl_xor_sync(0xffffffffu, v, o);
    return v;
}
__device__ __forceinline__ float warp_max(float v) {
    #pragma unroll
    for (int o = 16; o > 0; o >>= 1) v = fmaxf(v, __shfl_xor_sync(0xffffffffu, v, o));
    return v;
}
__device__ __forceinline__ float block_sum(float v, float* red) {
    v = warp_sum(v);
    int lane = threadIdx.x & 31, w = threadIdx.x >> 5;
    if (lane == 0) red[w] = v;
    __syncthreads();
    if (threadIdx.x < 32) {
        float r = (threadIdx.x < 8) ? red[threadIdx.x] : 0.f;
        r = warp_sum(r);
        if (threadIdx.x == 0) red[0] = r;
    }
    __syncthreads();
    float out = red[0];
    __syncthreads();
    return out;
}
__device__ __forceinline__ float block_max(float v, float* red) {
    v = warp_max(v);
    int lane = threadIdx.x & 31, w = threadIdx.x >> 5;
    if (lane == 0) red[w] = v;
    __syncthreads();
    if (threadIdx.x < 32) {
        float r = (threadIdx.x < 8) ? red[threadIdx.x] : -INFINITY;
        r = warp_max(r);
        if (threadIdx.x == 0) red[0] = r;
    }
    __syncthreads();
    float out = red[0];
    __syncthreads();
    return out;
}

// ---------------- SGEMM: C = A(MxK) @ B(KxN) [+bias] [+res], row-major ----------------
// 128x128 tile, BK=8, 256 threads, 8x8 per thread (4+4 split-register mapping).
template<int BIAS, int RES>
__global__ __launch_bounds__(256) void k_sgemm(
    const float* __restrict__ A, const float* __restrict__ B,
    const float* __restrict__ bias, const float* __restrict__ res,
    float* __restrict__ C, int M, int N, int K)
{
    __shared__ float As[8][128];
    __shared__ float Bs[8][128];
    int tid = threadIdx.x;
    int bm = blockIdx.y * 128;
    int bn = blockIdx.x * 128;
    int tx = tid & 15, ty = tid >> 4;
    int ar = tid >> 1, ac = (tid & 1) * 4;
    int br = tid >> 5, bc = (tid & 31) * 4;

    float acc[8][8];
    #pragma unroll
    for (int i = 0; i < 8; i++)
        #pragma unroll
        for (int j = 0; j < 8; j++) acc[i][j] = 0.f;

    bool aval = (bm + ar) < M;
    const float* Aptr = A + (size_t)(bm + ar) * K + ac;
    const float* Bptr = B + (size_t)br * N + bn + bc;

    for (int k0 = 0; k0 < K; k0 += 8) {
        float4 av = make_float4(0.f, 0.f, 0.f, 0.f);
        if (aval) av = *reinterpret_cast<const float4*>(Aptr + k0);
        As[ac + 0][ar] = av.x; As[ac + 1][ar] = av.y;
        As[ac + 2][ar] = av.z; As[ac + 3][ar] = av.w;
        float4 bv = *reinterpret_cast<const float4*>(Bptr + (size_t)k0 * N);
        *reinterpret_cast<float4*>(&Bs[br][bc]) = bv;
        __syncthreads();
        #pragma unroll
        for (int kk = 0; kk < 8; kk++) {
            float af[8], bf[8];
            *reinterpret_cast<float4*>(&af[0]) = *reinterpret_cast<const float4*>(&As[kk][ty * 4]);
            *reinterpret_cast<float4*>(&af[4]) = *reinterpret_cast<const float4*>(&As[kk][64 + ty * 4]);
            *reinterpret_cast<float4*>(&bf[0]) = *reinterpret_cast<const float4*>(&Bs[kk][tx * 4]);
            *reinterpret_cast<float4*>(&bf[4]) = *reinterpret_cast<const float4*>(&Bs[kk][64 + tx * 4]);
            #pragma unroll
            for (int i = 0; i < 8; i++)
                #pragma unroll
                for (int j = 0; j < 8; j++)
                    acc[i][j] = fmaf(af[i], bf[j], acc[i][j]);
        }
        __syncthreads();
    }

    #pragma unroll
    for (int i = 0; i < 8; i++) {
        int row = bm + ((i < 4) ? (ty * 4 + i) : (64 + ty * 4 + i - 4));
        if (row >= M) continue;
        #pragma unroll
        for (int jh = 0; jh < 2; jh++) {
            int col = bn + ((jh == 0) ? (tx * 4) : (64 + tx * 4));
            float4 v;
            v.x = acc[i][jh * 4 + 0]; v.y = acc[i][jh * 4 + 1];
            v.z = acc[i][jh * 4 + 2]; v.w = acc[i][jh * 4 + 3];
            if (BIAS) {
                float4 b4 = *reinterpret_cast<const float4*>(bias + col);
                v.x += b4.x; v.y += b4.y; v.z += b4.z; v.w += b4.w;
            }
            if (RES) {
                float4 r4 = *reinterpret_cast<const float4*>(res + (size_t)row * N + col);
                v.x += r4.x; v.y += r4.y; v.z += r4.z; v.w += r4.w;
            }
            *reinterpret_cast<float4*>(C + (size_t)row * N + col) = v;
        }
    }
}

// ---------------- rotary tables ----------------
__global__ void k_sincos() {
    int idx = blockIdx.x * blockDim.x + threadIdx.x;
    if (idx >= NPATCH * 32) return;
    int p = idx >> 5, s = idx & 31;
    int ph = p / 14, pw = p % 14;
    int ss = (s < 16) ? s : (s - 16);
    float scale = exp2f((float)ss * (2.321928094887362f / 15.f));  // 2^(ss*log2(5)/15)
    int pos_i = (s < 16) ? ph : pw;
    float pos = -1.f + 2.f * (float)pos_i / 13.f;
    float ang = pos * scale * 3.14159265358979323846f;
    g_sin[idx] = sinf(ang);
    g_cos[idx] = cosf(ang);
}

// ---------------- patch extraction (im2col) ----------------
__global__ void k_im2col(const float* __restrict__ video) {
    size_t idx = (size_t)blockIdx.x * blockDim.x + threadIdx.x;
    if (idx >= (size_t)B_ * NSP * DIMC) return;
    int e = (int)(idx & 511);
    size_t r = idx >> 9;
    int bb = (int)(r / NSP); int t = (int)(r % NSP);
    int fr = t / NPATCH; int pp = t % NPATCH;
    int ph = pp / 14, pw = pp % 14;
    int py = e >> 5, px = (e >> 1) & 15, cc = e & 1;
    size_t vidx = ((((size_t)(bb * F_ + fr) * 2 + cc) * 224 + (ph * 16 + py)) * 224 + (pw * 16 + px));
    g_pat[idx] = video[vidx];
}

// ---------------- token assembly: x = [joints_token ; tokens] ----------------
__global__ void k_assemble(const float* __restrict__ joints_token) {
    size_t idx = (size_t)blockIdx.x * blockDim.x + threadIdx.x;
    if (idx >= (size_t)B_ * NTOK * DIMC) return;
    int col = (int)(idx & 511);
    size_t r = idx >> 9;
    int bb = (int)(r / NTOK); int i = (int)(r % NTOK);
    g_x[idx] = (i < NJx) ? joints_token[i * DIMC + col]
                         : g_tok[((size_t)bb * NSP + (i - NJx)) * DIMC + col];
}

// ---------------- LayerNorm (512-wide rows) ----------------
__global__ __launch_bounds__(256) void k_ln(const float* __restrict__ in,
                                            const float* __restrict__ w,
                                            const float* __restrict__ b,
                                            float* __restrict__ out) {
    __shared__ float red[32];
    int row = blockIdx.x;
    int t = threadIdx.x;
    const float* ri = in + (size_t)row * DIMC;
    float v0 = ri[t], v1 = ri[t + 256];
    float mean = block_sum(v0 + v1, red) * (1.f / 512.f);
    float d0 = v0 - mean, d1 = v1 - mean;
    float var = block_sum(d0 * d0 + d1 * d1, red) * (1.f / 512.f);
    float rs = rsqrtf(var + 1e-5f);
    float* ro = out + (size_t)row * DIMC;
    ro[t]       = d0 * rs * w[t]       + b[t];
    ro[t + 256] = d1 * rs * w[t + 256] + b[t + 256];
}

// final LN on joint tokens, gathering 48 rows out of g_x -> g_jt (48x512)
__global__ __launch_bounds__(256) void k_ln_gather(const float* __restrict__ w,
                                                   const float* __restrict__ b) {
    __shared__ float red[32];
    int row = blockIdx.x;               // 0..47
    int bb = row / NJx, i = row % NJx;
    int t = threadIdx.x;
    const float* ri = g_x + ((size_t)bb * NTOK + i) * DIMC;
    float v0 = ri[t], v1 = ri[t + 256];
    float mean = block_sum(v0 + v1, red) * (1.f / 512.f);
    float d0 = v0 - mean, d1 = v1 - mean;
    float var = block_sum(d0 * d0 + d1 * d1, red) * (1.f / 512.f);
    float rs = rsqrtf(var + 1e-5f);
    float* ro = g_jt + (size_t)row * DIMC;
    ro[t]       = d0 * rs * w[t]       + b[t];
    ro[t + 256] = d1 * rs * w[t + 256] + b[t + 256];
}

// ---------------- joints attention (runs BEFORE rope; keys/values un-rotated) ----------------
// grid: B_*8*NJx blocks. q scaled by 0.125 inline.
__global__ __launch_bounds__(256) void k_joints_attn() {
    __shared__ float sq[64];
    __shared__ float s[NTOK];
    __shared__ float red[32];
    __shared__ float sacc[4][64];
    int bidx = blockIdx.x;
    int jq = bidx % NJx;
    int h  = (bidx / NJx) & 7;
    int bb = bidx / (NJx * 8);
    int t = threadIdx.x;
    const float* qp = g_qkv + ((size_t)(bb * NTOK + jq)) * 1536 + h * 64;
    if (t < 64) sq[t] = qp[t] * 0.125f;
    __syncthreads();
    for (int j = t; j < NTOK; j += 256) {
        const float* kp = g_qkv + ((size_t)(bb * NTOK + j)) * 1536 + 512 + h * 64;
        float acc = 0.f;
        #pragma unroll
        for (int d = 0; d < 64; d += 4) {
            float4 kv = *reinterpret_cast<const float4*>(kp + d);
            acc += sq[d] * kv.x + sq[d + 1] * kv.y + sq[d + 2] * kv.z + sq[d + 3] * kv.w;
        }
        s[j] = acc;
    }
    __syncthreads();
    float m = -INFINITY;
    for (int j = t; j < NTOK; j += 256) m = fmaxf(m, s[j]);
    m = block_max(m, red);
    float lsum = 0.f;
    for (int j = t; j < NTOK; j += 256) { float e = expf(s[j] - m); s[j] = e; lsum += e; }
    float denom = block_sum(lsum, red);
    float inv = 1.f / denom;
    int d = t & 63, c = t >> 6;
    float acc = 0.f;
    for (int j = c; j < NTOK; j += 4)
        acc += s[j] * g_qkv[((size_t)(bb * NTOK + j)) * 1536 + 1024 + h * 64 + d];
    sacc[c][d] = acc;
    __syncthreads();
    if (t < 64) {
        float o = (sacc[0][t] + sacc[1][t] + sacc[2][t] + sacc[3][t]) * inv;
        g_attn[((size_t)(bb * NTOK + jq)) * 512 + h * 64 + t] = o;
    }
}

// ---------------- rope + q-scale (in place on qkv; spatial tokens rotated) ----------------
__global__ void k_rope() {
    int idx = blockIdx.x * blockDim.x + threadIdx.x;
    if (idx >= B_ * NTOK * 8 * 32) return;
    int s = idx & 31;
    int h = (idx >> 5) & 7;
    int rest = idx >> 8;
    int i = rest % NTOK;
    int bb = rest / NTOK;
    size_t base = ((size_t)(bb * NTOK + i)) * 1536 + h * 64 + 2 * s;
    float q0 = g_qkv[base] * 0.125f, q1 = g_qkv[base + 1] * 0.125f;
    if (i >= NJx) {
        int p = (i - NJx) % NPATCH;
        float c = g_cos[p * 32 + s], sn = g_sin[p * 32 + s];
        float nq0 = q0 * c - q1 * sn, nq1 = q1 * c + q0 * sn;
        q0 = nq0; q1 = nq1;
        float k0 = g_qkv[base + 512], k1 = g_qkv[base + 513];
        g_qkv[base + 512] = k0 * c - k1 * sn;
        g_qkv[base + 513] = k1 * c + k0 * sn;
    }
    g_qkv[base] = q0; g_qkv[base + 1] = q1;
}

// ---------------- per-frame attention: 196 queries x (24 joint + 196 frame) keys ----------------
// grid (196, 256): x = query index, y = group (bb,h,fr)
__global__ __launch_bounds__(256) void k_frame_attn() {
    __shared__ float sq[64];
    __shared__ float s[224];
    __shared__ float red[32];
    __shared__ float sacc[4][64];
    int i = blockIdx.x;
    int g = blockIdx.y;
    int fr = g & 15;
    int bh = g >> 4;
    int h = bh & 7;
    int bb = bh >> 3;
    int t = threadIdx.x;
    int ti = NJx + fr * NPATCH + i;
    const float* qp = g_qkv + ((size_t)(bb * NTOK + ti)) * 1536 + h * 64;
    if (t < 64) sq[t] = qp[t];
    __syncthreads();
    if (t < 220) {
        int tj = (t < NJx) ? t : NJx + fr * NPATCH + (t - NJx);
        const float* kp = g_qkv + ((size_t)(bb * NTOK + tj)) * 1536 + 512 + h * 64;
        float acc = 0.f;
        #pragma unroll
        for (int d = 0; d < 64; d += 4) {
            float4 kv = *reinterpret_cast<const float4*>(kp + d);
            acc += sq[d] * kv.x + sq[d + 1] * kv.y + sq[d + 2] * kv.z + sq[d + 3] * kv.w;
        }
        s[t] = acc;
    }
    __syncthreads();
    float m = (t < 220) ? s[t] : -INFINITY;
    m = block_max(m, red);
    float e = 0.f;
    if (t < 220) { e = expf(s[t] - m); s[t] = e; }
    float denom = block_sum(e, red);
    float inv = 1.f / denom;
    int d = t & 63, c = t >> 6;
    float acc = 0.f;
    for (int j = c; j < 220; j += 4) {
        int tj = (j < NJx) ? j : NJx + fr * NPATCH + (j - NJx);
        acc += s[j] * g_qkv[((size_t)(bb * NTOK + tj)) * 1536 + 1024 + h * 64 + d];
    }
    sacc[c][d] = acc;
    __syncthreads();
    if (t < 64) {
        float o = (sacc[0][t] + sacc[1][t] + sacc[2][t] + sacc[3][t]) * inv;
        g_attn[((size_t)(bb * NTOK + ti)) * 512 + h * 64 + t] = o;
    }
}

// ---------------- GEGLU: hg = a * gelu_exact(g) ----------------
__global__ void k_geglu() {
    size_t idx = (size_t)blockIdx.x * blockDim.x + threadIdx.x;
    if (idx >= (size_t)ROWS * 2048) return;
    size_t r = idx >> 11;
    int j = (int)(idx & 2047);
    float a = g_h1[r * 4096 + j];
    float g = g_h1[r * 4096 + 2048 + j];
    float ge = 0.5f * g * (1.f + erff(g * 0.7071067811865476f));
    g_hg[idx] = a * ge;
}

// ---------------- host-side helpers ----------------
static void launch_sgemm(const float* A, const float* Bm, const float* bias,
                         const float* res, float* C, int M, int N, int K,
                         bool withBias, bool withRes) {
    dim3 grid(N / 128, (M + 127) / 128);
    if (withBias && withRes)
        k_sgemm<1, 1><<<grid, 256>>>(A, Bm, bias, res, C, M, N, K);
    else if (withBias)
        k_sgemm<1, 0><<<grid, 256>>>(A, Bm, bias, nullptr, C, M, N, K);
    else
        k_sgemm<0, 0><<<grid, 256>>>(A, Bm, nullptr, nullptr, C, M, N, K);
}

extern "C" void kernel_launch(void* const* d_in, const int* in_sizes, int n_in,
                              void* d_out, int out_size) {
    const float* video        = (const float*)d_in[0];
    const float* patch_w      = (const float*)d_in[1];
    const float* patch_b      = (const float*)d_in[2];
    const float* joints_token = (const float*)d_in[3];
    const float* ln_attn_w    = (const float*)d_in[4];
    const float* ln_attn_b    = (const float*)d_in[5];
    const float* qkv_w        = (const float*)d_in[6];
    const float* attn_out_w   = (const float*)d_in[7];
    const float* attn_out_b   = (const float*)d_in[8];
    const float* ln_ff_w      = (const float*)d_in[9];
    const float* ln_ff_b      = (const float*)d_in[10];
    const float* ff1_w        = (const float*)d_in[11];
    const float* ff1_b        = (const float*)d_in[12];
    const float* ff2_w        = (const float*)d_in[13];
    const float* ff2_b        = (const float*)d_in[14];
    const float* ln_out_w     = (const float*)d_in[15];
    const float* ln_out_b     = (const float*)d_in[16];
    const float* out_w        = (const float*)d_in[17];
    const float* out_b        = (const float*)d_in[18];

    float *px, *pxn, *pqkv, *pattn, *ph1, *phg, *ptok, *ppat, *pjt;
    cudaGetSymbolAddress((void**)&px,    g_x);
    cudaGetSymbolAddress((void**)&pxn,   g_xn);
    cudaGetSymbolAddress((void**)&pqkv,  g_qkv);
    cudaGetSymbolAddress((void**)&pattn, g_attn);
    cudaGetSymbolAddress((void**)&ph1,   g_h1);
    cudaGetSymbolAddress((void**)&phg,   g_hg);
    cudaGetSymbolAddress((void**)&ptok,  g_tok);
    cudaGetSymbolAddress((void**)&ppat,  g_pat);
    cudaGetSymbolAddress((void**)&pjt,   g_jt);

    // setup: rotary tables, patchify, patch embed, assemble token stream
    k_sincos<<<(NPATCH * 32 + 255) / 256, 256>>>();
    k_im2col<<<(B_ * NSP * DIMC + 255) / 256, 256>>>(video);
    launch_sgemm(ppat, patch_w, patch_b, nullptr, ptok, B_ * NSP, DIMC, DIMC, true, false);
    k_assemble<<<(B_ * NTOK * DIMC + 255) / 256, 256>>>(joints_token);

    for (int l = 0; l < 12; l++) {
        k_ln<<<ROWS, 256>>>(px, ln_attn_w + l * 512, ln_attn_b + l * 512, pxn);
        launch_sgemm(pxn, qkv_w + (size_t)l * 512 * 1536, nullptr, nullptr,
                     pqkv, ROWS, 1536, 512, false, false);
        k_joints_attn<<<B_ * 8 * NJx, 256>>>();                 // pre-rope keys/values
        k_rope<<<(B_ * NTOK * 8 * 32 + 255) / 256, 256>>>();    // scale q, rotate spatial q/k
        k_frame_attn<<<dim3(NPATCH, B_ * 8 * F_), 256>>>();
        launch_sgemm(pattn, attn_out_w + (size_t)l * 512 * 512, attn_out_b + l * 512,
                     px, px, ROWS, 512, 512, true, true);       // x += proj(attn)
        k_ln<<<ROWS, 256>>>(px, ln_ff_w + l * 512, ln_ff_b + l * 512, pxn);
        launch_sgemm(pxn, ff1_w + (size_t)l * 512 * 4096, ff1_b + (size_t)l * 4096, nullptr,
                     ph1, ROWS, 4096, 512, true, false);
        k_geglu<<<(int)(((size_t)ROWS * 2048 + 255) / 256), 256>>>();
        launch_sgemm(phg, ff2_w + (size_t)l * 2048 * 512, ff2_b + l * 512,
                     px, px, ROWS, 512, 2048, true, true);      // x += ff2(hg)
    }

    // head: LN over joint tokens, final projection -> (2,24,4,96) contiguous
    k_ln_gather<<<48, 256>>>(ln_out_w, ln_out_b);
    launch_sgemm(pjt, out_w, out_b, nullptr, (float*)d_out, 48, 384, 512, true, false);
}

// round 8
// speedup vs baseline: 1.5934x; 1.5934x over previous
#include <cuda_runtime.h>
#include <cuda_bf16.h>
#include <math.h>

// ---------------- problem constants ----------------
#define B_      2
#define F_      16
#define NJx     24
#define NPATCH  196          // 14*14
#define NSP     3136         // F_*NPATCH
#define NTOK    3160         // NJx + NSP
#define DIMC    512
#define ROWS    (B_*NTOK)    // 6320

// ---------------- scratch (device globals; no runtime alloc) ----------------
__device__ float g_x   [B_*NTOK*DIMC];
__device__ float g_xn  [B_*NTOK*DIMC];
__device__ float g_qkv [B_*NTOK*1536];
__device__ float g_attn[B_*NTOK*DIMC];
__device__ float g_h1  [(size_t)B_*NTOK*4096];
__device__ float g_hg  [(size_t)B_*NTOK*2048];
__device__ float g_tok [B_*NSP*DIMC];
__device__ float g_pat [B_*NSP*DIMC];
__device__ float g_sin [NPATCH*32];
__device__ float g_cos [NPATCH*32];
__device__ float g_jt  [48*DIMC];

// ---------------- block reductions (blockDim.x == 256) ----------------
__device__ __forceinline__ float warp_sum(float v) {
    #pragma unroll
    for (int o = 16; o > 0; o >>= 1) v += __shfl_xor_sync(0xffffffffu, v, o);
    return v;
}
__device__ __forceinline__ float warp_max(float v) {
    #pragma unroll
    for (int o = 16; o > 0; o >>= 1) v = fmaxf(v, __shfl_xor_sync(0xffffffffu, v, o));
    return v;
}
__device__ __forceinline__ float block_sum(float v, float* red) {
    v = warp_sum(v);
    int lane = threadIdx.x & 31, w = threadIdx.x >> 5;
    if (lane == 0) red[w] = v;
    __syncthreads();
    if (threadIdx.x < 32) {
        float r = (threadIdx.x < 8) ? red[threadIdx.x] : 0.f;
        r = warp_sum(r);
        if (threadIdx.x == 0) red[0] = r;
    }
    __syncthreads();
    float out = red[0];
    __syncthreads();
    return out;
}
__device__ __forceinline__ float block_max(float v, float* red) {
    v = warp_max(v);
    int lane = threadIdx.x & 31, w = threadIdx.x >> 5;
    if (lane == 0) red[w] = v;
    __syncthreads();
    if (threadIdx.x < 32) {
        float r = (threadIdx.x < 8) ? red[threadIdx.x] : -INFINITY;
        r = warp_max(r);
        if (threadIdx.x == 0) red[0] = r;
    }
    __syncthreads();
    float out = red[0];
    __syncthreads();
    return out;
}

// ---------------- SGEMM: C = A(MxK) @ B(KxN) [+bias] [+res], row-major ----------------
// 128x128 tile, BK=8, 256 threads, 8x8 per thread (4+4 split-register mapping).
template<int BIAS, int RES>
__global__ __launch_bounds__(256) void k_sgemm(
    const float* __restrict__ A, const float* __restrict__ B,
    const float* __restrict__ bias, const float* __restrict__ res,
    float* __restrict__ C, int M, int N, int K)
{
    __shared__ float As[8][128];
    __shared__ float Bs[8][128];
    int tid = threadIdx.x;
    int bm = blockIdx.y * 128;
    int bn = blockIdx.x * 128;
    int tx = tid & 15, ty = tid >> 4;
    int ar = tid >> 1, ac = (tid & 1) * 4;
    int br = tid >> 5, bc = (tid & 31) * 4;

    float acc[8][8];
    #pragma unroll
    for (int i = 0; i < 8; i++)
        #pragma unroll
        for (int j = 0; j < 8; j++) acc[i][j] = 0.f;

    bool aval = (bm + ar) < M;
    const float* Aptr = A + (size_t)(bm + ar) * K + ac;
    const float* Bptr = B + (size_t)br * N + bn + bc;

    for (int k0 = 0; k0 < K; k0 += 8) {
        float4 av = make_float4(0.f, 0.f, 0.f, 0.f);
        if (aval) av = *reinterpret_cast<const float4*>(Aptr + k0);
        As[ac + 0][ar] = av.x; As[ac + 1][ar] = av.y;
        As[ac + 2][ar] = av.z; As[ac + 3][ar] = av.w;
        float4 bv = *reinterpret_cast<const float4*>(Bptr + (size_t)k0 * N);
        *reinterpret_cast<float4*>(&Bs[br][bc]) = bv;
        __syncthreads();
        #pragma unroll
        for (int kk = 0; kk < 8; kk++) {
            float af[8], bf[8];
            *reinterpret_cast<float4*>(&af[0]) = *reinterpret_cast<const float4*>(&As[kk][ty * 4]);
            *reinterpret_cast<float4*>(&af[4]) = *reinterpret_cast<const float4*>(&As[kk][64 + ty * 4]);
            *reinterpret_cast<float4*>(&bf[0]) = *reinterpret_cast<const float4*>(&Bs[kk][tx * 4]);
            *reinterpret_cast<float4*>(&bf[4]) = *reinterpret_cast<const float4*>(&Bs[kk][64 + tx * 4]);
            #pragma unroll
            for (int i = 0; i < 8; i++)
                #pragma unroll
                for (int j = 0; j < 8; j++)
                    acc[i][j] = fmaf(af[i], bf[j], acc[i][j]);
        }
        __syncthreads();
    }

    #pragma unroll
    for (int i = 0; i < 8; i++) {
        int row = bm + ((i < 4) ? (ty * 4 + i) : (64 + ty * 4 + i - 4));
        if (row >= M) continue;
        #pragma unroll
        for (int jh = 0; jh < 2; jh++) {
            int col = bn + ((jh == 0) ? (tx * 4) : (64 + tx * 4));
            float4 v;
            v.x = acc[i][jh * 4 + 0]; v.y = acc[i][jh * 4 + 1];
            v.z = acc[i][jh * 4 + 2]; v.w = acc[i][jh * 4 + 3];
            if (BIAS) {
                float4 b4 = *reinterpret_cast<const float4*>(bias + col);
                v.x += b4.x; v.y += b4.y; v.z += b4.z; v.w += b4.w;
            }
            if (RES) {
                float4 r4 = *reinterpret_cast<const float4*>(res + (size_t)row * N + col);
                v.x += r4.x; v.y += r4.y; v.z += r4.z; v.w += r4.w;
            }
            *reinterpret_cast<float4*>(C + (size_t)row * N + col) = v;
        }
    }
}

// ---------------- rotary tables ----------------
__global__ void k_sincos() {
    int idx = blockIdx.x * blockDim.x + threadIdx.x;
    if (idx >= NPATCH * 32) return;
    int p = idx >> 5, s = idx & 31;
    int ph = p / 14, pw = p % 14;
    int ss = (s < 16) ? s : (s - 16);
    float scale = exp2f((float)ss * (2.321928094887362f / 15.f));  // 2^(ss*log2(5)/15)
    int pos_i = (s < 16) ? ph : pw;
    float pos = -1.f + 2.f * (float)pos_i / 13.f;
    float ang = pos * scale * 3.14159265358979323846f;
    g_sin[idx] = sinf(ang);
    g_cos[idx] = cosf(ang);
}

// ---------------- patch extraction (im2col) ----------------
__global__ void k_im2col(const float* __restrict__ video) {
    size_t idx = (size_t)blockIdx.x * blockDim.x + threadIdx.x;
    if (idx >= (size_t)B_ * NSP * DIMC) return;
    int e = (int)(idx & 511);
    size_t r = idx >> 9;
    int bb = (int)(r / NSP); int t = (int)(r % NSP);
    int fr = t / NPATCH; int pp = t % NPATCH;
    int ph = pp / 14, pw = pp % 14;
    int py = e >> 5, px = (e >> 1) & 15, cc = e & 1;
    size_t vidx = ((((size_t)(bb * F_ + fr) * 2 + cc) * 224 + (ph * 16 + py)) * 224 + (pw * 16 + px));
    g_pat[idx] = video[vidx];
}

// ---------------- token assembly: x = [joints_token ; tokens] ----------------
__global__ void k_assemble(const float* __restrict__ joints_token) {
    size_t idx = (size_t)blockIdx.x * blockDim.x + threadIdx.x;
    if (idx >= (size_t)B_ * NTOK * DIMC) return;
    int col = (int)(idx & 511);
    size_t r = idx >> 9;
    int bb = (int)(r / NTOK); int i = (int)(r % NTOK);
    g_x[idx] = (i < NJx) ? joints_token[i * DIMC + col]
                         : g_tok[((size_t)bb * NSP + (i - NJx)) * DIMC + col];
}

// ---------------- LayerNorm (512-wide rows) ----------------
__global__ __launch_bounds__(256) void k_ln(const float* __restrict__ in,
                                            const float* __restrict__ w,
                                            const float* __restrict__ b,
                                            float* __restrict__ out) {
    __shared__ float red[32];
    int row = blockIdx.x;
    int t = threadIdx.x;
    const float* ri = in + (size_t)row * DIMC;
    float v0 = ri[t], v1 = ri[t + 256];
    float mean = block_sum(v0 + v1, red) * (1.f / 512.f);
    float d0 = v0 - mean, d1 = v1 - mean;
    float var = block_sum(d0 * d0 + d1 * d1, red) * (1.f / 512.f);
    float rs = rsqrtf(var + 1e-5f);
    float* ro = out + (size_t)row * DIMC;
    ro[t]       = d0 * rs * w[t]       + b[t];
    ro[t + 256] = d1 * rs * w[t + 256] + b[t + 256];
}

// final LN on joint tokens, gathering 48 rows out of g_x -> g_jt (48x512)
__global__ __launch_bounds__(256) void k_ln_gather(const float* __restrict__ w,
                                                   const float* __restrict__ b) {
    __shared__ float red[32];
    int row = blockIdx.x;               // 0..47
    int bb = row / NJx, i = row % NJx;
    int t = threadIdx.x;
    const float* ri = g_x + ((size_t)bb * NTOK + i) * DIMC;
    float v0 = ri[t], v1 = ri[t + 256];
    float mean = block_sum(v0 + v1, red) * (1.f / 512.f);
    float d0 = v0 - mean, d1 = v1 - mean;
    float var = block_sum(d0 * d0 + d1 * d1, red) * (1.f / 512.f);
    float rs = rsqrtf(var + 1e-5f);
    float* ro = g_jt + (size_t)row * DIMC;
    ro[t]       = d0 * rs * w[t]       + b[t];
    ro[t + 256] = d1 * rs * w[t + 256] + b[t + 256];
}

// ---------------- joints attention (runs BEFORE rope; keys/values un-rotated) ----------------
// grid: B_*8*NJx blocks. q scaled by 0.125 inline.
__global__ __launch_bounds__(256) void k_joints_attn() {
    __shared__ float sq[64];
    __shared__ float s[NTOK];
    __shared__ float red[32];
    __shared__ float sacc[4][64];
    int bidx = blockIdx.x;
    int jq = bidx % NJx;
    int h  = (bidx / NJx) & 7;
    int bb = bidx / (NJx * 8);
    int t = threadIdx.x;
    const float* qp = g_qkv + ((size_t)(bb * NTOK + jq)) * 1536 + h * 64;
    if (t < 64) sq[t] = qp[t] * 0.125f;
    __syncthreads();
    for (int j = t; j < NTOK; j += 256) {
        const float* kp = g_qkv + ((size_t)(bb * NTOK + j)) * 1536 + 512 + h * 64;
        float acc = 0.f;
        #pragma unroll
        for (int d = 0; d < 64; d += 4) {
            float4 kv = *reinterpret_cast<const float4*>(kp + d);
            acc += sq[d] * kv.x + sq[d + 1] * kv.y + sq[d + 2] * kv.z + sq[d + 3] * kv.w;
        }
        s[j] = acc;
    }
    __syncthreads();
    float m = -INFINITY;
    for (int j = t; j < NTOK; j += 256) m = fmaxf(m, s[j]);
    m = block_max(m, red);
    float lsum = 0.f;
    for (int j = t; j < NTOK; j += 256) { float e = expf(s[j] - m); s[j] = e; lsum += e; }
    float denom = block_sum(lsum, red);
    float inv = 1.f / denom;
    int d = t & 63, c = t >> 6;
    float acc = 0.f;
    for (int j = c; j < NTOK; j += 4)
        acc += s[j] * g_qkv[((size_t)(bb * NTOK + j)) * 1536 + 1024 + h * 64 + d];
    sacc[c][d] = acc;
    __syncthreads();
    if (t < 64) {
        float o = (sacc[0][t] + sacc[1][t] + sacc[2][t] + sacc[3][t]) * inv;
        g_attn[((size_t)(bb * NTOK + jq)) * 512 + h * 64 + t] = o;
    }
}

// ---------------- rope + q-scale (in place on qkv; spatial tokens rotated) ----------------
__global__ void k_rope() {
    int idx = blockIdx.x * blockDim.x + threadIdx.x;
    if (idx >= B_ * NTOK * 8 * 32) return;
    int s = idx & 31;
    int h = (idx >> 5) & 7;
    int rest = idx >> 8;
    int i = rest % NTOK;
    int bb = rest / NTOK;
    size_t base = ((size_t)(bb * NTOK + i)) * 1536 + h * 64 + 2 * s;
    float q0 = g_qkv[base] * 0.125f, q1 = g_qkv[base + 1] * 0.125f;
    if (i >= NJx) {
        int p = (i - NJx) % NPATCH;
        float c = g_cos[p * 32 + s], sn = g_sin[p * 32 + s];
        float nq0 = q0 * c - q1 * sn, nq1 = q1 * c + q0 * sn;
        q0 = nq0; q1 = nq1;
        float k0 = g_qkv[base + 512], k1 = g_qkv[base + 513];
        g_qkv[base + 512] = k0 * c - k1 * sn;
        g_qkv[base + 513] = k1 * c + k0 * sn;
    }
    g_qkv[base] = q0; g_qkv[base + 1] = q1;
}

// ---------------- per-frame attention: 196 queries x (24 joint + 196 frame) keys ----------------
// grid (196, 256): x = query index, y = group (bb,h,fr)
__global__ __launch_bounds__(256) void k_frame_attn() {
    __shared__ float sq[64];
    __shared__ float s[224];
    __shared__ float red[32];
    __shared__ float sacc[4][64];
    int i = blockIdx.x;
    int g = blockIdx.y;
    int fr = g & 15;
    int bh = g >> 4;
    int h = bh & 7;
    int bb = bh >> 3;
    int t = threadIdx.x;
    int ti = NJx + fr * NPATCH + i;
    const float* qp = g_qkv + ((size_t)(bb * NTOK + ti)) * 1536 + h * 64;
    if (t < 64) sq[t] = qp[t];
    __syncthreads();
    if (t < 220) {
        int tj = (t < NJx) ? t : NJx + fr * NPATCH + (t - NJx);
        const float* kp = g_qkv + ((size_t)(bb * NTOK + tj)) * 1536 + 512 + h * 64;
        float acc = 0.f;
        #pragma unroll
        for (int d = 0; d < 64; d += 4) {
            float4 kv = *reinterpret_cast<const float4*>(kp + d);
            acc += sq[d] * kv.x + sq[d + 1] * kv.y + sq[d + 2] * kv.z + sq[d + 3] * kv.w;
        }
        s[t] = acc;
    }
    __syncthreads();
    float m = (t < 220) ? s[t] : -INFINITY;
    m = block_max(m, red);
    float e = 0.f;
    if (t < 220) { e = expf(s[t] - m); s[t] = e; }
    float denom = block_sum(e, red);
    float inv = 1.f / denom;
    int d = t & 63, c = t >> 6;
    float acc = 0.f;
    for (int j = c; j < 220; j += 4) {
        int tj = (j < NJx) ? j : NJx + fr * NPATCH + (j - NJx);
        acc += s[j] * g_qkv[((size_t)(bb * NTOK + tj)) * 1536 + 1024 + h * 64 + d];
    }
    sacc[c][d] = acc;
    __syncthreads();
    if (t < 64) {
        float o = (sacc[0][t] + sacc[1][t] + sacc[2][t] + sacc[3][t]) * inv;
        g_attn[((size_t)(bb * NTOK + ti)) * 512 + h * 64 + t] = o;
    }
}

// ---------------- GEGLU: hg = a * gelu_exact(g) ----------------
__global__ void k_geglu() {
    size_t idx = (size_t)blockIdx.x * blockDim.x + threadIdx.x;
    if (idx >= (size_t)ROWS * 2048) return;
    size_t r = idx >> 11;
    int j = (int)(idx & 2047);
    float a = g_h1[r * 4096 + j];
    float g = g_h1[r * 4096 + 2048 + j];
    float ge = 0.5f * g * (1.f + erff(g * 0.7071067811865476f));
    g_hg[idx] = a * ge;
}

// ---------------- host-side helpers ----------------
static void launch_sgemm(const float* A, const float* Bm, const float* bias,
                         const float* res, float* C, int M, int N, int K,
                         bool withBias, bool withRes) {
    dim3 grid(N / 128, (M + 127) / 128);
    if (withBias && withRes)
        k_sgemm<1, 1><<<grid, 256>>>(A, Bm, bias, res, C, M, N, K);
    else if (withBias)
        k_sgemm<1, 0><<<grid, 256>>>(A, Bm, bias, nullptr, C, M, N, K);
    else
        k_sgemm<0, 0><<<grid, 256>>>(A, Bm, nullptr, nullptr, C, M, N, K);
}

extern "C" void kernel_launch(void* const* d_in, const int* in_sizes, int n_in,
                              void* d_out, int out_size) {
    const float* video        = (const float*)d_in[0];
    const float* patch_w      = (const float*)d_in[1];
    const float* patch_b      = (const float*)d_in[2];
    const float* joints_token = (const float*)d_in[3];
    const float* ln_attn_w    = (const float*)d_in[4];
    const float* ln_attn_b    = (const float*)d_in[5];
    const float* qkv_w        = (const float*)d_in[6];
    const float* attn_out_w   = (const float*)d_in[7];
    const float* attn_out_b   = (const float*)d_in[8];
    const float* ln_ff_w      = (const float*)d_in[9];
    const float* ln_ff_b      = (const float*)d_in[10];
    const float* ff1_w        = (const float*)d_in[11];
    const float* ff1_b        = (const float*)d_in[12];
    const float* ff2_w        = (const float*)d_in[13];
    const float* ff2_b        = (const float*)d_in[14];
    const float* ln_out_w     = (const float*)d_in[15];
    const float* ln_out_b     = (const float*)d_in[16];
    const float* out_w        = (const float*)d_in[17];
    const float* out_b        = (const float*)d_in[18];

    float *px, *pxn, *pqkv, *pattn, *ph1, *phg, *ptok, *ppat, *pjt;
    cudaGetSymbolAddress((void**)&px,    g_x);
    cudaGetSymbolAddress((void**)&pxn,   g_xn);
    cudaGetSymbolAddress((void**)&pqkv,  g_qkv);
    cudaGetSymbolAddress((void**)&pattn, g_attn);
    cudaGetSymbolAddress((void**)&ph1,   g_h1);
    cudaGetSymbolAddress((void**)&phg,   g_hg);
    cudaGetSymbolAddress((void**)&ptok,  g_tok);
    cudaGetSymbolAddress((void**)&ppat,  g_pat);
    cudaGetSymbolAddress((void**)&pjt,   g_jt);

    // setup: rotary tables, patchify, patch embed, assemble token stream
    k_sincos<<<(NPATCH * 32 + 255) / 256, 256>>>();
    k_im2col<<<(B_ * NSP * DIMC + 255) / 256, 256>>>(video);
    launch_sgemm(ppat, patch_w, patch_b, nullptr, ptok, B_ * NSP, DIMC, DIMC, true, false);
    k_assemble<<<(B_ * NTOK * DIMC + 255) / 256, 256>>>(joints_token);

    for (int l = 0; l < 12; l++) {
        k_ln<<<ROWS, 256>>>(px, ln_attn_w + l * 512, ln_attn_b + l * 512, pxn);
        launch_sgemm(pxn, qkv_w + (size_t)l * 512 * 1536, nullptr, nullptr,
                     pqkv, ROWS, 1536, 512, false, false);
        k_joints_attn<<<B_ * 8 * NJx, 256>>>();                 // pre-rope keys/values
        k_rope<<<(B_ * NTOK * 8 * 32 + 255) / 256, 256>>>();    // scale q, rotate spatial q/k
        k_frame_attn<<<dim3(NPATCH, B_ * 8 * F_), 256>>>();
        launch_sgemm(pattn, attn_out_w + (size_t)l * 512 * 512, attn_out_b + l * 512,
                     px, px, ROWS, 512, 512, true, true);       // x += proj(attn)
        k_ln<<<ROWS, 256>>>(px, ln_ff_w + l * 512, ln_ff_b + l * 512, pxn);
        launch_sgemm(pxn, ff1_w + (size_t)l * 512 * 4096, ff1_b + (size_t)l * 4096, nullptr,
                     ph1, ROWS, 4096, 512, true, false);
        k_geglu<<<(int)(((size_t)ROWS * 2048 + 255) / 256), 256>>>();
        launch_sgemm(phg, ff2_w + (size_t)l * 2048 * 512, ff2_b + l * 512,
                     px, px, ROWS, 512, 2048, true, true);      // x += ff2(hg)
    }

    // head: LN over joint tokens, final projection -> (2,24,4,96) contiguous
    k_ln_gather<<<48, 256>>>(ln_out_w, ln_out_b);
    launch_sgemm(pjt, out_w, out_b, nullptr, (float*)d_out, 48, 384, 512, true, false);
}

// round 9
// speedup vs baseline: 1.5943x; 1.0006x over previous
#include <cuda_runtime.h>
#include <cuda_bf16.h>
#include <math.h>

// ---------------- problem constants ----------------
#define B_      2
#define F_      16
#define NJx     24
#define NPATCH  196          // 14*14
#define NSP     3136         // F_*NPATCH
#define NTOK    3160         // NJx + NSP
#define DIMC    512
#define ROWS    (B_*NTOK)    // 6320

// ---------------- scratch (device globals; no runtime alloc) ----------------
__device__ float g_x   [B_*NTOK*DIMC];
__device__ float g_xn  [B_*NTOK*DIMC];
__device__ float g_qkv [B_*NTOK*1536];
__device__ float g_attn[B_*NTOK*DIMC];
__device__ float g_h1  [(size_t)B_*NTOK*4096];
__device__ float g_hg  [(size_t)B_*NTOK*2048];
__device__ float g_tok [B_*NSP*DIMC];
__device__ float g_pat [B_*NSP*DIMC];
__device__ float g_sin [NPATCH*32];
__device__ float g_cos [NPATCH*32];
__device__ float g_jt  [48*DIMC];

// ---------------- block reductions (blockDim.x == 256) ----------------
__device__ __forceinline__ float warp_sum(float v) {
    #pragma unroll
    for (int o = 16; o > 0; o >>= 1) v += __shfl_xor_sync(0xffffffffu, v, o);
    return v;
}
__device__ __forceinline__ float warp_max(float v) {
    #pragma unroll
    for (int o = 16; o > 0; o >>= 1) v = fmaxf(v, __shfl_xor_sync(0xffffffffu, v, o));
    return v;
}
__device__ __forceinline__ float block_sum(float v, float* red) {
    v = warp_sum(v);
    int lane = threadIdx.x & 31, w = threadIdx.x >> 5;
    if (lane == 0) red[w] = v;
    __syncthreads();
    if (threadIdx.x < 32) {
        float r = (threadIdx.x < 8) ? red[threadIdx.x] : 0.f;
        r = warp_sum(r);
        if (threadIdx.x == 0) red[0] = r;
    }
    __syncthreads();
    float out = red[0];
    __syncthreads();
    return out;
}
__device__ __forceinline__ float block_max(float v, float* red) {
    v = warp_max(v);
    int lane = threadIdx.x & 31, w = threadIdx.x >> 5;
    if (lane == 0) red[w] = v;
    __syncthreads();
    if (threadIdx.x < 32) {
        float r = (threadIdx.x < 8) ? red[threadIdx.x] : -INFINITY;
        r = warp_max(r);
        if (threadIdx.x == 0) red[0] = r;
    }
    __syncthreads();
    float out = red[0];
    __syncthreads();
    return out;
}

// ---------------- SGEMM: C = A(MxK) @ B(KxN) [+bias] [+res], row-major ----------------
// 128x128 tile, BK=8, 256 threads, 8x8 per thread (4+4 split-register mapping).
template<int BIAS, int RES>
__global__ __launch_bounds__(256) void k_sgemm(
    const float* __restrict__ A, const float* __restrict__ B,
    const float* __restrict__ bias, const float* __restrict__ res,
    float* __restrict__ C, int M, int N, int K)
{
    __shared__ float As[8][128];
    __shared__ float Bs[8][128];
    int tid = threadIdx.x;
    int bm = blockIdx.y * 128;
    int bn = blockIdx.x * 128;
    int tx = tid & 15, ty = tid >> 4;
    int ar = tid >> 1, ac = (tid & 1) * 4;
    int br = tid >> 5, bc = (tid & 31) * 4;

    float acc[8][8];
    #pragma unroll
    for (int i = 0; i < 8; i++)
        #pragma unroll
        for (int j = 0; j < 8; j++) acc[i][j] = 0.f;

    bool aval = (bm + ar) < M;
    const float* Aptr = A + (size_t)(bm + ar) * K + ac;
    const float* Bptr = B + (size_t)br * N + bn + bc;

    for (int k0 = 0; k0 < K; k0 += 8) {
        float4 av = make_float4(0.f, 0.f, 0.f, 0.f);
        if (aval) av = *reinterpret_cast<const float4*>(Aptr + k0);
        As[ac + 0][ar] = av.x; As[ac + 1][ar] = av.y;
        As[ac + 2][ar] = av.z; As[ac + 3][ar] = av.w;
        float4 bv = *reinterpret_cast<const float4*>(Bptr + (size_t)k0 * N);
        *reinterpret_cast<float4*>(&Bs[br][bc]) = bv;
        __syncthreads();
        #pragma unroll
        for (int kk = 0; kk < 8; kk++) {
            float af[8], bf[8];
            *reinterpret_cast<float4*>(&af[0]) = *reinterpret_cast<const float4*>(&As[kk][ty * 4]);
            *reinterpret_cast<float4*>(&af[4]) = *reinterpret_cast<const float4*>(&As[kk][64 + ty * 4]);
            *reinterpret_cast<float4*>(&bf[0]) = *reinterpret_cast<const float4*>(&Bs[kk][tx * 4]);
            *reinterpret_cast<float4*>(&bf[4]) = *reinterpret_cast<const float4*>(&Bs[kk][64 + tx * 4]);
            #pragma unroll
            for (int i = 0; i < 8; i++)
                #pragma unroll
                for (int j = 0; j < 8; j++)
                    acc[i][j] = fmaf(af[i], bf[j], acc[i][j]);
        }
        __syncthreads();
    }

    #pragma unroll
    for (int i = 0; i < 8; i++) {
        int row = bm + ((i < 4) ? (ty * 4 + i) : (64 + ty * 4 + i - 4));
        if (row >= M) continue;
        #pragma unroll
        for (int jh = 0; jh < 2; jh++) {
            int col = bn + ((jh == 0) ? (tx * 4) : (64 + tx * 4));
            float4 v;
            v.x = acc[i][jh * 4 + 0]; v.y = acc[i][jh * 4 + 1];
            v.z = acc[i][jh * 4 + 2]; v.w = acc[i][jh * 4 + 3];
            if (BIAS) {
                float4 b4 = *reinterpret_cast<const float4*>(bias + col);
                v.x += b4.x; v.y += b4.y; v.z += b4.z; v.w += b4.w;
            }
            if (RES) {
                float4 r4 = *reinterpret_cast<const float4*>(res + (size_t)row * N + col);
                v.x += r4.x; v.y += r4.y; v.z += r4.z; v.w += r4.w;
            }
            *reinterpret_cast<float4*>(C + (size_t)row * N + col) = v;
        }
    }
}

// ---------------- rotary tables ----------------
__global__ void k_sincos() {
    int idx = blockIdx.x * blockDim.x + threadIdx.x;
    if (idx >= NPATCH * 32) return;
    int p = idx >> 5, s = idx & 31;
    int ph = p / 14, pw = p % 14;
    int ss = (s < 16) ? s : (s - 16);
    float scale = exp2f((float)ss * (2.321928094887362f / 15.f));  // 2^(ss*log2(5)/15)
    int pos_i = (s < 16) ? ph : pw;
    float pos = -1.f + 2.f * (float)pos_i / 13.f;
    float ang = pos * scale * 3.14159265358979323846f;
    g_sin[idx] = sinf(ang);
    g_cos[idx] = cosf(ang);
}

// ---------------- patch extraction (im2col) ----------------
__global__ void k_im2col(const float* __restrict__ video) {
    size_t idx = (size_t)blockIdx.x * blockDim.x + threadIdx.x;
    if (idx >= (size_t)B_ * NSP * DIMC) return;
    int e = (int)(idx & 511);
    size_t r = idx >> 9;
    int bb = (int)(r / NSP); int t = (int)(r % NSP);
    int fr = t / NPATCH; int pp = t % NPATCH;
    int ph = pp / 14, pw = pp % 14;
    int py = e >> 5, px = (e >> 1) & 15, cc = e & 1;
    size_t vidx = ((((size_t)(bb * F_ + fr) * 2 + cc) * 224 + (ph * 16 + py)) * 224 + (pw * 16 + px));
    g_pat[idx] = video[vidx];
}

// ---------------- token assembly: x = [joints_token ; tokens] ----------------
__global__ void k_assemble(const float* __restrict__ joints_token) {
    size_t idx = (size_t)blockIdx.x * blockDim.x + threadIdx.x;
    if (idx >= (size_t)B_ * NTOK * DIMC) return;
    int col = (int)(idx & 511);
    size_t r = idx >> 9;
    int bb = (int)(r / NTOK); int i = (int)(r % NTOK);
    g_x[idx] = (i < NJx) ? joints_token[i * DIMC + col]
                         : g_tok[((size_t)bb * NSP + (i - NJx)) * DIMC + col];
}

// ---------------- LayerNorm (512-wide rows) ----------------
__global__ __launch_bounds__(256) void k_ln(const float* __restrict__ in,
                                            const float* __restrict__ w,
                                            const float* __restrict__ b,
                                            float* __restrict__ out) {
    __shared__ float red[32];
    int row = blockIdx.x;
    int t = threadIdx.x;
    const float* ri = in + (size_t)row * DIMC;
    float v0 = ri[t], v1 = ri[t + 256];
    float mean = block_sum(v0 + v1, red) * (1.f / 512.f);
    float d0 = v0 - mean, d1 = v1 - mean;
    float var = block_sum(d0 * d0 + d1 * d1, red) * (1.f / 512.f);
    float rs = rsqrtf(var + 1e-5f);
    float* ro = out + (size_t)row * DIMC;
    ro[t]       = d0 * rs * w[t]       + b[t];
    ro[t + 256] = d1 * rs * w[t + 256] + b[t + 256];
}

// final LN on joint tokens, gathering 48 rows out of g_x -> g_jt (48x512)
__global__ __launch_bounds__(256) void k_ln_gather(const float* __restrict__ w,
                                                   const float* __restrict__ b) {
    __shared__ float red[32];
    int row = blockIdx.x;               // 0..47
    int bb = row / NJx, i = row % NJx;
    int t = threadIdx.x;
    const float* ri = g_x + ((size_t)bb * NTOK + i) * DIMC;
    float v0 = ri[t], v1 = ri[t + 256];
    float mean = block_sum(v0 + v1, red) * (1.f / 512.f);
    float d0 = v0 - mean, d1 = v1 - mean;
    float var = block_sum(d0 * d0 + d1 * d1, red) * (1.f / 512.f);
    float rs = rsqrtf(var + 1e-5f);
    float* ro = g_jt + (size_t)row * DIMC;
    ro[t]       = d0 * rs * w[t]       + b[t];
    ro[t + 256] = d1 * rs * w[t + 256] + b[t + 256];
}

// ---------------- joints attention (runs BEFORE rope; keys/values un-rotated) ----------------
// grid: B_*8*NJx blocks. q scaled by 0.125 inline.
__global__ __launch_bounds__(256) void k_joints_attn() {
    __shared__ float sq[64];
    __shared__ float s[NTOK];
    __shared__ float red[32];
    __shared__ float sacc[4][64];
    int bidx = blockIdx.x;
    int jq = bidx % NJx;
    int h  = (bidx / NJx) & 7;
    int bb = bidx / (NJx * 8);
    int t = threadIdx.x;
    const float* qp = g_qkv + ((size_t)(bb * NTOK + jq)) * 1536 + h * 64;
    if (t < 64) sq[t] = qp[t] * 0.125f;
    __syncthreads();
    for (int j = t; j < NTOK; j += 256) {
        const float* kp = g_qkv + ((size_t)(bb * NTOK + j)) * 1536 + 512 + h * 64;
        float acc = 0.f;
        #pragma unroll
        for (int d = 0; d < 64; d += 4) {
            float4 kv = *reinterpret_cast<const float4*>(kp + d);
            acc += sq[d] * kv.x + sq[d + 1] * kv.y + sq[d + 2] * kv.z + sq[d + 3] * kv.w;
        }
        s[j] = acc;
    }
    __syncthreads();
    float m = -INFINITY;
    for (int j = t; j < NTOK; j += 256) m = fmaxf(m, s[j]);
    m = block_max(m, red);
    float lsum = 0.f;
    for (int j = t; j < NTOK; j += 256) { float e = expf(s[j] - m); s[j] = e; lsum += e; }
    float denom = block_sum(lsum, red);
    float inv = 1.f / denom;
    int d = t & 63, c = t >> 6;
    float acc = 0.f;
    for (int j = c; j < NTOK; j += 4)
        acc += s[j] * g_qkv[((size_t)(bb * NTOK + j)) * 1536 + 1024 + h * 64 + d];
    sacc[c][d] = acc;
    __syncthreads();
    if (t < 64) {
        float o = (sacc[0][t] + sacc[1][t] + sacc[2][t] + sacc[3][t]) * inv;
        g_attn[((size_t)(bb * NTOK + jq)) * 512 + h * 64 + t] = o;
    }
}

// ---------------- rope + q-scale (in place on qkv; spatial tokens rotated) ----------------
__global__ void k_rope() {
    int idx = blockIdx.x * blockDim.x + threadIdx.x;
    if (idx >= B_ * NTOK * 8 * 32) return;
    int s = idx & 31;
    int h = (idx >> 5) & 7;
    int rest = idx >> 8;
    int i = rest % NTOK;
    int bb = rest / NTOK;
    size_t base = ((size_t)(bb * NTOK + i)) * 1536 + h * 64 + 2 * s;
    float q0 = g_qkv[base] * 0.125f, q1 = g_qkv[base + 1] * 0.125f;
    if (i >= NJx) {
        int p = (i - NJx) % NPATCH;
        float c = g_cos[p * 32 + s], sn = g_sin[p * 32 + s];
        float nq0 = q0 * c - q1 * sn, nq1 = q1 * c + q0 * sn;
        q0 = nq0; q1 = nq1;
        float k0 = g_qkv[base + 512], k1 = g_qkv[base + 513];
        g_qkv[base + 512] = k0 * c - k1 * sn;
        g_qkv[base + 513] = k1 * c + k0 * sn;
    }
    g_qkv[base] = q0; g_qkv[base + 1] = q1;
}

// ---------------- per-frame attention: 196 queries x (24 joint + 196 frame) keys ----------------
// grid (196, 256): x = query index, y = group (bb,h,fr)
__global__ __launch_bounds__(256) void k_frame_attn() {
    __shared__ float sq[64];
    __shared__ float s[224];
    __shared__ float red[32];
    __shared__ float sacc[4][64];
    int i = blockIdx.x;
    int g = blockIdx.y;
    int fr = g & 15;
    int bh = g >> 4;
    int h = bh & 7;
    int bb = bh >> 3;
    int t = threadIdx.x;
    int ti = NJx + fr * NPATCH + i;
    const float* qp = g_qkv + ((size_t)(bb * NTOK + ti)) * 1536 + h * 64;
    if (t < 64) sq[t] = qp[t];
    __syncthreads();
    if (t < 220) {
        int tj = (t < NJx) ? t : NJx + fr * NPATCH + (t - NJx);
        const float* kp = g_qkv + ((size_t)(bb * NTOK + tj)) * 1536 + 512 + h * 64;
        float acc = 0.f;
        #pragma unroll
        for (int d = 0; d < 64; d += 4) {
            float4 kv = *reinterpret_cast<const float4*>(kp + d);
            acc += sq[d] * kv.x + sq[d + 1] * kv.y + sq[d + 2] * kv.z + sq[d + 3] * kv.w;
        }
        s[t] = acc;
    }
    __syncthreads();
    float m = (t < 220) ? s[t] : -INFINITY;
    m = block_max(m, red);
    float e = 0.f;
    if (t < 220) { e = expf(s[t] - m); s[t] = e; }
    float denom = block_sum(e, red);
    float inv = 1.f / denom;
    int d = t & 63, c = t >> 6;
    float acc = 0.f;
    for (int j = c; j < 220; j += 4) {
        int tj = (j < NJx) ? j : NJx + fr * NPATCH + (j - NJx);
        acc += s[j] * g_qkv[((size_t)(bb * NTOK + tj)) * 1536 + 1024 + h * 64 + d];
    }
    sacc[c][d] = acc;
    __syncthreads();
    if (t < 64) {
        float o = (sacc[0][t] + sacc[1][t] + sacc[2][t] + sacc[3][t]) * inv;
        g_attn[((size_t)(bb * NTOK + ti)) * 512 + h * 64 + t] = o;
    }
}

// ---------------- GEGLU: hg = a * gelu_exact(g) ----------------
__global__ void k_geglu() {
    size_t idx = (size_t)blockIdx.x * blockDim.x + threadIdx.x;
    if (idx >= (size_t)ROWS * 2048) return;
    size_t r = idx >> 11;
    int j = (int)(idx & 2047);
    float a = g_h1[r * 4096 + j];
    float g = g_h1[r * 4096 + 2048 + j];
    float ge = 0.5f * g * (1.f + erff(g * 0.7071067811865476f));
    g_hg[idx] = a * ge;
}

// ---------------- host-side helpers ----------------
static void launch_sgemm(const float* A, const float* Bm, const float* bias,
                         const float* res, float* C, int M, int N, int K,
                         bool withBias, bool withRes) {
    dim3 grid(N / 128, (M + 127) / 128);
    if (withBias && withRes)
        k_sgemm<1, 1><<<grid, 256>>>(A, Bm, bias, res, C, M, N, K);
    else if (withBias)
        k_sgemm<1, 0><<<grid, 256>>>(A, Bm, bias, nullptr, C, M, N, K);
    else
        k_sgemm<0, 0><<<grid, 256>>>(A, Bm, nullptr, nullptr, C, M, N, K);
}

extern "C" void kernel_launch(void* const* d_in, const int* in_sizes, int n_in,
                              void* d_out, int out_size) {
    const float* video        = (const float*)d_in[0];
    const float* patch_w      = (const float*)d_in[1];
    const float* patch_b      = (const float*)d_in[2];
    const float* joints_token = (const float*)d_in[3];
    const float* ln_attn_w    = (const float*)d_in[4];
    const float* ln_attn_b    = (const float*)d_in[5];
    const float* qkv_w        = (const float*)d_in[6];
    const float* attn_out_w   = (const float*)d_in[7];
    const float* attn_out_b   = (const float*)d_in[8];
    const float* ln_ff_w      = (const float*)d_in[9];
    const float* ln_ff_b      = (const float*)d_in[10];
    const float* ff1_w        = (const float*)d_in[11];
    const float* ff1_b        = (const float*)d_in[12];
    const float* ff2_w        = (const float*)d_in[13];
    const float* ff2_b        = (const float*)d_in[14];
    const float* ln_out_w     = (const float*)d_in[15];
    const float* ln_out_b     = (const float*)d_in[16];
    const float* out_w        = (const float*)d_in[17];
    const float* out_b        = (const float*)d_in[18];

    float *px, *pxn, *pqkv, *pattn, *ph1, *phg, *ptok, *ppat, *pjt;
    cudaGetSymbolAddress((void**)&px,    g_x);
    cudaGetSymbolAddress((void**)&pxn,   g_xn);
    cudaGetSymbolAddress((void**)&pqkv,  g_qkv);
    cudaGetSymbolAddress((void**)&pattn, g_attn);
    cudaGetSymbolAddress((void**)&ph1,   g_h1);
    cudaGetSymbolAddress((void**)&phg,   g_hg);
    cudaGetSymbolAddress((void**)&ptok,  g_tok);
    cudaGetSymbolAddress((void**)&ppat,  g_pat);
    cudaGetSymbolAddress((void**)&pjt,   g_jt);

    // setup: rotary tables, patchify, patch embed, assemble token stream
    k_sincos<<<(NPATCH * 32 + 255) / 256, 256>>>();
    k_im2col<<<(B_ * NSP * DIMC + 255) / 256, 256>>>(video);
    launch_sgemm(ppat, patch_w, patch_b, nullptr, ptok, B_ * NSP, DIMC, DIMC, true, false);
    k_assemble<<<(B_ * NTOK * DIMC + 255) / 256, 256>>>(joints_token);

    for (int l = 0; l < 12; l++) {
        k_ln<<<ROWS, 256>>>(px, ln_attn_w + l * 512, ln_attn_b + l * 512, pxn);
        launch_sgemm(pxn, qkv_w + (size_t)l * 512 * 1536, nullptr, nullptr,
                     pqkv, ROWS, 1536, 512, false, false);
        k_joints_attn<<<B_ * 8 * NJx, 256>>>();                 // pre-rope keys/values
        k_rope<<<(B_ * NTOK * 8 * 32 + 255) / 256, 256>>>();    // scale q, rotate spatial q/k
        k_frame_attn<<<dim3(NPATCH, B_ * 8 * F_), 256>>>();
        launch_sgemm(pattn, attn_out_w + (size_t)l * 512 * 512, attn_out_b + l * 512,
                     px, px, ROWS, 512, 512, true, true);       // x += proj(attn)
        k_ln<<<ROWS, 256>>>(px, ln_ff_w + l * 512, ln_ff_b + l * 512, pxn);
        launch_sgemm(pxn, ff1_w + (size_t)l * 512 * 4096, ff1_b + (size_t)l * 4096, nullptr,
                     ph1, ROWS, 4096, 512, true, false);
        k_geglu<<<(int)(((size_t)ROWS * 2048 + 255) / 256), 256>>>();
        launch_sgemm(phg, ff2_w + (size_t)l * 2048 * 512, ff2_b + l * 512,
                     px, px, ROWS, 512, 2048, true, true);      // x += ff2(hg)
    }

    // head: LN over joint tokens, final projection -> (2,24,4,96) contiguous
    k_ln_gather<<<48, 256>>>(ln_out_w, ln_out_b);
    launch_sgemm(pjt, out_w, out_b, nullptr, (float*)d_out, 48, 384, 512, true, false);
}

// round 10
// speedup vs baseline: 1.5973x; 1.0019x over previous
#include <cuda_runtime.h>
#include <cuda_bf16.h>
#include <math.h>

// ---------------- problem constants ----------------
#define B_      2
#define F_      16
#define NJx     24
#define NPATCH  196          // 14*14
#define NSP     3136         // F_*NPATCH
#define NTOK    3160         // NJx + NSP
#define DIMC    512
#define ROWS    (B_*NTOK)    // 6320

// ---------------- scratch (device globals; no runtime alloc) ----------------
__device__ float g_x   [B_*NTOK*DIMC];
__device__ float g_xn  [B_*NTOK*DIMC];
__device__ float g_qkv [B_*NTOK*1536];
__device__ float g_attn[B_*NTOK*DIMC];
__device__ float g_h1  [(size_t)B_*NTOK*4096];
__device__ float g_hg  [(size_t)B_*NTOK*2048];
__device__ float g_tok [B_*NSP*DIMC];
__device__ float g_pat [B_*NSP*DIMC];
__device__ float g_sin [NPATCH*32];
__device__ float g_cos [NPATCH*32];
__device__ float g_jt  [48*DIMC];

// ---------------- block reductions (blockDim.x == 256) ----------------
__device__ __forceinline__ float warp_sum(float v) {
    #pragma unroll
    for (int o = 16; o > 0; o >>= 1) v += __shfl_xor_sync(0xffffffffu, v, o);
    return v;
}
__device__ __forceinline__ float warp_max(float v) {
    #pragma unroll
    for (int o = 16; o > 0; o >>= 1) v = fmaxf(v, __shfl_xor_sync(0xffffffffu, v, o));
    return v;
}
__device__ __forceinline__ float block_sum(float v, float* red) {
    v = warp_sum(v);
    int lane = threadIdx.x & 31, w = threadIdx.x >> 5;
    if (lane == 0) red[w] = v;
    __syncthreads();
    if (threadIdx.x < 32) {
        float r = (threadIdx.x < 8) ? red[threadIdx.x] : 0.f;
        r = warp_sum(r);
        if (threadIdx.x == 0) red[0] = r;
    }
    __syncthreads();
    float out = red[0];
    __syncthreads();
    return out;
}
__device__ __forceinline__ float block_max(float v, float* red) {
    v = warp_max(v);
    int lane = threadIdx.x & 31, w = threadIdx.x >> 5;
    if (lane == 0) red[w] = v;
    __syncthreads();
    if (threadIdx.x < 32) {
        float r = (threadIdx.x < 8) ? red[threadIdx.x] : -INFINITY;
        r = warp_max(r);
        if (threadIdx.x == 0) red[0] = r;
    }
    __syncthreads();
    float out = red[0];
    __syncthreads();
    return out;
}

// ---------------- SGEMM: C = A(MxK) @ B(KxN) [+bias] [+res], row-major ----------------
// 128x128 tile, BK=8, 256 threads, 8x8 per thread (4+4 split-register mapping).
template<int BIAS, int RES>
__global__ __launch_bounds__(256) void k_sgemm(
    const float* __restrict__ A, const float* __restrict__ B,
    const float* __restrict__ bias, const float* __restrict__ res,
    float* __restrict__ C, int M, int N, int K)
{
    __shared__ float As[8][128];
    __shared__ float Bs[8][128];
    int tid = threadIdx.x;
    int bm = blockIdx.y * 128;
    int bn = blockIdx.x * 128;
    int tx = tid & 15, ty = tid >> 4;
    int ar = tid >> 1, ac = (tid & 1) * 4;
    int br = tid >> 5, bc = (tid & 31) * 4;

    float acc[8][8];
    #pragma unroll
    for (int i = 0; i < 8; i++)
        #pragma unroll
        for (int j = 0; j < 8; j++) acc[i][j] = 0.f;

    bool aval = (bm + ar) < M;
    const float* Aptr = A + (size_t)(bm + ar) * K + ac;
    const float* Bptr = B + (size_t)br * N + bn + bc;

    for (int k0 = 0; k0 < K; k0 += 8) {
        float4 av = make_float4(0.f, 0.f, 0.f, 0.f);
        if (aval) av = *reinterpret_cast<const float4*>(Aptr + k0);
        As[ac + 0][ar] = av.x; As[ac + 1][ar] = av.y;
        As[ac + 2][ar] = av.z; As[ac + 3][ar] = av.w;
        float4 bv = *reinterpret_cast<const float4*>(Bptr + (size_t)k0 * N);
        *reinterpret_cast<float4*>(&Bs[br][bc]) = bv;
        __syncthreads();
        #pragma unroll
        for (int kk = 0; kk < 8; kk++) {
            float af[8], bf[8];
            *reinterpret_cast<float4*>(&af[0]) = *reinterpret_cast<const float4*>(&As[kk][ty * 4]);
            *reinterpret_cast<float4*>(&af[4]) = *reinterpret_cast<const float4*>(&As[kk][64 + ty * 4]);
            *reinterpret_cast<float4*>(&bf[0]) = *reinterpret_cast<const float4*>(&Bs[kk][tx * 4]);
            *reinterpret_cast<float4*>(&bf[4]) = *reinterpret_cast<const float4*>(&Bs[kk][64 + tx * 4]);
            #pragma unroll
            for (int i = 0; i < 8; i++)
                #pragma unroll
                for (int j = 0; j < 8; j++)
                    acc[i][j] = fmaf(af[i], bf[j], acc[i][j]);
        }
        __syncthreads();
    }

    #pragma unroll
    for (int i = 0; i < 8; i++) {
        int row = bm + ((i < 4) ? (ty * 4 + i) : (64 + ty * 4 + i - 4));
        if (row >= M) continue;
        #pragma unroll
        for (int jh = 0; jh < 2; jh++) {
            int col = bn + ((jh == 0) ? (tx * 4) : (64 + tx * 4));
            float4 v;
            v.x = acc[i][jh * 4 + 0]; v.y = acc[i][jh * 4 + 1];
            v.z = acc[i][jh * 4 + 2]; v.w = acc[i][jh * 4 + 3];
            if (BIAS) {
                float4 b4 = *reinterpret_cast<const float4*>(bias + col);
                v.x += b4.x; v.y += b4.y; v.z += b4.z; v.w += b4.w;
            }
            if (RES) {
                float4 r4 = *reinterpret_cast<const float4*>(res + (size_t)row * N + col);
                v.x += r4.x; v.y += r4.y; v.z += r4.z; v.w += r4.w;
            }
            *reinterpret_cast<float4*>(C + (size_t)row * N + col) = v;
        }
    }
}

// ---------------- rotary tables ----------------
__global__ void k_sincos() {
    int idx = blockIdx.x * blockDim.x + threadIdx.x;
    if (idx >= NPATCH * 32) return;
    int p = idx >> 5, s = idx & 31;
    int ph = p / 14, pw = p % 14;
    int ss = (s < 16) ? s : (s - 16);
    float scale = exp2f((float)ss * (2.321928094887362f / 15.f));  // 2^(ss*log2(5)/15)
    int pos_i = (s < 16) ? ph : pw;
    float pos = -1.f + 2.f * (float)pos_i / 13.f;
    float ang = pos * scale * 3.14159265358979323846f;
    g_sin[idx] = sinf(ang);
    g_cos[idx] = cosf(ang);
}

// ---------------- patch extraction (im2col) ----------------
__global__ void k_im2col(const float* __restrict__ video) {
    size_t idx = (size_t)blockIdx.x * blockDim.x + threadIdx.x;
    if (idx >= (size_t)B_ * NSP * DIMC) return;
    int e = (int)(idx & 511);
    size_t r = idx >> 9;
    int bb = (int)(r / NSP); int t = (int)(r % NSP);
    int fr = t / NPATCH; int pp = t % NPATCH;
    int ph = pp / 14, pw = pp % 14;
    int py = e >> 5, px = (e >> 1) & 15, cc = e & 1;
    size_t vidx = ((((size_t)(bb * F_ + fr) * 2 + cc) * 224 + (ph * 16 + py)) * 224 + (pw * 16 + px));
    g_pat[idx] = video[vidx];
}

// ---------------- token assembly: x = [joints_token ; tokens] ----------------
__global__ void k_assemble(const float* __restrict__ joints_token) {
    size_t idx = (size_t)blockIdx.x * blockDim.x + threadIdx.x;
    if (idx >= (size_t)B_ * NTOK * DIMC) return;
    int col = (int)(idx & 511);
    size_t r = idx >> 9;
    int bb = (int)(r / NTOK); int i = (int)(r % NTOK);
    g_x[idx] = (i < NJx) ? joints_token[i * DIMC + col]
                         : g_tok[((size_t)bb * NSP + (i - NJx)) * DIMC + col];
}

// ---------------- LayerNorm (512-wide rows) ----------------
__global__ __launch_bounds__(256) void k_ln(const float* __restrict__ in,
                                            const float* __restrict__ w,
                                            const float* __restrict__ b,
                                            float* __restrict__ out) {
    __shared__ float red[32];
    int row = blockIdx.x;
    int t = threadIdx.x;
    const float* ri = in + (size_t)row * DIMC;
    float v0 = ri[t], v1 = ri[t + 256];
    float mean = block_sum(v0 + v1, red) * (1.f / 512.f);
    float d0 = v0 - mean, d1 = v1 - mean;
    float var = block_sum(d0 * d0 + d1 * d1, red) * (1.f / 512.f);
    float rs = rsqrtf(var + 1e-5f);
    float* ro = out + (size_t)row * DIMC;
    ro[t]       = d0 * rs * w[t]       + b[t];
    ro[t + 256] = d1 * rs * w[t + 256] + b[t + 256];
}

// final LN on joint tokens, gathering 48 rows out of g_x -> g_jt (48x512)
__global__ __launch_bounds__(256) void k_ln_gather(const float* __restrict__ w,
                                                   const float* __restrict__ b) {
    __shared__ float red[32];
    int row = blockIdx.x;               // 0..47
    int bb = row / NJx, i = row % NJx;
    int t = threadIdx.x;
    const float* ri = g_x + ((size_t)bb * NTOK + i) * DIMC;
    float v0 = ri[t], v1 = ri[t + 256];
    float mean = block_sum(v0 + v1, red) * (1.f / 512.f);
    float d0 = v0 - mean, d1 = v1 - mean;
    float var = block_sum(d0 * d0 + d1 * d1, red) * (1.f / 512.f);
    float rs = rsqrtf(var + 1e-5f);
    float* ro = g_jt + (size_t)row * DIMC;
    ro[t]       = d0 * rs * w[t]       + b[t];
    ro[t + 256] = d1 * rs * w[t + 256] + b[t + 256];
}

// ---------------- joints attention (runs BEFORE rope; keys/values un-rotated) ----------------
// grid: B_*8*NJx blocks. q scaled by 0.125 inline.
__global__ __launch_bounds__(256) void k_joints_attn() {
    __shared__ float sq[64];
    __shared__ float s[NTOK];
    __shared__ float red[32];
    __shared__ float sacc[4][64];
    int bidx = blockIdx.x;
    int jq = bidx % NJx;
    int h  = (bidx / NJx) & 7;
    int bb = bidx / (NJx * 8);
    int t = threadIdx.x;
    const float* qp = g_qkv + ((size_t)(bb * NTOK + jq)) * 1536 + h * 64;
    if (t < 64) sq[t] = qp[t] * 0.125f;
    __syncthreads();
    for (int j = t; j < NTOK; j += 256) {
        const float* kp = g_qkv + ((size_t)(bb * NTOK + j)) * 1536 + 512 + h * 64;
        float acc = 0.f;
        #pragma unroll
        for (int d = 0; d < 64; d += 4) {
            float4 kv = *reinterpret_cast<const float4*>(kp + d);
            acc += sq[d] * kv.x + sq[d + 1] * kv.y + sq[d + 2] * kv.z + sq[d + 3] * kv.w;
        }
        s[j] = acc;
    }
    __syncthreads();
    float m = -INFINITY;
    for (int j = t; j < NTOK; j += 256) m = fmaxf(m, s[j]);
    m = block_max(m, red);
    float lsum = 0.f;
    for (int j = t; j < NTOK; j += 256) { float e = expf(s[j] - m); s[j] = e; lsum += e; }
    float denom = block_sum(lsum, red);
    float inv = 1.f / denom;
    int d = t & 63, c = t >> 6;
    float acc = 0.f;
    for (int j = c; j < NTOK; j += 4)
        acc += s[j] * g_qkv[((size_t)(bb * NTOK + j)) * 1536 + 1024 + h * 64 + d];
    sacc[c][d] = acc;
    __syncthreads();
    if (t < 64) {
        float o = (sacc[0][t] + sacc[1][t] + sacc[2][t] + sacc[3][t]) * inv;
        g_attn[((size_t)(bb * NTOK + jq)) * 512 + h * 64 + t] = o;
    }
}

// ---------------- rope + q-scale (in place on qkv; spatial tokens rotated) ----------------
__global__ void k_rope() {
    int idx = blockIdx.x * blockDim.x + threadIdx.x;
    if (idx >= B_ * NTOK * 8 * 32) return;
    int s = idx & 31;
    int h = (idx >> 5) & 7;
    int rest = idx >> 8;
    int i = rest % NTOK;
    int bb = rest / NTOK;
    size_t base = ((size_t)(bb * NTOK + i)) * 1536 + h * 64 + 2 * s;
    float q0 = g_qkv[base] * 0.125f, q1 = g_qkv[base + 1] * 0.125f;
    if (i >= NJx) {
        int p = (i - NJx) % NPATCH;
        float c = g_cos[p * 32 + s], sn = g_sin[p * 32 + s];
        float nq0 = q0 * c - q1 * sn, nq1 = q1 * c + q0 * sn;
        q0 = nq0; q1 = nq1;
        float k0 = g_qkv[base + 512], k1 = g_qkv[base + 513];
        g_qkv[base + 512] = k0 * c - k1 * sn;
        g_qkv[base + 513] = k1 * c + k0 * sn;
    }
    g_qkv[base] = q0; g_qkv[base + 1] = q1;
}

// ---------------- per-frame attention: 196 queries x (24 joint + 196 frame) keys ----------------
// grid (196, 256): x = query index, y = group (bb,h,fr)
__global__ __launch_bounds__(256) void k_frame_attn() {
    __shared__ float sq[64];
    __shared__ float s[224];
    __shared__ float red[32];
    __shared__ float sacc[4][64];
    int i = blockIdx.x;
    int g = blockIdx.y;
    int fr = g & 15;
    int bh = g >> 4;
    int h = bh & 7;
    int bb = bh >> 3;
    int t = threadIdx.x;
    int ti = NJx + fr * NPATCH + i;
    const float* qp = g_qkv + ((size_t)(bb * NTOK + ti)) * 1536 + h * 64;
    if (t < 64) sq[t] = qp[t];
    __syncthreads();
    if (t < 220) {
        int tj = (t < NJx) ? t : NJx + fr * NPATCH + (t - NJx);
        const float* kp = g_qkv + ((size_t)(bb * NTOK + tj)) * 1536 + 512 + h * 64;
        float acc = 0.f;
        #pragma unroll
        for (int d = 0; d < 64; d += 4) {
            float4 kv = *reinterpret_cast<const float4*>(kp + d);
            acc += sq[d] * kv.x + sq[d + 1] * kv.y + sq[d + 2] * kv.z + sq[d + 3] * kv.w;
        }
        s[t] = acc;
    }
    __syncthreads();
    float m = (t < 220) ? s[t] : -INFINITY;
    m = block_max(m, red);
    float e = 0.f;
    if (t < 220) { e = expf(s[t] - m); s[t] = e; }
    float denom = block_sum(e, red);
    float inv = 1.f / denom;
    int d = t & 63, c = t >> 6;
    float acc = 0.f;
    for (int j = c; j < 220; j += 4) {
        int tj = (j < NJx) ? j : NJx + fr * NPATCH + (j - NJx);
        acc += s[j] * g_qkv[((size_t)(bb * NTOK + tj)) * 1536 + 1024 + h * 64 + d];
    }
    sacc[c][d] = acc;
    __syncthreads();
    if (t < 64) {
        float o = (sacc[0][t] + sacc[1][t] + sacc[2][t] + sacc[3][t]) * inv;
        g_attn[((size_t)(bb * NTOK + ti)) * 512 + h * 64 + t] = o;
    }
}

// ---------------- GEGLU: hg = a * gelu_exact(g) ----------------
__global__ void k_geglu() {
    size_t idx = (size_t)blockIdx.x * blockDim.x + threadIdx.x;
    if (idx >= (size_t)ROWS * 2048) return;
    size_t r = idx >> 11;
    int j = (int)(idx & 2047);
    float a = g_h1[r * 4096 + j];
    float g = g_h1[r * 4096 + 2048 + j];
    float ge = 0.5f * g * (1.f + erff(g * 0.7071067811865476f));
    g_hg[idx] = a * ge;
}

// ---------------- host-side helpers ----------------
static void launch_sgemm(const float* A, const float* Bm, const float* bias,
                         const float* res, float* C, int M, int N, int K,
                         bool withBias, bool withRes) {
    dim3 grid(N / 128, (M + 127) / 128);
    if (withBias && withRes)
        k_sgemm<1, 1><<<grid, 256>>>(A, Bm, bias, res, C, M, N, K);
    else if (withBias)
        k_sgemm<1, 0><<<grid, 256>>>(A, Bm, bias, nullptr, C, M, N, K);
    else
        k_sgemm<0, 0><<<grid, 256>>>(A, Bm, nullptr, nullptr, C, M, N, K);
}

extern "C" void kernel_launch(void* const* d_in, const int* in_sizes, int n_in,
                              void* d_out, int out_size) {
    const float* video        = (const float*)d_in[0];
    const float* patch_w      = (const float*)d_in[1];
    const float* patch_b      = (const float*)d_in[2];
    const float* joints_token = (const float*)d_in[3];
    const float* ln_attn_w    = (const float*)d_in[4];
    const float* ln_attn_b    = (const float*)d_in[5];
    const float* qkv_w        = (const float*)d_in[6];
    const float* attn_out_w   = (const float*)d_in[7];
    const float* attn_out_b   = (const float*)d_in[8];
    const float* ln_ff_w      = (const float*)d_in[9];
    const float* ln_ff_b      = (const float*)d_in[10];
    const float* ff1_w        = (const float*)d_in[11];
    const float* ff1_b        = (const float*)d_in[12];
    const float* ff2_w        = (const float*)d_in[13];
    const float* ff2_b        = (const float*)d_in[14];
    const float* ln_out_w     = (const float*)d_in[15];
    const float* ln_out_b     = (const float*)d_in[16];
    const float* out_w        = (const float*)d_in[17];
    const float* out_b        = (const float*)d_in[18];

    float *px, *pxn, *pqkv, *pattn, *ph1, *phg, *ptok, *ppat, *pjt;
    cudaGetSymbolAddress((void**)&px,    g_x);
    cudaGetSymbolAddress((void**)&pxn,   g_xn);
    cudaGetSymbolAddress((void**)&pqkv,  g_qkv);
    cudaGetSymbolAddress((void**)&pattn, g_attn);
    cudaGetSymbolAddress((void**)&ph1,   g_h1);
    cudaGetSymbolAddress((void**)&phg,   g_hg);
    cudaGetSymbolAddress((void**)&ptok,  g_tok);
    cudaGetSymbolAddress((void**)&ppat,  g_pat);
    cudaGetSymbolAddress((void**)&pjt,   g_jt);

    // setup: rotary tables, patchify, patch embed, assemble token stream
    k_sincos<<<(NPATCH * 32 + 255) / 256, 256>>>();
    k_im2col<<<(B_ * NSP * DIMC + 255) / 256, 256>>>(video);
    launch_sgemm(ppat, patch_w, patch_b, nullptr, ptok, B_ * NSP, DIMC, DIMC, true, false);
    k_assemble<<<(B_ * NTOK * DIMC + 255) / 256, 256>>>(joints_token);

    for (int l = 0; l < 12; l++) {
        k_ln<<<ROWS, 256>>>(px, ln_attn_w + l * 512, ln_attn_b + l * 512, pxn);
        launch_sgemm(pxn, qkv_w + (size_t)l * 512 * 1536, nullptr, nullptr,
                     pqkv, ROWS, 1536, 512, false, false);
        k_joints_attn<<<B_ * 8 * NJx, 256>>>();                 // pre-rope keys/values
        k_rope<<<(B_ * NTOK * 8 * 32 + 255) / 256, 256>>>();    // scale q, rotate spatial q/k
        k_frame_attn<<<dim3(NPATCH, B_ * 8 * F_), 256>>>();
        launch_sgemm(pattn, attn_out_w + (size_t)l * 512 * 512, attn_out_b + l * 512,
                     px, px, ROWS, 512, 512, true, true);       // x += proj(attn)
        k_ln<<<ROWS, 256>>>(px, ln_ff_w + l * 512, ln_ff_b + l * 512, pxn);
        launch_sgemm(pxn, ff1_w + (size_t)l * 512 * 4096, ff1_b + (size_t)l * 4096, nullptr,
                     ph1, ROWS, 4096, 512, true, false);
        k_geglu<<<(int)(((size_t)ROWS * 2048 + 255) / 256), 256>>>();
        launch_sgemm(phg, ff2_w + (size_t)l * 2048 * 512, ff2_b + l * 512,
                     px, px, ROWS, 512, 2048, true, true);      // x += ff2(hg)
    }

    // head: LN over joint tokens, final projection -> (2,24,4,96) contiguous
    k_ln_gather<<<48, 256>>>(ln_out_w, ln_out_b);
    launch_sgemm(pjt, out_w, out_b, nullptr, (float*)d_out, 48, 384, 512, true, false);
}

// round 14
// speedup vs baseline: 2.2849x; 1.4305x over previous
#include <cuda_runtime.h>
#include <cuda_bf16.h>
#include <math.h>
#include <stdint.h>

// ---------------- problem constants ----------------
#define B_      2
#define F_      16
#define NJx     24
#define NPATCH  196          // 14*14
#define NSP     3136         // F_*NPATCH
#define NTOK    3160         // NJx + NSP
#define DIMC    512
#define ROWS    (B_*NTOK)    // 6320

// ---------------- scratch (device globals; no runtime alloc) ----------------
__device__ float g_x   [B_*NTOK*DIMC];
__device__ float g_qkv [B_*NTOK*1536];
__device__ float g_h1  [(size_t)B_*NTOK*4096];
__device__ float g_tok [B_*NSP*DIMC];
__device__ float g_sin [NPATCH*32];
__device__ float g_cos [NPATCH*32];
__device__ float g_jt  [48*DIMC];

// bf16 hi/lo activation operands (written fused by producers)
__device__ __nv_bfloat16 g_xn_hi  [ROWS*DIMC];
__device__ __nv_bfloat16 g_xn_lo  [ROWS*DIMC];
__device__ __nv_bfloat16 g_attn_hi[ROWS*DIMC];
__device__ __nv_bfloat16 g_attn_lo[ROWS*DIMC];
__device__ __nv_bfloat16 g_hg_hi  [(size_t)ROWS*2048];
__device__ __nv_bfloat16 g_hg_lo  [(size_t)ROWS*2048];
__device__ __nv_bfloat16 g_pat_hi [B_*NSP*DIMC];
__device__ __nv_bfloat16 g_pat_lo [B_*NSP*DIMC];

// transposed bf16 hi/lo weights ([N,K] layout)
__device__ __nv_bfloat16 g_patchT_hi[512*512];
__device__ __nv_bfloat16 g_patchT_lo[512*512];
__device__ __nv_bfloat16 g_qkvT_hi [12*1536*512];
__device__ __nv_bfloat16 g_qkvT_lo [12*1536*512];
__device__ __nv_bfloat16 g_outT_hi [12*512*512];
__device__ __nv_bfloat16 g_outT_lo [12*512*512];
__device__ __nv_bfloat16 g_ff1T_hi [(size_t)12*4096*512];
__device__ __nv_bfloat16 g_ff1T_lo [(size_t)12*4096*512];
__device__ __nv_bfloat16 g_ff2T_hi [(size_t)12*512*2048];
__device__ __nv_bfloat16 g_ff2T_lo [(size_t)12*512*2048];

// ---------------- helpers ----------------
__device__ __forceinline__ uint32_t smem_u32(const void* p) {
    uint32_t a;
    asm("{ .reg .u64 t; cvta.to.shared.u64 t, %1; cvt.u32.u64 %0, t; }" : "=r"(a) : "l"(p));
    return a;
}
__device__ __forceinline__ void cp_async16(uint32_t dst, const void* src, bool pred) {
    int sz = pred ? 16 : 0;
    asm volatile("cp.async.ca.shared.global [%0], [%1], 16, %2;"
                 :: "r"(dst), "l"(src), "r"(sz) : "memory");
}
__device__ __forceinline__ void cp_commit() {
    asm volatile("cp.async.commit_group;" ::: "memory");
}
template<int NW> __device__ __forceinline__ void cp_wait() {
    asm volatile("cp.async.wait_group %0;" :: "n"(NW) : "memory");
}
__device__ __forceinline__ void ldmx4(uint32_t* r, uint32_t addr) {
    asm volatile("ldmatrix.sync.aligned.m8n8.x4.shared.b16 {%0,%1,%2,%3}, [%4];"
                 : "=r"(r[0]), "=r"(r[1]), "=r"(r[2]), "=r"(r[3]) : "r"(addr));
}
__device__ __forceinline__ void mma16816(float* c, const uint32_t* a, const uint32_t* b) {
    asm volatile("mma.sync.aligned.m16n8k16.row.col.f32.bf16.bf16.f32 "
                 "{%0,%1,%2,%3}, {%4,%5,%6,%7}, {%8,%9}, {%0,%1,%2,%3};"
                 : "+f"(c[0]), "+f"(c[1]), "+f"(c[2]), "+f"(c[3])
                 : "r"(a[0]), "r"(a[1]), "r"(a[2]), "r"(a[3]), "r"(b[0]), "r"(b[1]));
}
__device__ __forceinline__ void split2(float v, __nv_bfloat16& h, __nv_bfloat16& l) {
    h = __float2bfloat16(v);
    l = __float2bfloat16(v - __bfloat162float(h));
}

// ---------------- block reductions (blockDim.x == 256) ----------------
__device__ __forceinline__ float warp_sum(float v) {
    #pragma unroll
    for (int o = 16; o > 0; o >>= 1) v += __shfl_xor_sync(0xffffffffu, v, o);
    return v;
}
__device__ __forceinline__ float warp_max(float v) {
    #pragma unroll
    for (int o = 16; o > 0; o >>= 1) v = fmaxf(v, __shfl_xor_sync(0xffffffffu, v, o));
    return v;
}
__device__ __forceinline__ float block_sum(float v, float* red) {
    v = warp_sum(v);
    int lane = threadIdx.x & 31, w = threadIdx.x >> 5;
    if (lane == 0) red[w] = v;
    __syncthreads();
    if (threadIdx.x < 32) {
        float r = (threadIdx.x < 8) ? red[threadIdx.x] : 0.f;
        r = warp_sum(r);
        if (threadIdx.x == 0) red[0] = r;
    }
    __syncthreads();
    float out = red[0];
    __syncthreads();
    return out;
}
__device__ __forceinline__ float block_max(float v, float* red) {
    v = warp_max(v);
    int lane = threadIdx.x & 31, w = threadIdx.x >> 5;
    if (lane == 0) red[w] = v;
    __syncthreads();
    if (threadIdx.x < 32) {
        float r = (threadIdx.x < 8) ? red[threadIdx.x] : -INFINITY;
        r = warp_max(r);
        if (threadIdx.x == 0) red[0] = r;
    }
    __syncthreads();
    float out = red[0];
    __syncthreads();
    return out;
}

// ---------------- weight prep: W[K,N] fp32 -> T_hi/T_lo [N,K] bf16 ----------------
__global__ __launch_bounds__(256) void k_wprep(const float* __restrict__ W,
                                               __nv_bfloat16* __restrict__ Thi,
                                               __nv_bfloat16* __restrict__ Tlo,
                                               int K, int N) {
    __shared__ float tile[32][33];
    int k0 = blockIdx.y * 32, n0 = blockIdx.x * 32;
    int tx = threadIdx.x & 31, ty = threadIdx.x >> 5;
    #pragma unroll
    for (int r = ty; r < 32; r += 8)
        tile[r][tx] = W[(size_t)(k0 + r) * N + n0 + tx];
    __syncthreads();
    #pragma unroll
    for (int r = ty; r < 32; r += 8) {
        float v = tile[tx][r];     // element (k0+tx, n0+r)
        __nv_bfloat16 hi, lo;
        split2(v, hi, lo);
        size_t o = (size_t)(n0 + r) * K + k0 + tx;
        Thi[o] = hi; Tlo[o] = lo;
    }
}

// ---------------- bf16x3 HMMA GEMM ----------------
// C[M,N] = Ah*Bh^T + Ah*Bl^T + Al*Bh^T  (+bias)(+res)
// A*: [M,K] bf16 row-major.  B*: [N,K] bf16 row-major (K-major, i.e. col-major B).
// 128x128 CTA tile, BK=32, 256 threads, double-buffered cp.async.
#define GPITCH 40                 // smem row pitch in elements (80B, conflict-free)
#define GTILE_B (128*GPITCH*2)    // 10240 bytes per tile
#define GSMEM   (GTILE_B*8)       // 4 tiles x 2 stages = 81920

__device__ __forceinline__ void gemm_issue(
    uint32_t sb, int stage, int kc, int t, int bm, int bn,
    const __nv_bfloat16* __restrict__ Ah, const __nv_bfloat16* __restrict__ Al,
    const __nv_bfloat16* __restrict__ Bh, const __nv_bfloat16* __restrict__ Bl,
    int M, int K)
{
    uint32_t s0 = sb + (uint32_t)stage * 4 * GTILE_B;
    int k0 = kc << 5;
    #pragma unroll
    for (int j = 0; j < 2; j++) {
        int i = t + j * 256;
        int row = i >> 2, ch = (i & 3) << 3;
        uint32_t doff = (uint32_t)(row * GPITCH + ch) * 2;
        int gra = bm + row;
        bool pa = gra < M;
        size_t aoff = (size_t)(pa ? gra : 0) * K + k0 + ch;
        cp_async16(s0 + 0 * GTILE_B + doff, Ah + aoff, pa);
        cp_async16(s0 + 1 * GTILE_B + doff, Al + aoff, pa);
        size_t boff = (size_t)(bn + row) * K + k0 + ch;
        cp_async16(s0 + 2 * GTILE_B + doff, Bh + boff, true);
        cp_async16(s0 + 3 * GTILE_B + doff, Bl + boff, true);
    }
    cp_commit();
}

__global__ __launch_bounds__(256, 2) void k_mma_gemm(
    const __nv_bfloat16* __restrict__ Ah, const __nv_bfloat16* __restrict__ Al,
    const __nv_bfloat16* __restrict__ Bh, const __nv_bfloat16* __restrict__ Bl,
    const float* __restrict__ bias, const float* __restrict__ res,
    float* __restrict__ C, int M, int N, int K, int BIAS, int RES)
{
    extern __shared__ char smem[];
    uint32_t sb = smem_u32(smem);
    int t = threadIdx.x, lane = t & 31, wid = t >> 5;
    int bm = blockIdx.y * 128, bn = blockIdx.x * 128;
    int wm = (wid >> 2) * 64, wn = (wid & 3) * 32;

    float c[4][4][4];
    #pragma unroll
    for (int mi = 0; mi < 4; mi++)
        #pragma unroll
        for (int ni = 0; ni < 4; ni++)
            #pragma unroll
            for (int f = 0; f < 4; f++) c[mi][ni][f] = 0.f;

    int nk = K >> 5;
    gemm_issue(sb, 0, 0, t, bm, bn, Ah, Al, Bh, Bl, M, K);

    int lr = lane & 15;             // row within 16
    int lc = ((lane >> 4) & 1) << 3; // 0 or 8 (k sub-column)

    for (int kc = 0; kc < nk; kc++) {
        if (kc + 1 < nk) {
            gemm_issue(sb, (kc + 1) & 1, kc + 1, t, bm, bn, Ah, Al, Bh, Bl, M, K);
            cp_wait<1>();
        } else {
            cp_wait<0>();
        }
        __syncthreads();

        uint32_t sA  = sb + (uint32_t)(kc & 1) * 4 * GTILE_B;
        uint32_t sAl = sA + GTILE_B;
        uint32_t sBh = sA + 2 * GTILE_B;
        uint32_t sBl = sA + 3 * GTILE_B;

        #pragma unroll
        for (int ks = 0; ks < 2; ks++) {
            int kcol = ks * 16 + lc;
            uint32_t a[4][4], bhr[4][2], blr[4][2];
            #pragma unroll
            for (int mi = 0; mi < 4; mi++)
                ldmx4(a[mi], sA + (uint32_t)((wm + mi * 16 + lr) * GPITCH + kcol) * 2);
            #pragma unroll
            for (int nh = 0; nh < 2; nh++) {
                uint32_t r[4];
                ldmx4(r, sBh + (uint32_t)((wn + nh * 16 + lr) * GPITCH + kcol) * 2);
                bhr[nh * 2][0] = r[0]; bhr[nh * 2][1] = r[2];
                bhr[nh * 2 + 1][0] = r[1]; bhr[nh * 2 + 1][1] = r[3];
                ldmx4(r, sBl + (uint32_t)((wn + nh * 16 + lr) * GPITCH + kcol) * 2);
                blr[nh * 2][0] = r[0]; blr[nh * 2][1] = r[2];
                blr[nh * 2 + 1][0] = r[1]; blr[nh * 2 + 1][1] = r[3];
            }
            #pragma unroll
            for (int mi = 0; mi < 4; mi++)
                #pragma unroll
                for (int ni = 0; ni < 4; ni++) {
                    mma16816(c[mi][ni], a[mi], bhr[ni]);
                    mma16816(c[mi][ni], a[mi], blr[ni]);
                }
            // reload A-lo into the same registers, third product
            #pragma unroll
            for (int mi = 0; mi < 4; mi++)
                ldmx4(a[mi], sAl + (uint32_t)((wm + mi * 16 + lr) * GPITCH + kcol) * 2);
            #pragma unroll
            for (int mi = 0; mi < 4; mi++)
                #pragma unroll
                for (int ni = 0; ni < 4; ni++)
                    mma16816(c[mi][ni], a[mi], bhr[ni]);
        }
        __syncthreads();
    }

    // epilogue: direct global stores (float2), fused bias/residual
    int row0 = bm + wm + (lane >> 2);
    int col0 = bn + wn + (lane & 3) * 2;
    #pragma unroll
    for (int mi = 0; mi < 4; mi++) {
        #pragma unroll
        for (int hh = 0; hh < 2; hh++) {
            int r = row0 + mi * 16 + hh * 8;
            if (r >= M) continue;
            #pragma unroll
            for (int ni = 0; ni < 4; ni++) {
                int col = col0 + ni * 8;
                float2 v = make_float2(c[mi][ni][hh * 2], c[mi][ni][hh * 2 + 1]);
                if (BIAS) {
                    v.x += bias[col]; v.y += bias[col + 1];
                }
                if (RES) {
                    float2 rr = *reinterpret_cast<const float2*>(res + (size_t)r * N + col);
                    v.x += rr.x; v.y += rr.y;
                }
                *reinterpret_cast<float2*>(C + (size_t)r * N + col) = v;
            }
        }
    }
}

// ---------------- fp32 SGEMM (tiny head GEMM only) ----------------
template<int BIAS, int RES>
__global__ __launch_bounds__(256) void k_sgemm(
    const float* __restrict__ A, const float* __restrict__ B,
    const float* __restrict__ bias, const float* __restrict__ res,
    float* __restrict__ C, int M, int N, int K)
{
    __shared__ float As[8][128];
    __shared__ float Bs[8][128];
    int tid = threadIdx.x;
    int bm = blockIdx.y * 128;
    int bn = blockIdx.x * 128;
    int tx = tid & 15, ty = tid >> 4;
    int ar = tid >> 1, ac = (tid & 1) * 4;
    int br = tid >> 5, bc = (tid & 31) * 4;

    float acc[8][8];
    #pragma unroll
    for (int i = 0; i < 8; i++)
        #pragma unroll
        for (int j = 0; j < 8; j++) acc[i][j] = 0.f;

    bool aval = (bm + ar) < M;
    const float* Aptr = A + (size_t)(bm + ar) * K + ac;
    const float* Bptr = B + (size_t)br * N + bn + bc;

    for (int k0 = 0; k0 < K; k0 += 8) {
        float4 av = make_float4(0.f, 0.f, 0.f, 0.f);
        if (aval) av = *reinterpret_cast<const float4*>(Aptr + k0);
        As[ac + 0][ar] = av.x; As[ac + 1][ar] = av.y;
        As[ac + 2][ar] = av.z; As[ac + 3][ar] = av.w;
        float4 bv = *reinterpret_cast<const float4*>(Bptr + (size_t)k0 * N);
        *reinterpret_cast<float4*>(&Bs[br][bc]) = bv;
        __syncthreads();
        #pragma unroll
        for (int kk = 0; kk < 8; kk++) {
            float af[8], bf[8];
            *reinterpret_cast<float4*>(&af[0]) = *reinterpret_cast<const float4*>(&As[kk][ty * 4]);
            *reinterpret_cast<float4*>(&af[4]) = *reinterpret_cast<const float4*>(&As[kk][64 + ty * 4]);
            *reinterpret_cast<float4*>(&bf[0]) = *reinterpret_cast<const float4*>(&Bs[kk][tx * 4]);
            *reinterpret_cast<float4*>(&bf[4]) = *reinterpret_cast<const float4*>(&Bs[kk][64 + tx * 4]);
            #pragma unroll
            for (int i = 0; i < 8; i++)
                #pragma unroll
                for (int j = 0; j < 8; j++)
                    acc[i][j] = fmaf(af[i], bf[j], acc[i][j]);
        }
        __syncthreads();
    }

    #pragma unroll
    for (int i = 0; i < 8; i++) {
        int row = bm + ((i < 4) ? (ty * 4 + i) : (64 + ty * 4 + i - 4));
        if (row >= M) continue;
        #pragma unroll
        for (int jh = 0; jh < 2; jh++) {
            int col = bn + ((jh == 0) ? (tx * 4) : (64 + tx * 4));
            float4 v;
            v.x = acc[i][jh * 4 + 0]; v.y = acc[i][jh * 4 + 1];
            v.z = acc[i][jh * 4 + 2]; v.w = acc[i][jh * 4 + 3];
            if (BIAS) {
                float4 b4 = *reinterpret_cast<const float4*>(bias + col);
                v.x += b4.x; v.y += b4.y; v.z += b4.z; v.w += b4.w;
            }
            if (RES) {
                float4 r4 = *reinterpret_cast<const float4*>(res + (size_t)row * N + col);
                v.x += r4.x; v.y += r4.y; v.z += r4.z; v.w += r4.w;
            }
            *reinterpret_cast<float4*>(C + (size_t)row * N + col) = v;
        }
    }
}

// ---------------- rotary tables ----------------
__global__ void k_sincos() {
    int idx = blockIdx.x * blockDim.x + threadIdx.x;
    if (idx >= NPATCH * 32) return;
    int p = idx >> 5, s = idx & 31;
    int ph = p / 14, pw = p % 14;
    int ss = (s < 16) ? s : (s - 16);
    float scale = exp2f((float)ss * (2.321928094887362f / 15.f));
    int pos_i = (s < 16) ? ph : pw;
    float pos = -1.f + 2.f * (float)pos_i / 13.f;
    float ang = pos * scale * 3.14159265358979323846f;
    g_sin[idx] = sinf(ang);
    g_cos[idx] = cosf(ang);
}

// ---------------- patch extraction (im2col, writes bf16 hi/lo) ----------------
__global__ void k_im2col(const float* __restrict__ video) {
    size_t idx = (size_t)blockIdx.x * blockDim.x + threadIdx.x;
    if (idx >= (size_t)B_ * NSP * DIMC) return;
    int e = (int)(idx & 511);
    size_t r = idx >> 9;
    int bb = (int)(r / NSP); int t = (int)(r % NSP);
    int fr = t / NPATCH; int pp = t % NPATCH;
    int ph = pp / 14, pw = pp % 14;
    int py = e >> 5, px = (e >> 1) & 15, cc = e & 1;
    size_t vidx = ((((size_t)(bb * F_ + fr) * 2 + cc) * 224 + (ph * 16 + py)) * 224 + (pw * 16 + px));
    float v = video[vidx];
    __nv_bfloat16 hi, lo;
    split2(v, hi, lo);
    g_pat_hi[idx] = hi; g_pat_lo[idx] = lo;
}

// ---------------- token assembly ----------------
__global__ void k_assemble(const float* __restrict__ joints_token) {
    size_t idx = (size_t)blockIdx.x * blockDim.x + threadIdx.x;
    if (idx >= (size_t)B_ * NTOK * DIMC) return;
    int col = (int)(idx & 511);
    size_t r = idx >> 9;
    int bb = (int)(r / NTOK); int i = (int)(r % NTOK);
    g_x[idx] = (i < NJx) ? joints_token[i * DIMC + col]
                         : g_tok[((size_t)bb * NSP + (i - NJx)) * DIMC + col];
}

// ---------------- LayerNorm (fused bf16 hi/lo split output) ----------------
__global__ __launch_bounds__(256) void k_ln(const float* __restrict__ in,
                                            const float* __restrict__ w,
                                            const float* __restrict__ b,
                                            __nv_bfloat16* __restrict__ ohi,
                                            __nv_bfloat16* __restrict__ olo) {
    __shared__ float red[32];
    int row = blockIdx.x;
    int t = threadIdx.x;
    const float* ri = in + (size_t)row * DIMC;
    float v0 = ri[t], v1 = ri[t + 256];
    float mean = block_sum(v0 + v1, red) * (1.f / 512.f);
    float d0 = v0 - mean, d1 = v1 - mean;
    float var = block_sum(d0 * d0 + d1 * d1, red) * (1.f / 512.f);
    float rs = rsqrtf(var + 1e-5f);
    float y0 = d0 * rs * w[t] + b[t];
    float y1 = d1 * rs * w[t + 256] + b[t + 256];
    size_t base = (size_t)row * DIMC;
    __nv_bfloat16 h, l;
    split2(y0, h, l); ohi[base + t] = h;       olo[base + t] = l;
    split2(y1, h, l); ohi[base + t + 256] = h; olo[base + t + 256] = l;
}

// final LN on joint tokens (fp32 out, tiny head)
__global__ __launch_bounds__(256) void k_ln_gather(const float* __restrict__ w,
                                                   const float* __restrict__ b) {
    __shared__ float red[32];
    int row = blockIdx.x;
    int bb = row / NJx, i = row % NJx;
    int t = threadIdx.x;
    const float* ri = g_x + ((size_t)bb * NTOK + i) * DIMC;
    float v0 = ri[t], v1 = ri[t + 256];
    float mean = block_sum(v0 + v1, red) * (1.f / 512.f);
    float d0 = v0 - mean, d1 = v1 - mean;
    float var = block_sum(d0 * d0 + d1 * d1, red) * (1.f / 512.f);
    float rs = rsqrtf(var + 1e-5f);
    float* ro = g_jt + (size_t)row * DIMC;
    ro[t]       = d0 * rs * w[t]       + b[t];
    ro[t + 256] = d1 * rs * w[t + 256] + b[t + 256];
}

// ---------------- joints attention (pre-rope keys/values; split output) ----------------
__global__ __launch_bounds__(256) void k_joints_attn() {
    __shared__ float sq[64];
    __shared__ float s[NTOK];
    __shared__ float red[32];
    __shared__ float sacc[4][64];
    int bidx = blockIdx.x;
    int jq = bidx % NJx;
    int h  = (bidx / NJx) & 7;
    int bb = bidx / (NJx * 8);
    int t = threadIdx.x;
    const float* qp = g_qkv + ((size_t)(bb * NTOK + jq)) * 1536 + h * 64;
    if (t < 64) sq[t] = qp[t] * 0.125f;
    __syncthreads();
    for (int j = t; j < NTOK; j += 256) {
        const float* kp = g_qkv + ((size_t)(bb * NTOK + j)) * 1536 + 512 + h * 64;
        float acc = 0.f;
        #pragma unroll
        for (int d = 0; d < 64; d += 4) {
            float4 kv = *reinterpret_cast<const float4*>(kp + d);
            acc += sq[d] * kv.x + sq[d + 1] * kv.y + sq[d + 2] * kv.z + sq[d + 3] * kv.w;
        }
        s[j] = acc;
    }
    __syncthreads();
    float m = -INFINITY;
    for (int j = t; j < NTOK; j += 256) m = fmaxf(m, s[j]);
    m = block_max(m, red);
    float lsum = 0.f;
    for (int j = t; j < NTOK; j += 256) { float e = expf(s[j] - m); s[j] = e; lsum += e; }
    float denom = block_sum(lsum, red);
    float inv = 1.f / denom;
    int d = t & 63, c = t >> 6;
    float acc = 0.f;
    for (int j = c; j < NTOK; j += 4)
        acc += s[j] * g_qkv[((size_t)(bb * NTOK + j)) * 1536 + 1024 + h * 64 + d];
    sacc[c][d] = acc;
    __syncthreads();
    if (t < 64) {
        float o = (sacc[0][t] + sacc[1][t] + sacc[2][t] + sacc[3][t]) * inv;
        size_t off = ((size_t)(bb * NTOK + jq)) * 512 + h * 64 + t;
        __nv_bfloat16 hi, lo;
        split2(o, hi, lo);
        g_attn_hi[off] = hi; g_attn_lo[off] = lo;
    }
}

// ---------------- rope + q-scale ----------------
__global__ void k_rope() {
    int idx = blockIdx.x * blockDim.x + threadIdx.x;
    if (idx >= B_ * NTOK * 8 * 32) return;
    int s = idx & 31;
    int h = (idx >> 5) & 7;
    int rest = idx >> 8;
    int i = rest % NTOK;
    int bb = rest / NTOK;
    size_t base = ((size_t)(bb * NTOK + i)) * 1536 + h * 64 + 2 * s;
    float q0 = g_qkv[base] * 0.125f, q1 = g_qkv[base + 1] * 0.125f;
    if (i >= NJx) {
        int p = (i - NJx) % NPATCH;
        float c = g_cos[p * 32 + s], sn = g_sin[p * 32 + s];
        float nq0 = q0 * c - q1 * sn, nq1 = q1 * c + q0 * sn;
        q0 = nq0; q1 = nq1;
        float k0 = g_qkv[base + 512], k1 = g_qkv[base + 513];
        g_qkv[base + 512] = k0 * c - k1 * sn;
        g_qkv[base + 513] = k1 * c + k0 * sn;
    }
    g_qkv[base] = q0; g_qkv[base + 1] = q1;
}

// ---------------- per-frame attention (split output) ----------------
__global__ __launch_bounds__(256) void k_frame_attn() {
    __shared__ float sq[64];
    __shared__ float s[224];
    __shared__ float red[32];
    __shared__ float sacc[4][64];
    int i = blockIdx.x;
    int g = blockIdx.y;
    int fr = g & 15;
    int bh = g >> 4;
    int h = bh & 7;
    int bb = bh >> 3;
    int t = threadIdx.x;
    int ti = NJx + fr * NPATCH + i;
    const float* qp = g_qkv + ((size_t)(bb * NTOK + ti)) * 1536 + h * 64;
    if (t < 64) sq[t] = qp[t];
    __syncthreads();
    if (t < 220) {
        int tj = (t < NJx) ? t : NJx + fr * NPATCH + (t - NJx);
        const float* kp = g_qkv + ((size_t)(bb * NTOK + tj)) * 1536 + 512 + h * 64;
        float acc = 0.f;
        #pragma unroll
        for (int d = 0; d < 64; d += 4) {
            float4 kv = *reinterpret_cast<const float4*>(kp + d);
            acc += sq[d] * kv.x + sq[d + 1] * kv.y + sq[d + 2] * kv.z + sq[d + 3] * kv.w;
        }
        s[t] = acc;
    }
    __syncthreads();
    float m = (t < 220) ? s[t] : -INFINITY;
    m = block_max(m, red);
    float e = 0.f;
    if (t < 220) { e = expf(s[t] - m); s[t] = e; }
    float denom = block_sum(e, red);
    float inv = 1.f / denom;
    int d = t & 63, c = t >> 6;
    float acc = 0.f;
    for (int j = c; j < 220; j += 4) {
        int tj = (j < NJx) ? j : NJx + fr * NPATCH + (j - NJx);
        acc += s[j] * g_qkv[((size_t)(bb * NTOK + tj)) * 1536 + 1024 + h * 64 + d];
    }
    sacc[c][d] = acc;
    __syncthreads();
    if (t < 64) {
        float o = (sacc[0][t] + sacc[1][t] + sacc[2][t] + sacc[3][t]) * inv;
        size_t off = ((size_t)(bb * NTOK + ti)) * 512 + h * 64 + t;
        __nv_bfloat16 hi, lo;
        split2(o, hi, lo);
        g_attn_hi[off] = hi; g_attn_lo[off] = lo;
    }
}

// ---------------- GEGLU (fused bf16 hi/lo split output) ----------------
__global__ void k_geglu() {
    size_t idx = (size_t)blockIdx.x * blockDim.x + threadIdx.x;
    if (idx >= (size_t)ROWS * 2048) return;
    size_t r = idx >> 11;
    int j = (int)(idx & 2047);
    float a = g_h1[r * 4096 + j];
    float g = g_h1[r * 4096 + 2048 + j];
    float ge = 0.5f * g * (1.f + erff(g * 0.7071067811865476f));
    float v = a * ge;
    __nv_bfloat16 hi, lo;
    split2(v, hi, lo);
    g_hg_hi[idx] = hi; g_hg_lo[idx] = lo;
}

// ---------------- host helpers ----------------
static void launch_mma(const __nv_bfloat16* Ah, const __nv_bfloat16* Al,
                       const __nv_bfloat16* Bh, const __nv_bfloat16* Bl,
                       const float* bias, const float* res, float* C,
                       int M, int N, int K, int BIAS, int RES) {
    dim3 grid(N / 128, (M + 127) / 128);
    k_mma_gemm<<<grid, 256, GSMEM>>>(Ah, Al, Bh, Bl, bias, res, C, M, N, K, BIAS, RES);
}

extern "C" void kernel_launch(void* const* d_in, const int* in_sizes, int n_in,
                              void* d_out, int out_size) {
    const float* video        = (const float*)d_in[0];
    const float* patch_w      = (const float*)d_in[1];
    const float* patch_b      = (const float*)d_in[2];
    const float* joints_token = (const float*)d_in[3];
    const float* ln_attn_w    = (const float*)d_in[4];
    const float* ln_attn_b    = (const float*)d_in[5];
    const float* qkv_w        = (const float*)d_in[6];
    const float* attn_out_w   = (const float*)d_in[7];
    const float* attn_out_b   = (const float*)d_in[8];
    const float* ln_ff_w      = (const float*)d_in[9];
    const float* ln_ff_b      = (const float*)d_in[10];
    const float* ff1_w        = (const float*)d_in[11];
    const float* ff1_b        = (const float*)d_in[12];
    const float* ff2_w        = (const float*)d_in[13];
    const float* ff2_b        = (const float*)d_in[14];
    const float* ln_out_w     = (const float*)d_in[15];
    const float* ln_out_b     = (const float*)d_in[16];
    const float* out_w        = (const float*)d_in[17];
    const float* out_b        = (const float*)d_in[18];

    static bool attr_set = false;
    if (!attr_set) {
        cudaFuncSetAttribute(k_mma_gemm, cudaFuncAttributeMaxDynamicSharedMemorySize, GSMEM);
        attr_set = true;
    }

    float *px, *pqkv, *ph1, *ptok, *pjt;
    cudaGetSymbolAddress((void**)&px,    g_x);
    cudaGetSymbolAddress((void**)&pqkv,  g_qkv);
    cudaGetSymbolAddress((void**)&ph1,   g_h1);
    cudaGetSymbolAddress((void**)&ptok,  g_tok);
    cudaGetSymbolAddress((void**)&pjt,   g_jt);

    __nv_bfloat16 *xnh, *xnl, *ath, *atl, *hgh, *hgl, *pth, *ptl;
    cudaGetSymbolAddress((void**)&xnh, g_xn_hi);
    cudaGetSymbolAddress((void**)&xnl, g_xn_lo);
    cudaGetSymbolAddress((void**)&ath, g_attn_hi);
    cudaGetSymbolAddress((void**)&atl, g_attn_lo);
    cudaGetSymbolAddress((void**)&hgh, g_hg_hi);
    cudaGetSymbolAddress((void**)&hgl, g_hg_lo);
    cudaGetSymbolAddress((void**)&pth, g_pat_hi);
    cudaGetSymbolAddress((void**)&ptl, g_pat_lo);

    __nv_bfloat16 *patchThi, *patchTlo, *qkvThi, *qkvTlo, *outThi, *outTlo,
                  *ff1Thi, *ff1Tlo, *ff2Thi, *ff2Tlo;
    cudaGetSymbolAddress((void**)&patchThi, g_patchT_hi);
    cudaGetSymbolAddress((void**)&patchTlo, g_patchT_lo);
    cudaGetSymbolAddress((void**)&qkvThi,   g_qkvT_hi);
    cudaGetSymbolAddress((void**)&qkvTlo,   g_qkvT_lo);
    cudaGetSymbolAddress((void**)&outThi,   g_outT_hi);
    cudaGetSymbolAddress((void**)&outTlo,   g_outT_lo);
    cudaGetSymbolAddress((void**)&ff1Thi,   g_ff1T_hi);
    cudaGetSymbolAddress((void**)&ff1Tlo,   g_ff1T_lo);
    cudaGetSymbolAddress((void**)&ff2Thi,   g_ff2T_hi);
    cudaGetSymbolAddress((void**)&ff2Tlo,   g_ff2T_lo);

    // ---- weight prep (transpose + bf16 hi/lo split) ----
    k_wprep<<<dim3(512 / 32, 512 / 32), 256>>>(patch_w, patchThi, patchTlo, 512, 512);
    for (int l = 0; l < 12; l++) {
        k_wprep<<<dim3(1536 / 32, 512 / 32), 256>>>(qkv_w + (size_t)l * 512 * 1536,
            qkvThi + (size_t)l * 1536 * 512, qkvTlo + (size_t)l * 1536 * 512, 512, 1536);
        k_wprep<<<dim3(512 / 32, 512 / 32), 256>>>(attn_out_w + (size_t)l * 512 * 512,
            outThi + (size_t)l * 512 * 512, outTlo + (size_t)l * 512 * 512, 512, 512);
        k_wprep<<<dim3(4096 / 32, 512 / 32), 256>>>(ff1_w + (size_t)l * 512 * 4096,
            ff1Thi + (size_t)l * 4096 * 512, ff1Tlo + (size_t)l * 4096 * 512, 512, 4096);
        k_wprep<<<dim3(512 / 32, 2048 / 32), 256>>>(ff2_w + (size_t)l * 2048 * 512,
            ff2Thi + (size_t)l * 512 * 2048, ff2Tlo + (size_t)l * 512 * 2048, 2048, 512);
    }

    // ---- setup ----
    k_sincos<<<(NPATCH * 32 + 255) / 256, 256>>>();
    k_im2col<<<(int)(((size_t)B_ * NSP * DIMC + 255) / 256), 256>>>(video);
    launch_mma(pth, ptl, patchThi, patchTlo, patch_b, nullptr, ptok,
               B_ * NSP, DIMC, DIMC, 1, 0);
    k_assemble<<<(int)(((size_t)B_ * NTOK * DIMC + 255) / 256), 256>>>(joints_token);

    for (int l = 0; l < 12; l++) {
        k_ln<<<ROWS, 256>>>(px, ln_attn_w + l * 512, ln_attn_b + l * 512, xnh, xnl);
        launch_mma(xnh, xnl, qkvThi + (size_t)l * 1536 * 512, qkvTlo + (size_t)l * 1536 * 512,
                   nullptr, nullptr, pqkv, ROWS, 1536, 512, 0, 0);
        k_joints_attn<<<B_ * 8 * NJx, 256>>>();
        k_rope<<<(B_ * NTOK * 8 * 32 + 255) / 256, 256>>>();
        k_frame_attn<<<dim3(NPATCH, B_ * 8 * F_), 256>>>();
        launch_mma(ath, atl, outThi + (size_t)l * 512 * 512, outTlo + (size_t)l * 512 * 512,
                   attn_out_b + l * 512, px, px, ROWS, 512, 512, 1, 1);
        k_ln<<<ROWS, 256>>>(px, ln_ff_w + l * 512, ln_ff_b + l * 512, xnh, xnl);
        launch_mma(xnh, xnl, ff1Thi + (size_t)l * 4096 * 512, ff1Tlo + (size_t)l * 4096 * 512,
                   ff1_b + (size_t)l * 4096, nullptr, ph1, ROWS, 4096, 512, 1, 0);
        k_geglu<<<(int)(((size_t)ROWS * 2048 + 255) / 256), 256>>>();
        launch_mma(hgh, hgl, ff2Thi + (size_t)l * 512 * 2048, ff2Tlo + (size_t)l * 512 * 2048,
                   ff2_b + l * 512, px, px, ROWS, 512, 2048, 1, 1);
    }

    // ---- head (tiny, fp32 path) ----
    k_ln_gather<<<48, 256>>>(ln_out_w, ln_out_b);
    {
        dim3 grid(384 / 128, 1);
        k_sgemm<1, 0><<<grid, 256>>>(pjt, out_w, out_b, nullptr, (float*)d_out, 48, 384, 512);
    }
}

// round 15
// speedup vs baseline: 2.6149x; 1.1444x over previous
#include <cuda_runtime.h>
#include <cuda_bf16.h>
#include <math.h>
#include <stdint.h>

// ---------------- problem constants ----------------
#define B_      2
#define F_      16
#define NJx     24
#define NPATCH  196          // 14*14
#define NSP     3136         // F_*NPATCH
#define NTOK    3160         // NJx + NSP
#define DIMC    512
#define ROWS    (B_*NTOK)    // 6320

// ---------------- scratch (device globals; no runtime alloc) ----------------
__device__ float g_x   [B_*NTOK*DIMC];
__device__ float g_qkv [B_*NTOK*1536];
__device__ float g_h1  [(size_t)B_*NTOK*4096];
__device__ float g_tok [B_*NSP*DIMC];
__device__ float g_sin [NPATCH*32];
__device__ float g_cos [NPATCH*32];
__device__ float g_jt  [48*DIMC];

// bf16 hi/lo activation operands (written fused by producers)
__device__ __nv_bfloat16 g_xn_hi  [ROWS*DIMC];
__device__ __nv_bfloat16 g_xn_lo  [ROWS*DIMC];
__device__ __nv_bfloat16 g_attn_hi[ROWS*DIMC];
__device__ __nv_bfloat16 g_attn_lo[ROWS*DIMC];
__device__ __nv_bfloat16 g_hg_hi  [(size_t)ROWS*2048];
__device__ __nv_bfloat16 g_hg_lo  [(size_t)ROWS*2048];
__device__ __nv_bfloat16 g_pat_hi [B_*NSP*DIMC];
__device__ __nv_bfloat16 g_pat_lo [B_*NSP*DIMC];

// transposed bf16 hi/lo weights ([N,K] layout)
__device__ __nv_bfloat16 g_patchT_hi[512*512];
__device__ __nv_bfloat16 g_patchT_lo[512*512];
__device__ __nv_bfloat16 g_qkvT_hi [12*1536*512];
__device__ __nv_bfloat16 g_qkvT_lo [12*1536*512];
__device__ __nv_bfloat16 g_outT_hi [12*512*512];
__device__ __nv_bfloat16 g_outT_lo [12*512*512];
__device__ __nv_bfloat16 g_ff1T_hi [(size_t)12*4096*512];
__device__ __nv_bfloat16 g_ff1T_lo [(size_t)12*4096*512];
__device__ __nv_bfloat16 g_ff2T_hi [(size_t)12*512*2048];
__device__ __nv_bfloat16 g_ff2T_lo [(size_t)12*512*2048];

// ---------------- helpers ----------------
__device__ __forceinline__ uint32_t smem_u32(const void* p) {
    uint32_t a;
    asm("{ .reg .u64 t; cvta.to.shared.u64 t, %1; cvt.u32.u64 %0, t; }" : "=r"(a) : "l"(p));
    return a;
}
__device__ __forceinline__ void cp_async16(uint32_t dst, const void* src, bool pred) {
    int sz = pred ? 16 : 0;
    asm volatile("cp.async.ca.shared.global [%0], [%1], 16, %2;"
                 :: "r"(dst), "l"(src), "r"(sz) : "memory");
}
__device__ __forceinline__ void cp_commit() {
    asm volatile("cp.async.commit_group;" ::: "memory");
}
template<int NW> __device__ __forceinline__ void cp_wait() {
    asm volatile("cp.async.wait_group %0;" :: "n"(NW) : "memory");
}
__device__ __forceinline__ void ldmx4(uint32_t* r, uint32_t addr) {
    asm volatile("ldmatrix.sync.aligned.m8n8.x4.shared.b16 {%0,%1,%2,%3}, [%4];"
                 : "=r"(r[0]), "=r"(r[1]), "=r"(r[2]), "=r"(r[3]) : "r"(addr));
}
__device__ __forceinline__ void mma16816(float* c, const uint32_t* a, const uint32_t* b) {
    asm volatile("mma.sync.aligned.m16n8k16.row.col.f32.bf16.bf16.f32 "
                 "{%0,%1,%2,%3}, {%4,%5,%6,%7}, {%8,%9}, {%0,%1,%2,%3};"
                 : "+f"(c[0]), "+f"(c[1]), "+f"(c[2]), "+f"(c[3])
                 : "r"(a[0]), "r"(a[1]), "r"(a[2]), "r"(a[3]), "r"(b[0]), "r"(b[1]));
}
__device__ __forceinline__ void split2(float v, __nv_bfloat16& h, __nv_bfloat16& l) {
    h = __float2bfloat16(v);
    l = __float2bfloat16(v - __bfloat162float(h));
}

// ---------------- block reductions (blockDim.x == 256) ----------------
__device__ __forceinline__ float warp_sum(float v) {
    #pragma unroll
    for (int o = 16; o > 0; o >>= 1) v += __shfl_xor_sync(0xffffffffu, v, o);
    return v;
}
__device__ __forceinline__ float warp_max(float v) {
    #pragma unroll
    for (int o = 16; o > 0; o >>= 1) v = fmaxf(v, __shfl_xor_sync(0xffffffffu, v, o));
    return v;
}
__device__ __forceinline__ float block_sum(float v, float* red) {
    v = warp_sum(v);
    int lane = threadIdx.x & 31, w = threadIdx.x >> 5;
    if (lane == 0) red[w] = v;
    __syncthreads();
    if (threadIdx.x < 32) {
        float r = (threadIdx.x < 8) ? red[threadIdx.x] : 0.f;
        r = warp_sum(r);
        if (threadIdx.x == 0) red[0] = r;
    }
    __syncthreads();
    float out = red[0];
    __syncthreads();
    return out;
}
__device__ __forceinline__ float block_max(float v, float* red) {
    v = warp_max(v);
    int lane = threadIdx.x & 31, w = threadIdx.x >> 5;
    if (lane == 0) red[w] = v;
    __syncthreads();
    if (threadIdx.x < 32) {
        float r = (threadIdx.x < 8) ? red[threadIdx.x] : -INFINITY;
        r = warp_max(r);
        if (threadIdx.x == 0) red[0] = r;
    }
    __syncthreads();
    float out = red[0];
    __syncthreads();
    return out;
}

// ---------------- weight prep: W[K,N] fp32 -> T_hi/T_lo [N,K] bf16 ----------------
__global__ __launch_bounds__(256) void k_wprep(const float* __restrict__ W,
                                               __nv_bfloat16* __restrict__ Thi,
                                               __nv_bfloat16* __restrict__ Tlo,
                                               int K, int N) {
    __shared__ float tile[32][33];
    int k0 = blockIdx.y * 32, n0 = blockIdx.x * 32;
    int tx = threadIdx.x & 31, ty = threadIdx.x >> 5;
    #pragma unroll
    for (int r = ty; r < 32; r += 8)
        tile[r][tx] = W[(size_t)(k0 + r) * N + n0 + tx];
    __syncthreads();
    #pragma unroll
    for (int r = ty; r < 32; r += 8) {
        float v = tile[tx][r];     // element (k0+tx, n0+r)
        __nv_bfloat16 hi, lo;
        split2(v, hi, lo);
        size_t o = (size_t)(n0 + r) * K + k0 + tx;
        Thi[o] = hi; Tlo[o] = lo;
    }
}

// ---------------- bf16x3 HMMA GEMM v2 ----------------
// C[M,N] = Ah*Bh^T + Ah*Bl^T + Al*Bh^T  (+bias)(+res)
// CTA tile 128x256, BK=32, 256 threads, warp tile 64x64 (2x4 warps),
// 3-stage cp.async ring, one __syncthreads per K-chunk.
// smem stage layout (bytes): Ah@0 (128x40x2), Al@10240, Bh@20480 (256x40x2), Bl@40960
#define GSTAGE 61440
#define GSMEM  (3*GSTAGE)   // 184320

__device__ __forceinline__ void g2_issue(
    uint32_t sb, int stage, int kc, int t, int bm, int bn,
    const __nv_bfloat16* __restrict__ Ah, const __nv_bfloat16* __restrict__ Al,
    const __nv_bfloat16* __restrict__ Bh, const __nv_bfloat16* __restrict__ Bl,
    int M, int K)
{
    uint32_t s0 = sb + (uint32_t)stage * GSTAGE;
    int k0 = kc << 5;
    #pragma unroll
    for (int j = 0; j < 12; j++) {
        int i = t + j * 256;            // 0..3071
        int r = i >> 2, c = i & 3;
        if (r < 128) {
            int gr = bm + r; bool p = gr < M;
            cp_async16(s0 + (uint32_t)(r * 80 + c * 16),
                       Ah + (size_t)(p ? gr : 0) * K + k0 + c * 8, p);
        } else if (r < 256) {
            int rr = r - 128; int gr = bm + rr; bool p = gr < M;
            cp_async16(s0 + 10240u + (uint32_t)(rr * 80 + c * 16),
                       Al + (size_t)(p ? gr : 0) * K + k0 + c * 8, p);
        } else if (r < 512) {
            int rr = r - 256;
            cp_async16(s0 + 20480u + (uint32_t)(rr * 80 + c * 16),
                       Bh + (size_t)(bn + rr) * K + k0 + c * 8, true);
        } else {
            int rr = r - 512;
            cp_async16(s0 + 40960u + (uint32_t)(rr * 80 + c * 16),
                       Bl + (size_t)(bn + rr) * K + k0 + c * 8, true);
        }
    }
    cp_commit();
}

__global__ __launch_bounds__(256, 1) void k_mma_gemm(
    const __nv_bfloat16* __restrict__ Ah, const __nv_bfloat16* __restrict__ Al,
    const __nv_bfloat16* __restrict__ Bh, const __nv_bfloat16* __restrict__ Bl,
    const float* __restrict__ bias, const float* __restrict__ res,
    float* __restrict__ C, int M, int N, int K, int BIAS, int RES)
{
    extern __shared__ char smem[];
    uint32_t sb = smem_u32(smem);
    int t = threadIdx.x, lane = t & 31, wid = t >> 5;
    int bm = blockIdx.y * 128, bn = blockIdx.x * 256;
    int wm = (wid >> 2) * 64, wn = (wid & 3) * 64;

    float c[4][8][4];
    #pragma unroll
    for (int mi = 0; mi < 4; mi++)
        #pragma unroll
        for (int ni = 0; ni < 8; ni++)
            #pragma unroll
            for (int f = 0; f < 4; f++) c[mi][ni][f] = 0.f;

    int nk = K >> 5;
    g2_issue(sb, 0, 0, t, bm, bn, Ah, Al, Bh, Bl, M, K);
    g2_issue(sb, 1, 1, t, bm, bn, Ah, Al, Bh, Bl, M, K);

    int lr = lane & 15;
    int lc = ((lane >> 4) & 1) << 3;

    for (int kc = 0; kc < nk; kc++) {
        if (kc + 1 < nk) cp_wait<1>(); else cp_wait<0>();
        __syncthreads();
        if (kc + 2 < nk)
            g2_issue(sb, (kc + 2) % 3, kc + 2, t, bm, bn, Ah, Al, Bh, Bl, M, K);

        uint32_t st  = sb + (uint32_t)(kc % 3) * GSTAGE;
        uint32_t sAh = st, sAl = st + 10240u, sBh = st + 20480u, sBl = st + 40960u;

        #pragma unroll
        for (int ks = 0; ks < 2; ks++) {
            int kcol = ks * 16 + lc;
            uint32_t a[4][4], bh[8][2], bl[8][2];
            #pragma unroll
            for (int mi = 0; mi < 4; mi++)
                ldmx4(a[mi], sAh + (uint32_t)((wm + mi * 16 + lr) * 40 + kcol) * 2);
            #pragma unroll
            for (int nh = 0; nh < 4; nh++) {
                uint32_t r[4];
                ldmx4(r, sBh + (uint32_t)((wn + nh * 16 + lr) * 40 + kcol) * 2);
                bh[nh * 2][0] = r[0]; bh[nh * 2][1] = r[2];
                bh[nh * 2 + 1][0] = r[1]; bh[nh * 2 + 1][1] = r[3];
                ldmx4(r, sBl + (uint32_t)((wn + nh * 16 + lr) * 40 + kcol) * 2);
                bl[nh * 2][0] = r[0]; bl[nh * 2][1] = r[2];
                bl[nh * 2 + 1][0] = r[1]; bl[nh * 2 + 1][1] = r[3];
            }
            #pragma unroll
            for (int mi = 0; mi < 4; mi++)
                #pragma unroll
                for (int ni = 0; ni < 8; ni++) {
                    mma16816(c[mi][ni], a[mi], bh[ni]);
                    mma16816(c[mi][ni], a[mi], bl[ni]);
                }
            #pragma unroll
            for (int mi = 0; mi < 4; mi++)
                ldmx4(a[mi], sAl + (uint32_t)((wm + mi * 16 + lr) * 40 + kcol) * 2);
            #pragma unroll
            for (int mi = 0; mi < 4; mi++)
                #pragma unroll
                for (int ni = 0; ni < 8; ni++)
                    mma16816(c[mi][ni], a[mi], bh[ni]);
        }
    }

    // epilogue: direct float2 stores, fused bias/residual
    int row0 = bm + wm + (lane >> 2);
    int col0 = bn + wn + (lane & 3) * 2;
    #pragma unroll
    for (int mi = 0; mi < 4; mi++) {
        #pragma unroll
        for (int hh = 0; hh < 2; hh++) {
            int r = row0 + mi * 16 + hh * 8;
            if (r >= M) continue;
            #pragma unroll
            for (int ni = 0; ni < 8; ni++) {
                int col = col0 + ni * 8;
                float2 v = make_float2(c[mi][ni][hh * 2], c[mi][ni][hh * 2 + 1]);
                if (BIAS) { v.x += bias[col]; v.y += bias[col + 1]; }
                if (RES) {
                    float2 rr = *reinterpret_cast<const float2*>(res + (size_t)r * N + col);
                    v.x += rr.x; v.y += rr.y;
                }
                *reinterpret_cast<float2*>(C + (size_t)r * N + col) = v;
            }
        }
    }
}

// ---------------- fp32 SGEMM (tiny head GEMM only) ----------------
template<int BIAS, int RES>
__global__ __launch_bounds__(256) void k_sgemm(
    const float* __restrict__ A, const float* __restrict__ B,
    const float* __restrict__ bias, const float* __restrict__ res,
    float* __restrict__ C, int M, int N, int K)
{
    __shared__ float As[8][128];
    __shared__ float Bs[8][128];
    int tid = threadIdx.x;
    int bm = blockIdx.y * 128;
    int bn = blockIdx.x * 128;
    int tx = tid & 15, ty = tid >> 4;
    int ar = tid >> 1, ac = (tid & 1) * 4;
    int br = tid >> 5, bc = (tid & 31) * 4;

    float acc[8][8];
    #pragma unroll
    for (int i = 0; i < 8; i++)
        #pragma unroll
        for (int j = 0; j < 8; j++) acc[i][j] = 0.f;

    bool aval = (bm + ar) < M;
    const float* Aptr = A + (size_t)(bm + ar) * K + ac;
    const float* Bptr = B + (size_t)br * N + bn + bc;

    for (int k0 = 0; k0 < K; k0 += 8) {
        float4 av = make_float4(0.f, 0.f, 0.f, 0.f);
        if (aval) av = *reinterpret_cast<const float4*>(Aptr + k0);
        As[ac + 0][ar] = av.x; As[ac + 1][ar] = av.y;
        As[ac + 2][ar] = av.z; As[ac + 3][ar] = av.w;
        float4 bv = *reinterpret_cast<const float4*>(Bptr + (size_t)k0 * N);
        *reinterpret_cast<float4*>(&Bs[br][bc]) = bv;
        __syncthreads();
        #pragma unroll
        for (int kk = 0; kk < 8; kk++) {
            float af[8], bf[8];
            *reinterpret_cast<float4*>(&af[0]) = *reinterpret_cast<const float4*>(&As[kk][ty * 4]);
            *reinterpret_cast<float4*>(&af[4]) = *reinterpret_cast<const float4*>(&As[kk][64 + ty * 4]);
            *reinterpret_cast<float4*>(&bf[0]) = *reinterpret_cast<const float4*>(&Bs[kk][tx * 4]);
            *reinterpret_cast<float4*>(&bf[4]) = *reinterpret_cast<const float4*>(&Bs[kk][64 + tx * 4]);
            #pragma unroll
            for (int i = 0; i < 8; i++)
                #pragma unroll
                for (int j = 0; j < 8; j++)
                    acc[i][j] = fmaf(af[i], bf[j], acc[i][j]);
        }
        __syncthreads();
    }

    #pragma unroll
    for (int i = 0; i < 8; i++) {
        int row = bm + ((i < 4) ? (ty * 4 + i) : (64 + ty * 4 + i - 4));
        if (row >= M) continue;
        #pragma unroll
        for (int jh = 0; jh < 2; jh++) {
            int col = bn + ((jh == 0) ? (tx * 4) : (64 + tx * 4));
            float4 v;
            v.x = acc[i][jh * 4 + 0]; v.y = acc[i][jh * 4 + 1];
            v.z = acc[i][jh * 4 + 2]; v.w = acc[i][jh * 4 + 3];
            if (BIAS) {
                float4 b4 = *reinterpret_cast<const float4*>(bias + col);
                v.x += b4.x; v.y += b4.y; v.z += b4.z; v.w += b4.w;
            }
            if (RES) {
                float4 r4 = *reinterpret_cast<const float4*>(res + (size_t)row * N + col);
                v.x += r4.x; v.y += r4.y; v.z += r4.z; v.w += r4.w;
            }
            *reinterpret_cast<float4*>(C + (size_t)row * N + col) = v;
        }
    }
}

// ---------------- rotary tables ----------------
__global__ void k_sincos() {
    int idx = blockIdx.x * blockDim.x + threadIdx.x;
    if (idx >= NPATCH * 32) return;
    int p = idx >> 5, s = idx & 31;
    int ph = p / 14, pw = p % 14;
    int ss = (s < 16) ? s : (s - 16);
    float scale = exp2f((float)ss * (2.321928094887362f / 15.f));
    int pos_i = (s < 16) ? ph : pw;
    float pos = -1.f + 2.f * (float)pos_i / 13.f;
    float ang = pos * scale * 3.14159265358979323846f;
    g_sin[idx] = sinf(ang);
    g_cos[idx] = cosf(ang);
}

// ---------------- patch extraction (im2col, writes bf16 hi/lo) ----------------
__global__ void k_im2col(const float* __restrict__ video) {
    size_t idx = (size_t)blockIdx.x * blockDim.x + threadIdx.x;
    if (idx >= (size_t)B_ * NSP * DIMC) return;
    int e = (int)(idx & 511);
    size_t r = idx >> 9;
    int bb = (int)(r / NSP); int t = (int)(r % NSP);
    int fr = t / NPATCH; int pp = t % NPATCH;
    int ph = pp / 14, pw = pp % 14;
    int py = e >> 5, px = (e >> 1) & 15, cc = e & 1;
    size_t vidx = ((((size_t)(bb * F_ + fr) * 2 + cc) * 224 + (ph * 16 + py)) * 224 + (pw * 16 + px));
    float v = video[vidx];
    __nv_bfloat16 hi, lo;
    split2(v, hi, lo);
    g_pat_hi[idx] = hi; g_pat_lo[idx] = lo;
}

// ---------------- token assembly ----------------
__global__ void k_assemble(const float* __restrict__ joints_token) {
    size_t idx = (size_t)blockIdx.x * blockDim.x + threadIdx.x;
    if (idx >= (size_t)B_ * NTOK * DIMC) return;
    int col = (int)(idx & 511);
    size_t r = idx >> 9;
    int bb = (int)(r / NTOK); int i = (int)(r % NTOK);
    g_x[idx] = (i < NJx) ? joints_token[i * DIMC + col]
                         : g_tok[((size_t)bb * NSP + (i - NJx)) * DIMC + col];
}

// ---------------- LayerNorm (fused bf16 hi/lo split output) ----------------
__global__ __launch_bounds__(256) void k_ln(const float* __restrict__ in,
                                            const float* __restrict__ w,
                                            const float* __restrict__ b,
                                            __nv_bfloat16* __restrict__ ohi,
                                            __nv_bfloat16* __restrict__ olo) {
    __shared__ float red[32];
    int row = blockIdx.x;
    int t = threadIdx.x;
    const float* ri = in + (size_t)row * DIMC;
    float v0 = ri[t], v1 = ri[t + 256];
    float mean = block_sum(v0 + v1, red) * (1.f / 512.f);
    float d0 = v0 - mean, d1 = v1 - mean;
    float var = block_sum(d0 * d0 + d1 * d1, red) * (1.f / 512.f);
    float rs = rsqrtf(var + 1e-5f);
    float y0 = d0 * rs * w[t] + b[t];
    float y1 = d1 * rs * w[t + 256] + b[t + 256];
    size_t base = (size_t)row * DIMC;
    __nv_bfloat16 h, l;
    split2(y0, h, l); ohi[base + t] = h;       olo[base + t] = l;
    split2(y1, h, l); ohi[base + t + 256] = h; olo[base + t + 256] = l;
}

// final LN on joint tokens (fp32 out, tiny head)
__global__ __launch_bounds__(256) void k_ln_gather(const float* __restrict__ w,
                                                   const float* __restrict__ b) {
    __shared__ float red[32];
    int row = blockIdx.x;
    int bb = row / NJx, i = row % NJx;
    int t = threadIdx.x;
    const float* ri = g_x + ((size_t)bb * NTOK + i) * DIMC;
    float v0 = ri[t], v1 = ri[t + 256];
    float mean = block_sum(v0 + v1, red) * (1.f / 512.f);
    float d0 = v0 - mean, d1 = v1 - mean;
    float var = block_sum(d0 * d0 + d1 * d1, red) * (1.f / 512.f);
    float rs = rsqrtf(var + 1e-5f);
    float* ro = g_jt + (size_t)row * DIMC;
    ro[t]       = d0 * rs * w[t]       + b[t];
    ro[t + 256] = d1 * rs * w[t + 256] + b[t + 256];
}

// ---------------- joints attention v2: 4 queries per block ----------------
// grid (6, 16): x = query chunk (4 queries), y = (bb*8+h). Pre-rope K/V.
#define JA_FLOATS (256 + 4*NTOK + 32 + 1024)
#define JA_BYTES  (JA_FLOATS*4)
__global__ __launch_bounds__(256, 1) void k_joints_attn() {
    extern __shared__ float js[];
    float* sq   = js;                  // 4 x 64
    float* s    = js + 256;            // 4 x NTOK
    float* red  = js + 256 + 4*NTOK;   // 32
    float* sacc = red + 32;            // 4 x 4 x 64
    int qc = blockIdx.x;
    int g  = blockIdx.y; int h = g & 7, bb = g >> 3;
    int t = threadIdx.x;
    {
        int q = t >> 6, d = t & 63;
        int jq = qc * 4 + q;
        sq[t] = g_qkv[((size_t)(bb * NTOK + jq)) * 1536 + h * 64 + d] * 0.125f;
    }
    __syncthreads();
    for (int j = t; j < NTOK; j += 256) {
        const float* kp = g_qkv + ((size_t)(bb * NTOK + j)) * 1536 + 512 + h * 64;
        float a0 = 0.f, a1 = 0.f, a2 = 0.f, a3 = 0.f;
        #pragma unroll
        for (int d = 0; d < 64; d += 4) {
            float4 kv = *reinterpret_cast<const float4*>(kp + d);
            a0 += sq[d] * kv.x + sq[d+1] * kv.y + sq[d+2] * kv.z + sq[d+3] * kv.w;
            a1 += sq[64+d] * kv.x + sq[64+d+1] * kv.y + sq[64+d+2] * kv.z + sq[64+d+3] * kv.w;
            a2 += sq[128+d] * kv.x + sq[128+d+1] * kv.y + sq[128+d+2] * kv.z + sq[128+d+3] * kv.w;
            a3 += sq[192+d] * kv.x + sq[192+d+1] * kv.y + sq[192+d+2] * kv.z + sq[192+d+3] * kv.w;
        }
        s[0*NTOK + j] = a0; s[1*NTOK + j] = a1;
        s[2*NTOK + j] = a2; s[3*NTOK + j] = a3;
    }
    __syncthreads();
    float inv[4];
    #pragma unroll
    for (int q = 0; q < 4; q++) {
        float m = -INFINITY;
        for (int j = t; j < NTOK; j += 256) m = fmaxf(m, s[q*NTOK + j]);
        m = block_max(m, red);
        float ls = 0.f;
        for (int j = t; j < NTOK; j += 256) {
            float e = expf(s[q*NTOK + j] - m); s[q*NTOK + j] = e; ls += e;
        }
        inv[q] = 1.f / block_sum(ls, red);
    }
    int d = t & 63, cc = t >> 6;
    float acc0 = 0.f, acc1 = 0.f, acc2 = 0.f, acc3 = 0.f;
    for (int j = cc; j < NTOK; j += 4) {
        float v = g_qkv[((size_t)(bb * NTOK + j)) * 1536 + 1024 + h * 64 + d];
        acc0 += s[0*NTOK + j] * v; acc1 += s[1*NTOK + j] * v;
        acc2 += s[2*NTOK + j] * v; acc3 += s[3*NTOK + j] * v;
    }
    sacc[(0*4 + cc)*64 + d] = acc0; sacc[(1*4 + cc)*64 + d] = acc1;
    sacc[(2*4 + cc)*64 + d] = acc2; sacc[(3*4 + cc)*64 + d] = acc3;
    __syncthreads();
    if (t < 64) {
        #pragma unroll
        for (int q = 0; q < 4; q++) {
            float o = (sacc[(q*4+0)*64+t] + sacc[(q*4+1)*64+t] +
                       sacc[(q*4+2)*64+t] + sacc[(q*4+3)*64+t]) * inv[q];
            int jq = qc * 4 + q;
            size_t off = ((size_t)(bb * NTOK + jq)) * 512 + h * 64 + t;
            __nv_bfloat16 hi, lo;
            split2(o, hi, lo);
            g_attn_hi[off] = hi; g_attn_lo[off] = lo;
        }
    }
}

// ---------------- rope + q-scale ----------------
__global__ void k_rope() {
    int idx = blockIdx.x * blockDim.x + threadIdx.x;
    if (idx >= B_ * NTOK * 8 * 32) return;
    int s = idx & 31;
    int h = (idx >> 5) & 7;
    int rest = idx >> 8;
    int i = rest % NTOK;
    int bb = rest / NTOK;
    size_t base = ((size_t)(bb * NTOK + i)) * 1536 + h * 64 + 2 * s;
    float q0 = g_qkv[base] * 0.125f, q1 = g_qkv[base + 1] * 0.125f;
    if (i >= NJx) {
        int p = (i - NJx) % NPATCH;
        float c = g_cos[p * 32 + s], sn = g_sin[p * 32 + s];
        float nq0 = q0 * c - q1 * sn, nq1 = q1 * c + q0 * sn;
        q0 = nq0; q1 = nq1;
        float k0 = g_qkv[base + 512], k1 = g_qkv[base + 513];
        g_qkv[base + 512] = k0 * c - k1 * sn;
        g_qkv[base + 513] = k1 * c + k0 * sn;
    }
    g_qkv[base] = q0; g_qkv[base + 1] = q1;
}

// ---------------- frame attention v2: K/V cached in smem, 14 queries/block ----------------
// grid (14, 256): x = query chunk, y = group (bb,h,fr)
// smem floats: K[220*65]@0, V[220*65]@14300, q[14*64]@28600, s[224]@29496,
//              red[32]@29720, sacc[256]@29752  -> 30008 floats = 120032 B
#define FA_BYTES (30008*4)
__global__ __launch_bounds__(256, 1) void k_frame_attn() {
    extern __shared__ float fs[];
    float* Ks   = fs;
    float* Vs   = fs + 14300;
    float* qs   = fs + 28600;
    float* s    = fs + 29496;
    float* red  = fs + 29720;
    float* sacc = fs + 29752;
    int g = blockIdx.y;
    int fr = g & 15;
    int bh = g >> 4;
    int h = bh & 7, bb = bh >> 3;
    int qbase = blockIdx.x * 14;
    int t = threadIdx.x;

    for (int i = t; i < 220 * 64; i += 256) {
        int j = i >> 6, d = i & 63;
        int tj = (j < NJx) ? j : NJx + fr * NPATCH + (j - NJx);
        size_t base = ((size_t)(bb * NTOK + tj)) * 1536 + h * 64 + d;
        Ks[j * 65 + d] = g_qkv[base + 512];
        Vs[j * 65 + d] = g_qkv[base + 1024];
    }
    for (int i = t; i < 14 * 64; i += 256) {
        int q = i >> 6, d = i & 63;
        int ti = NJx + fr * NPATCH + qbase + q;
        qs[i] = g_qkv[((size_t)(bb * NTOK + ti)) * 1536 + h * 64 + d];
    }
    __syncthreads();

    for (int ql = 0; ql < 14; ql++) {
        if (t < 220) {
            const float* kr = Ks + t * 65;
            const float* qq = qs + ql * 64;
            float acc = 0.f;
            #pragma unroll
            for (int d = 0; d < 64; d++) acc += qq[d] * kr[d];
            s[t] = acc;
        }
        __syncthreads();
        float m = (t < 220) ? s[t] : -INFINITY;
        m = block_max(m, red);
        float e = 0.f;
        if (t < 220) { e = expf(s[t] - m); s[t] = e; }
        float denom = block_sum(e, red);
        float inv = 1.f / denom;
        int d = t & 63, cc = t >> 6;
        float acc = 0.f;
        for (int j = cc; j < 220; j += 4) acc += s[j] * Vs[j * 65 + d];
        sacc[cc * 64 + d] = acc;
        __syncthreads();
        if (t < 64) {
            float o = (sacc[t] + sacc[64 + t] + sacc[128 + t] + sacc[192 + t]) * inv;
            int ti = NJx + fr * NPATCH + qbase + ql;
            size_t off = ((size_t)(bb * NTOK + ti)) * 512 + h * 64 + t;
            __nv_bfloat16 hi, lo;
            split2(o, hi, lo);
            g_attn_hi[off] = hi; g_attn_lo[off] = lo;
        }
        __syncthreads();
    }
}

// ---------------- GEGLU (fused bf16 hi/lo split output) ----------------
__global__ void k_geglu() {
    size_t idx = (size_t)blockIdx.x * blockDim.x + threadIdx.x;
    if (idx >= (size_t)ROWS * 2048) return;
    size_t r = idx >> 11;
    int j = (int)(idx & 2047);
    float a = g_h1[r * 4096 + j];
    float g = g_h1[r * 4096 + 2048 + j];
    float ge = 0.5f * g * (1.f + erff(g * 0.7071067811865476f));
    float v = a * ge;
    __nv_bfloat16 hi, lo;
    split2(v, hi, lo);
    g_hg_hi[idx] = hi; g_hg_lo[idx] = lo;
}

// ---------------- host helpers ----------------
static void launch_mma(const __nv_bfloat16* Ah, const __nv_bfloat16* Al,
                       const __nv_bfloat16* Bh, const __nv_bfloat16* Bl,
                       const float* bias, const float* res, float* C,
                       int M, int N, int K, int BIAS, int RES) {
    dim3 grid(N / 256, (M + 127) / 128);
    k_mma_gemm<<<grid, 256, GSMEM>>>(Ah, Al, Bh, Bl, bias, res, C, M, N, K, BIAS, RES);
}

extern "C" void kernel_launch(void* const* d_in, const int* in_sizes, int n_in,
                              void* d_out, int out_size) {
    const float* video        = (const float*)d_in[0];
    const float* patch_w      = (const float*)d_in[1];
    const float* patch_b      = (const float*)d_in[2];
    const float* joints_token = (const float*)d_in[3];
    const float* ln_attn_w    = (const float*)d_in[4];
    const float* ln_attn_b    = (const float*)d_in[5];
    const float* qkv_w        = (const float*)d_in[6];
    const float* attn_out_w   = (const float*)d_in[7];
    const float* attn_out_b   = (const float*)d_in[8];
    const float* ln_ff_w      = (const float*)d_in[9];
    const float* ln_ff_b      = (const float*)d_in[10];
    const float* ff1_w        = (const float*)d_in[11];
    const float* ff1_b        = (const float*)d_in[12];
    const float* ff2_w        = (const float*)d_in[13];
    const float* ff2_b        = (const float*)d_in[14];
    const float* ln_out_w     = (const float*)d_in[15];
    const float* ln_out_b     = (const float*)d_in[16];
    const float* out_w        = (const float*)d_in[17];
    const float* out_b        = (const float*)d_in[18];

    static bool attr_set = false;
    if (!attr_set) {
        cudaFuncSetAttribute(k_mma_gemm, cudaFuncAttributeMaxDynamicSharedMemorySize, GSMEM);
        cudaFuncSetAttribute(k_frame_attn, cudaFuncAttributeMaxDynamicSharedMemorySize, FA_BYTES);
        cudaFuncSetAttribute(k_joints_attn, cudaFuncAttributeMaxDynamicSharedMemorySize, JA_BYTES);
        attr_set = true;
    }

    float *px, *pqkv, *ph1, *ptok, *pjt;
    cudaGetSymbolAddress((void**)&px,    g_x);
    cudaGetSymbolAddress((void**)&pqkv,  g_qkv);
    cudaGetSymbolAddress((void**)&ph1,   g_h1);
    cudaGetSymbolAddress((void**)&ptok,  g_tok);
    cudaGetSymbolAddress((void**)&pjt,   g_jt);

    __nv_bfloat16 *xnh, *xnl, *ath, *atl, *hgh, *hgl, *pth, *ptl;
    cudaGetSymbolAddress((void**)&xnh, g_xn_hi);
    cudaGetSymbolAddress((void**)&xnl, g_xn_lo);
    cudaGetSymbolAddress((void**)&ath, g_attn_hi);
    cudaGetSymbolAddress((void**)&atl, g_attn_lo);
    cudaGetSymbolAddress((void**)&hgh, g_hg_hi);
    cudaGetSymbolAddress((void**)&hgl, g_hg_lo);
    cudaGetSymbolAddress((void**)&pth, g_pat_hi);
    cudaGetSymbolAddress((void**)&ptl, g_pat_lo);

    __nv_bfloat16 *patchThi, *patchTlo, *qkvThi, *qkvTlo, *outThi, *outTlo,
                  *ff1Thi, *ff1Tlo, *ff2Thi, *ff2Tlo;
    cudaGetSymbolAddress((void**)&patchThi, g_patchT_hi);
    cudaGetSymbolAddress((void**)&patchTlo, g_patchT_lo);
    cudaGetSymbolAddress((void**)&qkvThi,   g_qkvT_hi);
    cudaGetSymbolAddress((void**)&qkvTlo,   g_qkvT_lo);
    cudaGetSymbolAddress((void**)&outThi,   g_outT_hi);
    cudaGetSymbolAddress((void**)&outTlo,   g_outT_lo);
    cudaGetSymbolAddress((void**)&ff1Thi,   g_ff1T_hi);
    cudaGetSymbolAddress((void**)&ff1Tlo,   g_ff1T_lo);
    cudaGetSymbolAddress((void**)&ff2Thi,   g_ff2T_hi);
    cudaGetSymbolAddress((void**)&ff2Tlo,   g_ff2T_lo);

    // ---- weight prep (transpose + bf16 hi/lo split) ----
    k_wprep<<<dim3(512 / 32, 512 / 32), 256>>>(patch_w, patchThi, patchTlo, 512, 512);
    for (int l = 0; l < 12; l++) {
        k_wprep<<<dim3(1536 / 32, 512 / 32), 256>>>(qkv_w + (size_t)l * 512 * 1536,
            qkvThi + (size_t)l * 1536 * 512, qkvTlo + (size_t)l * 1536 * 512, 512, 1536);
        k_wprep<<<dim3(512 / 32, 512 / 32), 256>>>(attn_out_w + (size_t)l * 512 * 512,
            outThi + (size_t)l * 512 * 512, outTlo + (size_t)l * 512 * 512, 512, 512);
        k_wprep<<<dim3(4096 / 32, 512 / 32), 256>>>(ff1_w + (size_t)l * 512 * 4096,
            ff1Thi + (size_t)l * 4096 * 512, ff1Tlo + (size_t)l * 4096 * 512, 512, 4096);
        k_wprep<<<dim3(512 / 32, 2048 / 32), 256>>>(ff2_w + (size_t)l * 2048 * 512,
            ff2Thi + (size_t)l * 512 * 2048, ff2Tlo + (size_t)l * 512 * 2048, 2048, 512);
    }

    // ---- setup ----
    k_sincos<<<(NPATCH * 32 + 255) / 256, 256>>>();
    k_im2col<<<(int)(((size_t)B_ * NSP * DIMC + 255) / 256), 256>>>(video);
    launch_mma(pth, ptl, patchThi, patchTlo, patch_b, nullptr, ptok,
               B_ * NSP, DIMC, DIMC, 1, 0);
    k_assemble<<<(int)(((size_t)B_ * NTOK * DIMC + 255) / 256), 256>>>(joints_token);

    for (int l = 0; l < 12; l++) {
        k_ln<<<ROWS, 256>>>(px, ln_attn_w + l * 512, ln_attn_b + l * 512, xnh, xnl);
        launch_mma(xnh, xnl, qkvThi + (size_t)l * 1536 * 512, qkvTlo + (size_t)l * 1536 * 512,
                   nullptr, nullptr, pqkv, ROWS, 1536, 512, 0, 0);
        k_joints_attn<<<dim3(6, 16), 256, JA_BYTES>>>();
        k_rope<<<(B_ * NTOK * 8 * 32 + 255) / 256, 256>>>();
        k_frame_attn<<<dim3(14, 256), 256, FA_BYTES>>>();
        launch_mma(ath, atl, outThi + (size_t)l * 512 * 512, outTlo + (size_t)l * 512 * 512,
                   attn_out_b + l * 512, px, px, ROWS, 512, 512, 1, 1);
        k_ln<<<ROWS, 256>>>(px, ln_ff_w + l * 512, ln_ff_b + l * 512, xnh, xnl);
        launch_mma(xnh, xnl, ff1Thi + (size_t)l * 4096 * 512, ff1Tlo + (size_t)l * 4096 * 512,
                   ff1_b + (size_t)l * 4096, nullptr, ph1, ROWS, 4096, 512, 1, 0);
        k_geglu<<<(int)(((size_t)ROWS * 2048 + 255) / 256), 256>>>();
        launch_mma(hgh, hgl, ff2Thi + (size_t)l * 512 * 2048, ff2Tlo + (size_t)l * 512 * 2048,
                   ff2_b + l * 512, px, px, ROWS, 512, 2048, 1, 1);
    }

    // ---- head (tiny, fp32 path) ----
    k_ln_gather<<<48, 256>>>(ln_out_w, ln_out_b);
    {
        dim3 grid(384 / 128, 1);
        k_sgemm<1, 0><<<grid, 256>>>(pjt, out_w, out_b, nullptr, (float*)d_out, 48, 384, 512);
    }
}

// round 16
// speedup vs baseline: 2.6706x; 1.0213x over previous
#include <cuda_runtime.h>
#include <cuda_bf16.h>
#include <math.h>
#include <stdint.h>

// ---------------- problem constants ----------------
#define B_      2
#define F_      16
#define NJx     24
#define NPATCH  196          // 14*14
#define NSP     3136         // F_*NPATCH
#define NTOK    3160         // NJx + NSP
#define DIMC    512
#define ROWS    (B_*NTOK)    // 6320

// ---------------- scratch (device globals; no runtime alloc) ----------------
__device__ float g_x   [B_*NTOK*DIMC];
__device__ float g_qkv [B_*NTOK*1536];
__device__ float g_tok [B_*NSP*DIMC];
__device__ float g_sin [NPATCH*32];
__device__ float g_cos [NPATCH*32];
__device__ float g_jt  [48*DIMC];

// bf16 hi/lo activation operands (written fused by producers)
__device__ __nv_bfloat16 g_xn_hi  [ROWS*DIMC];
__device__ __nv_bfloat16 g_xn_lo  [ROWS*DIMC];
__device__ __nv_bfloat16 g_attn_hi[ROWS*DIMC];
__device__ __nv_bfloat16 g_attn_lo[ROWS*DIMC];
__device__ __nv_bfloat16 g_hg_hi  [(size_t)ROWS*2048];
__device__ __nv_bfloat16 g_hg_lo  [(size_t)ROWS*2048];
__device__ __nv_bfloat16 g_pat_hi [B_*NSP*DIMC];
__device__ __nv_bfloat16 g_pat_lo [B_*NSP*DIMC];

// transposed bf16 hi/lo weights ([N,K] layout; ff1 column-pair-permuted)
__device__ __nv_bfloat16 g_patchT_hi[512*512];
__device__ __nv_bfloat16 g_patchT_lo[512*512];
__device__ __nv_bfloat16 g_qkvT_hi [12*1536*512];
__device__ __nv_bfloat16 g_qkvT_lo [12*1536*512];
__device__ __nv_bfloat16 g_outT_hi [12*512*512];
__device__ __nv_bfloat16 g_outT_lo [12*512*512];
__device__ __nv_bfloat16 g_ff1T_hi [(size_t)12*4096*512];
__device__ __nv_bfloat16 g_ff1T_lo [(size_t)12*4096*512];
__device__ __nv_bfloat16 g_ff2T_hi [(size_t)12*512*2048];
__device__ __nv_bfloat16 g_ff2T_lo [(size_t)12*512*2048];

// ---------------- helpers ----------------
__device__ __forceinline__ uint32_t smem_u32(const void* p) {
    uint32_t a;
    asm("{ .reg .u64 t; cvta.to.shared.u64 t, %1; cvt.u32.u64 %0, t; }" : "=r"(a) : "l"(p));
    return a;
}
__device__ __forceinline__ void cp_async16(uint32_t dst, const void* src, bool pred) {
    int sz = pred ? 16 : 0;
    asm volatile("cp.async.ca.shared.global [%0], [%1], 16, %2;"
                 :: "r"(dst), "l"(src), "r"(sz) : "memory");
}
__device__ __forceinline__ void cp_commit() {
    asm volatile("cp.async.commit_group;" ::: "memory");
}
template<int NW> __device__ __forceinline__ void cp_wait() {
    asm volatile("cp.async.wait_group %0;" :: "n"(NW) : "memory");
}
__device__ __forceinline__ void ldmx4(uint32_t* r, uint32_t addr) {
    asm volatile("ldmatrix.sync.aligned.m8n8.x4.shared.b16 {%0,%1,%2,%3}, [%4];"
                 : "=r"(r[0]), "=r"(r[1]), "=r"(r[2]), "=r"(r[3]) : "r"(addr));
}
__device__ __forceinline__ void mma16816(float* c, const uint32_t* a, const uint32_t* b) {
    asm volatile("mma.sync.aligned.m16n8k16.row.col.f32.bf16.bf16.f32 "
                 "{%0,%1,%2,%3}, {%4,%5,%6,%7}, {%8,%9}, {%0,%1,%2,%3};"
                 : "+f"(c[0]), "+f"(c[1]), "+f"(c[2]), "+f"(c[3])
                 : "r"(a[0]), "r"(a[1]), "r"(a[2]), "r"(a[3]), "r"(b[0]), "r"(b[1]));
}
__device__ __forceinline__ void split2(float v, __nv_bfloat16& h, __nv_bfloat16& l) {
    h = __float2bfloat16(v);
    l = __float2bfloat16(v - __bfloat162float(h));
}

// ---------------- block reductions (blockDim.x == 256) ----------------
__device__ __forceinline__ float warp_sum(float v) {
    #pragma unroll
    for (int o = 16; o > 0; o >>= 1) v += __shfl_xor_sync(0xffffffffu, v, o);
    return v;
}
__device__ __forceinline__ float warp_max(float v) {
    #pragma unroll
    for (int o = 16; o > 0; o >>= 1) v = fmaxf(v, __shfl_xor_sync(0xffffffffu, v, o));
    return v;
}
__device__ __forceinline__ float block_sum(float v, float* red) {
    v = warp_sum(v);
    int lane = threadIdx.x & 31, w = threadIdx.x >> 5;
    if (lane == 0) red[w] = v;
    __syncthreads();
    if (threadIdx.x < 32) {
        float r = (threadIdx.x < 8) ? red[threadIdx.x] : 0.f;
        r = warp_sum(r);
        if (threadIdx.x == 0) red[0] = r;
    }
    __syncthreads();
    float out = red[0];
    __syncthreads();
    return out;
}
__device__ __forceinline__ float block_max(float v, float* red) {
    v = warp_max(v);
    int lane = threadIdx.x & 31, w = threadIdx.x >> 5;
    if (lane == 0) red[w] = v;
    __syncthreads();
    if (threadIdx.x < 32) {
        float r = (threadIdx.x < 8) ? red[threadIdx.x] : -INFINITY;
        r = warp_max(r);
        if (threadIdx.x == 0) red[0] = r;
    }
    __syncthreads();
    float out = red[0];
    __syncthreads();
    return out;
}

// ---------------- weight prep: W[K,N] fp32 -> T_hi/T_lo [N,K] bf16 ----------------
__global__ __launch_bounds__(256) void k_wprep(const float* __restrict__ W,
                                               __nv_bfloat16* __restrict__ Thi,
                                               __nv_bfloat16* __restrict__ Tlo,
                                               int K, int N) {
    __shared__ float tile[32][33];
    int k0 = blockIdx.y * 32, n0 = blockIdx.x * 32;
    int tx = threadIdx.x & 31, ty = threadIdx.x >> 5;
    #pragma unroll
    for (int r = ty; r < 32; r += 8)
        tile[r][tx] = W[(size_t)(k0 + r) * N + n0 + tx];
    __syncthreads();
    #pragma unroll
    for (int r = ty; r < 32; r += 8) {
        float v = tile[tx][r];
        __nv_bfloat16 hi, lo;
        split2(v, hi, lo);
        size_t o = (size_t)(n0 + r) * K + k0 + tx;
        Thi[o] = hi; Tlo[o] = lo;
    }
}

// ff1 prep: W[512,4096] -> permuted T[4096,512]; out row 2j <- col j, 2j+1 <- col j+2048
__global__ __launch_bounds__(256) void k_wprep_ff1(const float* __restrict__ W,
                                                   __nv_bfloat16* __restrict__ Thi,
                                                   __nv_bfloat16* __restrict__ Tlo) {
    __shared__ float tile[32][33];
    int k0 = blockIdx.y * 32, n0 = blockIdx.x * 32;
    int tx = threadIdx.x & 31, ty = threadIdx.x >> 5;
    int n0h = n0 >> 1;
    int scol = (tx < 16) ? (n0h + tx) : (n0h + 2048 + tx - 16);
    #pragma unroll
    for (int r = ty; r < 32; r += 8)
        tile[r][tx] = W[(size_t)(k0 + r) * 4096 + scol];
    __syncthreads();
    #pragma unroll
    for (int r = ty; r < 32; r += 8) {
        int cc = (r >> 1) + ((r & 1) << 4);
        float v = tile[tx][cc];
        __nv_bfloat16 hi, lo;
        split2(v, hi, lo);
        size_t o = (size_t)(n0 + r) * 512 + k0 + tx;
        Thi[o] = hi; Tlo[o] = lo;
    }
}

// ---------------- bf16x3 HMMA GEMM (templated) ----------------
// MT: 16-row m-frags per warp (4 -> CTA 128xN, 2 -> CTA 64xN). CTA N = 256.
// MODE 0: C = gemm (+bias)(+res) fp32.  MODE 1: fused GEGLU epilogue
// (permuted ff1 weights): hg = (a+ba)*gelu(g+bg) -> bf16 hi/lo to g_hg.
template<int MT>
__device__ __forceinline__ void g2_issue(
    uint32_t sb, int stage, int kc, int t, int bm, int bn,
    const __nv_bfloat16* __restrict__ Ah, const __nv_bfloat16* __restrict__ Al,
    const __nv_bfloat16* __restrict__ Bh, const __nv_bfloat16* __restrict__ Bl,
    int M, int K)
{
    constexpr uint32_t OAL = MT * 2560u;
    constexpr uint32_t OBH = MT * 5120u;
    constexpr uint32_t OBL = MT * 5120u + 20480u;
    constexpr uint32_t STG = MT * 5120u + 40960u;
    uint32_t s0 = sb + (uint32_t)stage * STG;
    int k0 = kc << 5;
    #pragma unroll
    for (int j = 0; j < MT + 8; j++) {
        int i = t + j * 256;
        int r = i >> 2, c = i & 3;
        if (r < MT * 32) {
            int gr = bm + r; bool p = gr < M;
            cp_async16(s0 + (uint32_t)(r * 80 + c * 16),
                       Ah + (size_t)(p ? gr : 0) * K + k0 + c * 8, p);
        } else if (r < MT * 64) {
            int rr = r - MT * 32; int gr = bm + rr; bool p = gr < M;
            cp_async16(s0 + OAL + (uint32_t)(rr * 80 + c * 16),
                       Al + (size_t)(p ? gr : 0) * K + k0 + c * 8, p);
        } else if (r < MT * 64 + 256) {
            int rr = r - MT * 64;
            cp_async16(s0 + OBH + (uint32_t)(rr * 80 + c * 16),
                       Bh + (size_t)(bn + rr) * K + k0 + c * 8, true);
        } else {
            int rr = r - MT * 64 - 256;
            cp_async16(s0 + OBL + (uint32_t)(rr * 80 + c * 16),
                       Bl + (size_t)(bn + rr) * K + k0 + c * 8, true);
        }
    }
    cp_commit();
}

template<int MT, int MODE>
__global__ __launch_bounds__(256, 1) void k_mma_gemm(
    const __nv_bfloat16* __restrict__ Ah, const __nv_bfloat16* __restrict__ Al,
    const __nv_bfloat16* __restrict__ Bh, const __nv_bfloat16* __restrict__ Bl,
    const float* __restrict__ bias, const float* __restrict__ res,
    float* __restrict__ C, int M, int N, int K, int BIAS, int RES)
{
    constexpr uint32_t OAL = MT * 2560u;
    constexpr uint32_t OBH = MT * 5120u;
    constexpr uint32_t OBL = MT * 5120u + 20480u;
    constexpr uint32_t STG = MT * 5120u + 40960u;
    extern __shared__ char smem[];
    uint32_t sb = smem_u32(smem);
    int t = threadIdx.x, lane = t & 31, wid = t >> 5;
    int bm = blockIdx.y * (MT * 32), bn = blockIdx.x * 256;
    int wm = (wid >> 2) * (MT * 16), wn = (wid & 3) * 64;

    float c[MT][8][4];
    #pragma unroll
    for (int mi = 0; mi < MT; mi++)
        #pragma unroll
        for (int ni = 0; ni < 8; ni++)
            #pragma unroll
            for (int f = 0; f < 4; f++) c[mi][ni][f] = 0.f;

    int nk = K >> 5;
    g2_issue<MT>(sb, 0, 0, t, bm, bn, Ah, Al, Bh, Bl, M, K);
    g2_issue<MT>(sb, 1, 1, t, bm, bn, Ah, Al, Bh, Bl, M, K);

    int lr = lane & 15;
    int lc = ((lane >> 4) & 1) << 3;

    for (int kc = 0; kc < nk; kc++) {
        if (kc + 1 < nk) cp_wait<1>(); else cp_wait<0>();
        __syncthreads();
        if (kc + 2 < nk)
            g2_issue<MT>(sb, (kc + 2) % 3, kc + 2, t, bm, bn, Ah, Al, Bh, Bl, M, K);

        uint32_t st  = sb + (uint32_t)(kc % 3) * STG;
        uint32_t sAh = st, sAl = st + OAL, sBh = st + OBH, sBl = st + OBL;

        #pragma unroll
        for (int ks = 0; ks < 2; ks++) {
            int kcol = ks * 16 + lc;
            uint32_t a[MT][4], bh[8][2], bl[8][2];
            #pragma unroll
            for (int mi = 0; mi < MT; mi++)
                ldmx4(a[mi], sAh + (uint32_t)((wm + mi * 16 + lr) * 40 + kcol) * 2);
            #pragma unroll
            for (int nh = 0; nh < 4; nh++) {
                uint32_t r[4];
                ldmx4(r, sBh + (uint32_t)((wn + nh * 16 + lr) * 40 + kcol) * 2);
                bh[nh * 2][0] = r[0]; bh[nh * 2][1] = r[2];
                bh[nh * 2 + 1][0] = r[1]; bh[nh * 2 + 1][1] = r[3];
                ldmx4(r, sBl + (uint32_t)((wn + nh * 16 + lr) * 40 + kcol) * 2);
                bl[nh * 2][0] = r[0]; bl[nh * 2][1] = r[2];
                bl[nh * 2 + 1][0] = r[1]; bl[nh * 2 + 1][1] = r[3];
            }
            #pragma unroll
            for (int mi = 0; mi < MT; mi++)
                #pragma unroll
                for (int ni = 0; ni < 8; ni++) {
                    mma16816(c[mi][ni], a[mi], bh[ni]);
                    mma16816(c[mi][ni], a[mi], bl[ni]);
                }
            #pragma unroll
            for (int mi = 0; mi < MT; mi++)
                ldmx4(a[mi], sAl + (uint32_t)((wm + mi * 16 + lr) * 40 + kcol) * 2);
            #pragma unroll
            for (int mi = 0; mi < MT; mi++)
                #pragma unroll
                for (int ni = 0; ni < 8; ni++)
                    mma16816(c[mi][ni], a[mi], bh[ni]);
        }
    }

    int row0 = bm + wm + (lane >> 2);
    int col0 = bn + wn + (lane & 3) * 2;
    #pragma unroll
    for (int mi = 0; mi < MT; mi++) {
        #pragma unroll
        for (int hh = 0; hh < 2; hh++) {
            int r = row0 + mi * 16 + hh * 8;
            if (r >= M) continue;
            #pragma unroll
            for (int ni = 0; ni < 8; ni++) {
                int col = col0 + ni * 8;
                if (MODE == 0) {
                    float2 v = make_float2(c[mi][ni][hh * 2], c[mi][ni][hh * 2 + 1]);
                    if (BIAS) { v.x += bias[col]; v.y += bias[col + 1]; }
                    if (RES) {
                        float2 rr = *reinterpret_cast<const float2*>(res + (size_t)r * N + col);
                        v.x += rr.x; v.y += rr.y;
                    }
                    *reinterpret_cast<float2*>(C + (size_t)r * N + col) = v;
                } else {
                    int j = col >> 1;
                    float a = c[mi][ni][hh * 2]     + bias[j];
                    float g = c[mi][ni][hh * 2 + 1] + bias[j + 2048];
                    float ge = 0.5f * g * (1.f + erff(g * 0.7071067811865476f));
                    float v = a * ge;
                    __nv_bfloat16 hi, lo;
                    split2(v, hi, lo);
                    g_hg_hi[(size_t)r * 2048 + j] = hi;
                    g_hg_lo[(size_t)r * 2048 + j] = lo;
                }
            }
        }
    }
}

// ---------------- fp32 SGEMM (tiny head GEMM only) ----------------
template<int BIAS, int RES>
__global__ __launch_bounds__(256) void k_sgemm(
    const float* __restrict__ A, const float* __restrict__ B,
    const float* __restrict__ bias, const float* __restrict__ res,
    float* __restrict__ C, int M, int N, int K)
{
    __shared__ float As[8][128];
    __shared__ float Bs[8][128];
    int tid = threadIdx.x;
    int bm = blockIdx.y * 128;
    int bn = blockIdx.x * 128;
    int tx = tid & 15, ty = tid >> 4;
    int ar = tid >> 1, ac = (tid & 1) * 4;
    int br = tid >> 5, bc = (tid & 31) * 4;

    float acc[8][8];
    #pragma unroll
    for (int i = 0; i < 8; i++)
        #pragma unroll
        for (int j = 0; j < 8; j++) acc[i][j] = 0.f;

    bool aval = (bm + ar) < M;
    const float* Aptr = A + (size_t)(bm + ar) * K + ac;
    const float* Bptr = B + (size_t)br * N + bn + bc;

    for (int k0 = 0; k0 < K; k0 += 8) {
        float4 av = make_float4(0.f, 0.f, 0.f, 0.f);
        if (aval) av = *reinterpret_cast<const float4*>(Aptr + k0);
        As[ac + 0][ar] = av.x; As[ac + 1][ar] = av.y;
        As[ac + 2][ar] = av.z; As[ac + 3][ar] = av.w;
        float4 bv = *reinterpret_cast<const float4*>(Bptr + (size_t)k0 * N);
        *reinterpret_cast<float4*>(&Bs[br][bc]) = bv;
        __syncthreads();
        #pragma unroll
        for (int kk = 0; kk < 8; kk++) {
            float af[8], bf[8];
            *reinterpret_cast<float4*>(&af[0]) = *reinterpret_cast<const float4*>(&As[kk][ty * 4]);
            *reinterpret_cast<float4*>(&af[4]) = *reinterpret_cast<const float4*>(&As[kk][64 + ty * 4]);
            *reinterpret_cast<float4*>(&bf[0]) = *reinterpret_cast<const float4*>(&Bs[kk][tx * 4]);
            *reinterpret_cast<float4*>(&bf[4]) = *reinterpret_cast<const float4*>(&Bs[kk][64 + tx * 4]);
            #pragma unroll
            for (int i = 0; i < 8; i++)
                #pragma unroll
                for (int j = 0; j < 8; j++)
                    acc[i][j] = fmaf(af[i], bf[j], acc[i][j]);
        }
        __syncthreads();
    }

    #pragma unroll
    for (int i = 0; i < 8; i++) {
        int row = bm + ((i < 4) ? (ty * 4 + i) : (64 + ty * 4 + i - 4));
        if (row >= M) continue;
        #pragma unroll
        for (int jh = 0; jh < 2; jh++) {
            int col = bn + ((jh == 0) ? (tx * 4) : (64 + tx * 4));
            float4 v;
            v.x = acc[i][jh * 4 + 0]; v.y = acc[i][jh * 4 + 1];
            v.z = acc[i][jh * 4 + 2]; v.w = acc[i][jh * 4 + 3];
            if (BIAS) {
                float4 b4 = *reinterpret_cast<const float4*>(bias + col);
                v.x += b4.x; v.y += b4.y; v.z += b4.z; v.w += b4.w;
            }
            if (RES) {
                float4 r4 = *reinterpret_cast<const float4*>(res + (size_t)row * N + col);
                v.x += r4.x; v.y += r4.y; v.z += r4.z; v.w += r4.w;
            }
            *reinterpret_cast<float4*>(C + (size_t)row * N + col) = v;
        }
    }
}

// ---------------- rotary tables ----------------
__global__ void k_sincos() {
    int idx = blockIdx.x * blockDim.x + threadIdx.x;
    if (idx >= NPATCH * 32) return;
    int p = idx >> 5, s = idx & 31;
    int ph = p / 14, pw = p % 14;
    int ss = (s < 16) ? s : (s - 16);
    float scale = exp2f((float)ss * (2.321928094887362f / 15.f));
    int pos_i = (s < 16) ? ph : pw;
    float pos = -1.f + 2.f * (float)pos_i / 13.f;
    float ang = pos * scale * 3.14159265358979323846f;
    g_sin[idx] = sinf(ang);
    g_cos[idx] = cosf(ang);
}

// ---------------- patch extraction (im2col, writes bf16 hi/lo) ----------------
__global__ void k_im2col(const float* __restrict__ video) {
    size_t idx = (size_t)blockIdx.x * blockDim.x + threadIdx.x;
    if (idx >= (size_t)B_ * NSP * DIMC) return;
    int e = (int)(idx & 511);
    size_t r = idx >> 9;
    int bb = (int)(r / NSP); int t = (int)(r % NSP);
    int fr = t / NPATCH; int pp = t % NPATCH;
    int ph = pp / 14, pw = pp % 14;
    int py = e >> 5, px = (e >> 1) & 15, cc = e & 1;
    size_t vidx = ((((size_t)(bb * F_ + fr) * 2 + cc) * 224 + (ph * 16 + py)) * 224 + (pw * 16 + px));
    float v = video[vidx];
    __nv_bfloat16 hi, lo;
    split2(v, hi, lo);
    g_pat_hi[idx] = hi; g_pat_lo[idx] = lo;
}

// ---------------- token assembly ----------------
__global__ void k_assemble(const float* __restrict__ joints_token) {
    size_t idx = (size_t)blockIdx.x * blockDim.x + threadIdx.x;
    if (idx >= (size_t)B_ * NTOK * DIMC) return;
    int col = (int)(idx & 511);
    size_t r = idx >> 9;
    int bb = (int)(r / NTOK); int i = (int)(r % NTOK);
    g_x[idx] = (i < NJx) ? joints_token[i * DIMC + col]
                         : g_tok[((size_t)bb * NSP + (i - NJx)) * DIMC + col];
}

// ---------------- LayerNorm (fused bf16 hi/lo split output) ----------------
__global__ __launch_bounds__(256) void k_ln(const float* __restrict__ in,
                                            const float* __restrict__ w,
                                            const float* __restrict__ b,
                                            __nv_bfloat16* __restrict__ ohi,
                                            __nv_bfloat16* __restrict__ olo) {
    __shared__ float red[32];
    int row = blockIdx.x;
    int t = threadIdx.x;
    const float* ri = in + (size_t)row * DIMC;
    float v0 = ri[t], v1 = ri[t + 256];
    float mean = block_sum(v0 + v1, red) * (1.f / 512.f);
    float d0 = v0 - mean, d1 = v1 - mean;
    float var = block_sum(d0 * d0 + d1 * d1, red) * (1.f / 512.f);
    float rs = rsqrtf(var + 1e-5f);
    float y0 = d0 * rs * w[t] + b[t];
    float y1 = d1 * rs * w[t + 256] + b[t + 256];
    size_t base = (size_t)row * DIMC;
    __nv_bfloat16 h, l;
    split2(y0, h, l); ohi[base + t] = h;       olo[base + t] = l;
    split2(y1, h, l); ohi[base + t + 256] = h; olo[base + t + 256] = l;
}

// final LN on joint tokens (fp32 out, tiny head)
__global__ __launch_bounds__(256) void k_ln_gather(const float* __restrict__ w,
                                                   const float* __restrict__ b) {
    __shared__ float red[32];
    int row = blockIdx.x;
    int bb = row / NJx, i = row % NJx;
    int t = threadIdx.x;
    const float* ri = g_x + ((size_t)bb * NTOK + i) * DIMC;
    float v0 = ri[t], v1 = ri[t + 256];
    float mean = block_sum(v0 + v1, red) * (1.f / 512.f);
    float d0 = v0 - mean, d1 = v1 - mean;
    float var = block_sum(d0 * d0 + d1 * d1, red) * (1.f / 512.f);
    float rs = rsqrtf(var + 1e-5f);
    float* ro = g_jt + (size_t)row * DIMC;
    ro[t]       = d0 * rs * w[t]       + b[t];
    ro[t + 256] = d1 * rs * w[t + 256] + b[t + 256];
}

// ---------------- joints attention: 4 queries/block, raw (pre-rope) qkv ----------------
#define JA_FLOATS (256 + 4*NTOK + 32 + 1024)
#define JA_BYTES  (JA_FLOATS*4)
__global__ __launch_bounds__(256, 1) void k_joints_attn() {
    extern __shared__ float js[];
    float* sq   = js;                  // 4 x 64
    float* s    = js + 256;            // 4 x NTOK
    float* red  = js + 256 + 4*NTOK;   // 32
    float* sacc = red + 32;            // 4 x 4 x 64
    int qc = blockIdx.x;
    int g  = blockIdx.y; int h = g & 7, bb = g >> 3;
    int t = threadIdx.x;
    {
        int q = t >> 6, d = t & 63;
        int jq = qc * 4 + q;
        sq[t] = g_qkv[((size_t)(bb * NTOK + jq)) * 1536 + h * 64 + d] * 0.125f;
    }
    __syncthreads();
    for (int j = t; j < NTOK; j += 256) {
        const float* kp = g_qkv + ((size_t)(bb * NTOK + j)) * 1536 + 512 + h * 64;
        float a0 = 0.f, a1 = 0.f, a2 = 0.f, a3 = 0.f;
        #pragma unroll
        for (int d = 0; d < 64; d += 4) {
            float4 kv = *reinterpret_cast<const float4*>(kp + d);
            a0 += sq[d] * kv.x + sq[d+1] * kv.y + sq[d+2] * kv.z + sq[d+3] * kv.w;
            a1 += sq[64+d] * kv.x + sq[64+d+1] * kv.y + sq[64+d+2] * kv.z + sq[64+d+3] * kv.w;
            a2 += sq[128+d] * kv.x + sq[128+d+1] * kv.y + sq[128+d+2] * kv.z + sq[128+d+3] * kv.w;
            a3 += sq[192+d] * kv.x + sq[192+d+1] * kv.y + sq[192+d+2] * kv.z + sq[192+d+3] * kv.w;
        }
        s[0*NTOK + j] = a0; s[1*NTOK + j] = a1;
        s[2*NTOK + j] = a2; s[3*NTOK + j] = a3;
    }
    __syncthreads();
    float inv[4];
    #pragma unroll
    for (int q = 0; q < 4; q++) {
        float m = -INFINITY;
        for (int j = t; j < NTOK; j += 256) m = fmaxf(m, s[q*NTOK + j]);
        m = block_max(m, red);
        float ls = 0.f;
        for (int j = t; j < NTOK; j += 256) {
            float e = expf(s[q*NTOK + j] - m); s[q*NTOK + j] = e; ls += e;
        }
        inv[q] = 1.f / block_sum(ls, red);
    }
    int d = t & 63, cc = t >> 6;
    float acc0 = 0.f, acc1 = 0.f, acc2 = 0.f, acc3 = 0.f;
    for (int j = cc; j < NTOK; j += 4) {
        float v = g_qkv[((size_t)(bb * NTOK + j)) * 1536 + 1024 + h * 64 + d];
        acc0 += s[0*NTOK + j] * v; acc1 += s[1*NTOK + j] * v;
        acc2 += s[2*NTOK + j] * v; acc3 += s[3*NTOK + j] * v;
    }
    sacc[(0*4 + cc)*64 + d] = acc0; sacc[(1*4 + cc)*64 + d] = acc1;
    sacc[(2*4 + cc)*64 + d] = acc2; sacc[(3*4 + cc)*64 + d] = acc3;
    __syncthreads();
    if (t < 64) {
        #pragma unroll
        for (int q = 0; q < 4; q++) {
            float o = (sacc[(q*4+0)*64+t] + sacc[(q*4+1)*64+t] +
                       sacc[(q*4+2)*64+t] + sacc[(q*4+3)*64+t]) * inv[q];
            int jq = qc * 4 + q;
            size_t off = ((size_t)(bb * NTOK + jq)) * 512 + h * 64 + t;
            __nv_bfloat16 hi, lo;
            split2(o, hi, lo);
            g_attn_hi[off] = hi; g_attn_lo[off] = lo;
        }
    }
}

// ---------------- frame attention: fused rope + q-scale, K/V in smem ----------------
// grid (14, 256): x = query chunk (14 queries), y = group (bb,h,fr). Reads RAW qkv.
#define FA_BYTES (30008*4)
__global__ __launch_bounds__(256, 1) void k_frame_attn() {
    extern __shared__ float fs[];
    float* Ks   = fs;           // 220 x 65
    float* Vs   = fs + 14300;   // 220 x 65
    float* qs   = fs + 28600;   // 14 x 64
    float* s    = fs + 29496;   // 224
    float* red  = fs + 29720;   // 32
    float* sacc = fs + 29752;   // 256
    int g = blockIdx.y;
    int fr = g & 15;
    int bh = g >> 4;
    int h = bh & 7, bb = bh >> 3;
    int qbase = blockIdx.x * 14;
    int t = threadIdx.x;

    for (int i = t; i < 220 * 32; i += 256) {
        int j = i >> 5, sx = i & 31;
        int tj = (j < NJx) ? j : NJx + fr * NPATCH + (j - NJx);
        size_t base = ((size_t)(bb * NTOK + tj)) * 1536 + h * 64 + 2 * sx;
        float k0 = g_qkv[base + 512], k1 = g_qkv[base + 513];
        if (j >= NJx) {
            int p = j - NJx;
            float c = g_cos[p * 32 + sx], sn = g_sin[p * 32 + sx];
            float nk0 = k0 * c - k1 * sn, nk1 = k1 * c + k0 * sn;
            k0 = nk0; k1 = nk1;
        }
        Ks[j * 65 + 2 * sx]     = k0;
        Ks[j * 65 + 2 * sx + 1] = k1;
        Vs[j * 65 + 2 * sx]     = g_qkv[base + 1024];
        Vs[j * 65 + 2 * sx + 1] = g_qkv[base + 1025];
    }
    for (int i = t; i < 14 * 32; i += 256) {
        int q = i >> 5, sx = i & 31;
        int ti = NJx + fr * NPATCH + qbase + q;
        size_t base = ((size_t)(bb * NTOK + ti)) * 1536 + h * 64 + 2 * sx;
        float q0 = g_qkv[base] * 0.125f, q1 = g_qkv[base + 1] * 0.125f;
        int p = qbase + q;
        float c = g_cos[p * 32 + sx], sn = g_sin[p * 32 + sx];
        qs[q * 64 + 2 * sx]     = q0 * c - q1 * sn;
        qs[q * 64 + 2 * sx + 1] = q1 * c + q0 * sn;
    }
    __syncthreads();

    for (int ql = 0; ql < 14; ql++) {
        if (t < 220) {
            const float* kr = Ks + t * 65;
            const float* qq = qs + ql * 64;
            float acc = 0.f;
            #pragma unroll
            for (int d = 0; d < 64; d++) acc += qq[d] * kr[d];
            s[t] = acc;
        }
        __syncthreads();
        float m = (t < 220) ? s[t] : -INFINITY;
        m = block_max(m, red);
        float e = 0.f;
        if (t < 220) { e = expf(s[t] - m); s[t] = e; }
        float denom = block_sum(e, red);
        float inv = 1.f / denom;
        int d = t & 63, cc = t >> 6;
        float acc = 0.f;
        for (int j = cc; j < 220; j += 4) acc += s[j] * Vs[j * 65 + d];
        sacc[cc * 64 + d] = acc;
        __syncthreads();
        if (t < 64) {
            float o = (sacc[t] + sacc[64 + t] + sacc[128 + t] + sacc[192 + t]) * inv;
            int ti = NJx + fr * NPATCH + qbase + ql;
            size_t off = ((size_t)(bb * NTOK + ti)) * 512 + h * 64 + t;
            __nv_bfloat16 hi, lo;
            split2(o, hi, lo);
            g_attn_hi[off] = hi; g_attn_lo[off] = lo;
        }
        __syncthreads();
    }
}

// ---------------- host helpers ----------------
template<int MT, int MODE>
static void launch_mma_t(const __nv_bfloat16* Ah, const __nv_bfloat16* Al,
                         const __nv_bfloat16* Bh, const __nv_bfloat16* Bl,
                         const float* bias, const float* res, float* C,
                         int M, int N, int K, int BIAS, int RES) {
    constexpr int SMEM = 3 * (MT * 5120 + 40960);
    dim3 grid(N / 256, (M + MT * 32 - 1) / (MT * 32));
    k_mma_gemm<MT, MODE><<<grid, 256, SMEM>>>(Ah, Al, Bh, Bl, bias, res, C, M, N, K, BIAS, RES);
}

extern "C" void kernel_launch(void* const* d_in, const int* in_sizes, int n_in,
                              void* d_out, int out_size) {
    const float* video        = (const float*)d_in[0];
    const float* patch_w      = (const float*)d_in[1];
    const float* patch_b      = (const float*)d_in[2];
    const float* joints_token = (const float*)d_in[3];
    const float* ln_attn_w    = (const float*)d_in[4];
    const float* ln_attn_b    = (const float*)d_in[5];
    const float* qkv_w        = (const float*)d_in[6];
    const float* attn_out_w   = (const float*)d_in[7];
    const float* attn_out_b   = (const float*)d_in[8];
    const float* ln_ff_w      = (const float*)d_in[9];
    const float* ln_ff_b      = (const float*)d_in[10];
    const float* ff1_w        = (const float*)d_in[11];
    const float* ff1_b        = (const float*)d_in[12];
    const float* ff2_w        = (const float*)d_in[13];
    const float* ff2_b        = (const float*)d_in[14];
    const float* ln_out_w     = (const float*)d_in[15];
    const float* ln_out_b     = (const float*)d_in[16];
    const float* out_w        = (const float*)d_in[17];
    const float* out_b        = (const float*)d_in[18];

    static bool attr_set = false;
    if (!attr_set) {
        cudaFuncSetAttribute(k_mma_gemm<4,0>, cudaFuncAttributeMaxDynamicSharedMemorySize, 3*(4*5120+40960));
        cudaFuncSetAttribute(k_mma_gemm<4,1>, cudaFuncAttributeMaxDynamicSharedMemorySize, 3*(4*5120+40960));
        cudaFuncSetAttribute(k_mma_gemm<2,0>, cudaFuncAttributeMaxDynamicSharedMemorySize, 3*(2*5120+40960));
        cudaFuncSetAttribute(k_frame_attn, cudaFuncAttributeMaxDynamicSharedMemorySize, FA_BYTES);
        cudaFuncSetAttribute(k_joints_attn, cudaFuncAttributeMaxDynamicSharedMemorySize, JA_BYTES);
        attr_set = true;
    }

    float *px, *pqkv, *ptok, *pjt;
    cudaGetSymbolAddress((void**)&px,    g_x);
    cudaGetSymbolAddress((void**)&pqkv,  g_qkv);
    cudaGetSymbolAddress((void**)&ptok,  g_tok);
    cudaGetSymbolAddress((void**)&pjt,   g_jt);

    __nv_bfloat16 *xnh, *xnl, *ath, *atl, *hgh, *hgl, *pth, *ptl;
    cudaGetSymbolAddress((void**)&xnh, g_xn_hi);
    cudaGetSymbolAddress((void**)&xnl, g_xn_lo);
    cudaGetSymbolAddress((void**)&ath, g_attn_hi);
    cudaGetSymbolAddress((void**)&atl, g_attn_lo);
    cudaGetSymbolAddress((void**)&hgh, g_hg_hi);
    cudaGetSymbolAddress((void**)&hgl, g_hg_lo);
    cudaGetSymbolAddress((void**)&pth, g_pat_hi);
    cudaGetSymbolAddress((void**)&ptl, g_pat_lo);

    __nv_bfloat16 *patchThi, *patchTlo, *qkvThi, *qkvTlo, *outThi, *outTlo,
                  *ff1Thi, *ff1Tlo, *ff2Thi, *ff2Tlo;
    cudaGetSymbolAddress((void**)&patchThi, g_patchT_hi);
    cudaGetSymbolAddress((void**)&patchTlo, g_patchT_lo);
    cudaGetSymbolAddress((void**)&qkvThi,   g_qkvT_hi);
    cudaGetSymbolAddress((void**)&qkvTlo,   g_qkvT_lo);
    cudaGetSymbolAddress((void**)&outThi,   g_outT_hi);
    cudaGetSymbolAddress((void**)&outTlo,   g_outT_lo);
    cudaGetSymbolAddress((void**)&ff1Thi,   g_ff1T_hi);
    cudaGetSymbolAddress((void**)&ff1Tlo,   g_ff1T_lo);
    cudaGetSymbolAddress((void**)&ff2Thi,   g_ff2T_hi);
    cudaGetSymbolAddress((void**)&ff2Tlo,   g_ff2T_lo);

    // ---- weight prep ----
    k_wprep<<<dim3(16, 16), 256>>>(patch_w, patchThi, patchTlo, 512, 512);
    for (int l = 0; l < 12; l++) {
        k_wprep<<<dim3(48, 16), 256>>>(qkv_w + (size_t)l * 512 * 1536,
            qkvThi + (size_t)l * 1536 * 512, qkvTlo + (size_t)l * 1536 * 512, 512, 1536);
        k_wprep<<<dim3(16, 16), 256>>>(attn_out_w + (size_t)l * 512 * 512,
            outThi + (size_t)l * 512 * 512, outTlo + (size_t)l * 512 * 512, 512, 512);
        k_wprep_ff1<<<dim3(128, 16), 256>>>(ff1_w + (size_t)l * 512 * 4096,
            ff1Thi + (size_t)l * 4096 * 512, ff1Tlo + (size_t)l * 4096 * 512);
        k_wprep<<<dim3(16, 64), 256>>>(ff2_w + (size_t)l * 2048 * 512,
            ff2Thi + (size_t)l * 512 * 2048, ff2Tlo + (size_t)l * 512 * 2048, 2048, 512);
    }

    // ---- setup ----
    k_sincos<<<(NPATCH * 32 + 255) / 256, 256>>>();
    k_im2col<<<(int)(((size_t)B_ * NSP * DIMC + 255) / 256), 256>>>(video);
    launch_mma_t<4,0>(pth, ptl, patchThi, patchTlo, patch_b, nullptr, ptok,
                      B_ * NSP, DIMC, DIMC, 1, 0);
    k_assemble<<<(int)(((size_t)B_ * NTOK * DIMC + 255) / 256), 256>>>(joints_token);

    for (int l = 0; l < 12; l++) {
        k_ln<<<ROWS, 256>>>(px, ln_attn_w + l * 512, ln_attn_b + l * 512, xnh, xnl);
        launch_mma_t<4,0>(xnh, xnl, qkvThi + (size_t)l * 1536 * 512, qkvTlo + (size_t)l * 1536 * 512,
                          nullptr, nullptr, pqkv, ROWS, 1536, 512, 0, 0);
        k_joints_attn<<<dim3(6, 16), 256, JA_BYTES>>>();
        k_frame_attn<<<dim3(14, 256), 256, FA_BYTES>>>();
        launch_mma_t<2,0>(ath, atl, outThi + (size_t)l * 512 * 512, outTlo + (size_t)l * 512 * 512,
                          attn_out_b + l * 512, px, px, ROWS, 512, 512, 1, 1);
        k_ln<<<ROWS, 256>>>(px, ln_ff_w + l * 512, ln_ff_b + l * 512, xnh, xnl);
        launch_mma_t<4,1>(xnh, xnl, ff1Thi + (size_t)l * 4096 * 512, ff1Tlo + (size_t)l * 4096 * 512,
                          ff1_b + (size_t)l * 4096, nullptr, nullptr, ROWS, 4096, 512, 1, 0);
        launch_mma_t<2,0>(hgh, hgl, ff2Thi + (size_t)l * 512 * 2048, ff2Tlo + (size_t)l * 512 * 2048,
                          ff2_b + l * 512, px, px, ROWS, 512, 2048, 1, 1);
    }

    // ---- head ----
    k_ln_gather<<<48, 256>>>(ln_out_w, ln_out_b);
    {
        dim3 grid(384 / 128, 1);
        k_sgemm<1, 0><<<grid, 256>>>(pjt, out_w, out_b, nullptr, (float*)d_out, 48, 384, 512);
    }
}

// round 17
// speedup vs baseline: 3.8472x; 1.4406x over previous
#include <cuda_runtime.h>
#include <cuda_bf16.h>
#include <math.h>
#include <stdint.h>

// ---------------- problem constants ----------------
#define B_      2
#define F_      16
#define NJx     24
#define NPATCH  196          // 14*14
#define NSP     3136         // F_*NPATCH
#define NTOK    3160         // NJx + NSP
#define DIMC    512
#define ROWS    (B_*NTOK)    // 6320

// ---------------- scratch (device globals; no runtime alloc) ----------------
__device__ float g_x   [B_*NTOK*DIMC];
__device__ float g_qkv [B_*NTOK*1536];
__device__ float g_tok [B_*NSP*DIMC];
__device__ float g_sin [NPATCH*32];
__device__ float g_cos [NPATCH*32];
__device__ float g_jt  [48*DIMC];

// bf16 hi/lo activation operands (written fused by producers)
__device__ __nv_bfloat16 g_xn_hi  [ROWS*DIMC];
__device__ __nv_bfloat16 g_xn_lo  [ROWS*DIMC];
__device__ __nv_bfloat16 g_attn_hi[ROWS*DIMC];
__device__ __nv_bfloat16 g_attn_lo[ROWS*DIMC];
__device__ __nv_bfloat16 g_hg_hi  [(size_t)ROWS*2048];
__device__ __nv_bfloat16 g_hg_lo  [(size_t)ROWS*2048];
__device__ __nv_bfloat16 g_pat_hi [B_*NSP*DIMC];
__device__ __nv_bfloat16 g_pat_lo [B_*NSP*DIMC];

// transposed bf16 hi/lo weights ([N,K] layout; ff1 column-pair-permuted)
__device__ __nv_bfloat16 g_patchT_hi[512*512];
__device__ __nv_bfloat16 g_patchT_lo[512*512];
__device__ __nv_bfloat16 g_qkvT_hi [12*1536*512];
__device__ __nv_bfloat16 g_qkvT_lo [12*1536*512];
__device__ __nv_bfloat16 g_outT_hi [12*512*512];
__device__ __nv_bfloat16 g_outT_lo [12*512*512];
__device__ __nv_bfloat16 g_ff1T_hi [(size_t)12*4096*512];
__device__ __nv_bfloat16 g_ff1T_lo [(size_t)12*4096*512];
__device__ __nv_bfloat16 g_ff2T_hi [(size_t)12*512*2048];
__device__ __nv_bfloat16 g_ff2T_lo [(size_t)12*512*2048];

// ---------------- helpers ----------------
__device__ __forceinline__ uint32_t smem_u32(const void* p) {
    uint32_t a;
    asm("{ .reg .u64 t; cvta.to.shared.u64 t, %1; cvt.u32.u64 %0, t; }" : "=r"(a) : "l"(p));
    return a;
}
__device__ __forceinline__ void cp_async16(uint32_t dst, const void* src, bool pred) {
    int sz = pred ? 16 : 0;
    asm volatile("cp.async.ca.shared.global [%0], [%1], 16, %2;"
                 :: "r"(dst), "l"(src), "r"(sz) : "memory");
}
__device__ __forceinline__ void cp_commit() {
    asm volatile("cp.async.commit_group;" ::: "memory");
}
template<int NW> __device__ __forceinline__ void cp_wait() {
    asm volatile("cp.async.wait_group %0;" :: "n"(NW) : "memory");
}
__device__ __forceinline__ void ldmx4(uint32_t* r, uint32_t addr) {
    asm volatile("ldmatrix.sync.aligned.m8n8.x4.shared.b16 {%0,%1,%2,%3}, [%4];"
                 : "=r"(r[0]), "=r"(r[1]), "=r"(r[2]), "=r"(r[3]) : "r"(addr));
}
__device__ __forceinline__ void mma16816(float* c, const uint32_t* a, const uint32_t* b) {
    asm volatile("mma.sync.aligned.m16n8k16.row.col.f32.bf16.bf16.f32 "
                 "{%0,%1,%2,%3}, {%4,%5,%6,%7}, {%8,%9}, {%0,%1,%2,%3};"
                 : "+f"(c[0]), "+f"(c[1]), "+f"(c[2]), "+f"(c[3])
                 : "r"(a[0]), "r"(a[1]), "r"(a[2]), "r"(a[3]), "r"(b[0]), "r"(b[1]));
}
__device__ __forceinline__ void split2(float v, __nv_bfloat16& h, __nv_bfloat16& l) {
    h = __float2bfloat16(v);
    l = __float2bfloat16(v - __bfloat162float(h));
}

// ---------------- block reductions (blockDim.x == 256) ----------------
__device__ __forceinline__ float warp_sum(float v) {
    #pragma unroll
    for (int o = 16; o > 0; o >>= 1) v += __shfl_xor_sync(0xffffffffu, v, o);
    return v;
}
__device__ __forceinline__ float warp_max(float v) {
    #pragma unroll
    for (int o = 16; o > 0; o >>= 1) v = fmaxf(v, __shfl_xor_sync(0xffffffffu, v, o));
    return v;
}
__device__ __forceinline__ float block_sum(float v, float* red) {
    v = warp_sum(v);
    int lane = threadIdx.x & 31, w = threadIdx.x >> 5;
    if (lane == 0) red[w] = v;
    __syncthreads();
    if (threadIdx.x < 32) {
        float r = (threadIdx.x < 8) ? red[threadIdx.x] : 0.f;
        r = warp_sum(r);
        if (threadIdx.x == 0) red[0] = r;
    }
    __syncthreads();
    float out = red[0];
    __syncthreads();
    return out;
}
__device__ __forceinline__ float block_max(float v, float* red) {
    v = warp_max(v);
    int lane = threadIdx.x & 31, w = threadIdx.x >> 5;
    if (lane == 0) red[w] = v;
    __syncthreads();
    if (threadIdx.x < 32) {
        float r = (threadIdx.x < 8) ? red[threadIdx.x] : -INFINITY;
        r = warp_max(r);
        if (threadIdx.x == 0) red[0] = r;
    }
    __syncthreads();
    float out = red[0];
    __syncthreads();
    return out;
}

// ---------------- weight prep (batched over layers via blockIdx.z) ----------------
__global__ __launch_bounds__(256) void k_wprep(const float* __restrict__ W,
                                               __nv_bfloat16* __restrict__ Thi,
                                               __nv_bfloat16* __restrict__ Tlo,
                                               int K, int N) {
    __shared__ float tile[32][33];
    size_t loff = (size_t)blockIdx.z * K * N;
    W += loff; Thi += loff; Tlo += loff;
    int k0 = blockIdx.y * 32, n0 = blockIdx.x * 32;
    int tx = threadIdx.x & 31, ty = threadIdx.x >> 5;
    #pragma unroll
    for (int r = ty; r < 32; r += 8)
        tile[r][tx] = W[(size_t)(k0 + r) * N + n0 + tx];
    __syncthreads();
    #pragma unroll
    for (int r = ty; r < 32; r += 8) {
        float v = tile[tx][r];
        __nv_bfloat16 hi, lo;
        split2(v, hi, lo);
        size_t o = (size_t)(n0 + r) * K + k0 + tx;
        Thi[o] = hi; Tlo[o] = lo;
    }
}

// ff1 prep: W[512,4096] -> permuted T[4096,512]; out row 2j <- col j, 2j+1 <- col j+2048
__global__ __launch_bounds__(256) void k_wprep_ff1(const float* __restrict__ W,
                                                   __nv_bfloat16* __restrict__ Thi,
                                                   __nv_bfloat16* __restrict__ Tlo) {
    __shared__ float tile[32][33];
    size_t loff = (size_t)blockIdx.z * 512 * 4096;
    W += loff; Thi += loff; Tlo += loff;
    int k0 = blockIdx.y * 32, n0 = blockIdx.x * 32;
    int tx = threadIdx.x & 31, ty = threadIdx.x >> 5;
    int n0h = n0 >> 1;
    int scol = (tx < 16) ? (n0h + tx) : (n0h + 2048 + tx - 16);
    #pragma unroll
    for (int r = ty; r < 32; r += 8)
        tile[r][tx] = W[(size_t)(k0 + r) * 4096 + scol];
    __syncthreads();
    #pragma unroll
    for (int r = ty; r < 32; r += 8) {
        int cc = (r >> 1) + ((r & 1) << 4);
        float v = tile[tx][cc];
        __nv_bfloat16 hi, lo;
        split2(v, hi, lo);
        size_t o = (size_t)(n0 + r) * 512 + k0 + tx;
        Thi[o] = hi; Tlo[o] = lo;
    }
}

// ---------------- bf16x3 HMMA GEMM (templated) ----------------
template<int MT>
__device__ __forceinline__ void g2_issue(
    uint32_t sb, int stage, int kc, int t, int bm, int bn,
    const __nv_bfloat16* __restrict__ Ah, const __nv_bfloat16* __restrict__ Al,
    const __nv_bfloat16* __restrict__ Bh, const __nv_bfloat16* __restrict__ Bl,
    int M, int K)
{
    constexpr uint32_t OAL = MT * 2560u;
    constexpr uint32_t OBH = MT * 5120u;
    constexpr uint32_t OBL = MT * 5120u + 20480u;
    constexpr uint32_t STG = MT * 5120u + 40960u;
    uint32_t s0 = sb + (uint32_t)stage * STG;
    int k0 = kc << 5;
    #pragma unroll
    for (int j = 0; j < MT + 8; j++) {
        int i = t + j * 256;
        int r = i >> 2, c = i & 3;
        if (r < MT * 32) {
            int gr = bm + r; bool p = gr < M;
            cp_async16(s0 + (uint32_t)(r * 80 + c * 16),
                       Ah + (size_t)(p ? gr : 0) * K + k0 + c * 8, p);
        } else if (r < MT * 64) {
            int rr = r - MT * 32; int gr = bm + rr; bool p = gr < M;
            cp_async16(s0 + OAL + (uint32_t)(rr * 80 + c * 16),
                       Al + (size_t)(p ? gr : 0) * K + k0 + c * 8, p);
        } else if (r < MT * 64 + 256) {
            int rr = r - MT * 64;
            cp_async16(s0 + OBH + (uint32_t)(rr * 80 + c * 16),
                       Bh + (size_t)(bn + rr) * K + k0 + c * 8, true);
        } else {
            int rr = r - MT * 64 - 256;
            cp_async16(s0 + OBL + (uint32_t)(rr * 80 + c * 16),
                       Bl + (size_t)(bn + rr) * K + k0 + c * 8, true);
        }
    }
    cp_commit();
}

template<int MT, int MODE>
__global__ __launch_bounds__(256, 1) void k_mma_gemm(
    const __nv_bfloat16* __restrict__ Ah, const __nv_bfloat16* __restrict__ Al,
    const __nv_bfloat16* __restrict__ Bh, const __nv_bfloat16* __restrict__ Bl,
    const float* __restrict__ bias, const float* __restrict__ res,
    float* __restrict__ C, int M, int N, int K, int BIAS, int RES)
{
    constexpr uint32_t OAL = MT * 2560u;
    constexpr uint32_t OBH = MT * 5120u;
    constexpr uint32_t OBL = MT * 5120u + 20480u;
    constexpr uint32_t STG = MT * 5120u + 40960u;
    extern __shared__ char smem[];
    uint32_t sb = smem_u32(smem);
    int t = threadIdx.x, lane = t & 31, wid = t >> 5;
    int bm = blockIdx.y * (MT * 32), bn = blockIdx.x * 256;
    int wm = (wid >> 2) * (MT * 16), wn = (wid & 3) * 64;

    float c[MT][8][4];
    #pragma unroll
    for (int mi = 0; mi < MT; mi++)
        #pragma unroll
        for (int ni = 0; ni < 8; ni++)
            #pragma unroll
            for (int f = 0; f < 4; f++) c[mi][ni][f] = 0.f;

    int nk = K >> 5;
    g2_issue<MT>(sb, 0, 0, t, bm, bn, Ah, Al, Bh, Bl, M, K);
    g2_issue<MT>(sb, 1, 1, t, bm, bn, Ah, Al, Bh, Bl, M, K);

    int lr = lane & 15;
    int lc = ((lane >> 4) & 1) << 3;

    for (int kc = 0; kc < nk; kc++) {
        if (kc + 1 < nk) cp_wait<1>(); else cp_wait<0>();
        __syncthreads();
        if (kc + 2 < nk)
            g2_issue<MT>(sb, (kc + 2) % 3, kc + 2, t, bm, bn, Ah, Al, Bh, Bl, M, K);

        uint32_t st  = sb + (uint32_t)(kc % 3) * STG;
        uint32_t sAh = st, sAl = st + OAL, sBh = st + OBH, sBl = st + OBL;

        #pragma unroll
        for (int ks = 0; ks < 2; ks++) {
            int kcol = ks * 16 + lc;
            uint32_t a[MT][4], bh[8][2], bl[8][2];
            #pragma unroll
            for (int mi = 0; mi < MT; mi++)
                ldmx4(a[mi], sAh + (uint32_t)((wm + mi * 16 + lr) * 40 + kcol) * 2);
            #pragma unroll
            for (int nh = 0; nh < 4; nh++) {
                uint32_t r[4];
                ldmx4(r, sBh + (uint32_t)((wn + nh * 16 + lr) * 40 + kcol) * 2);
                bh[nh * 2][0] = r[0]; bh[nh * 2][1] = r[2];
                bh[nh * 2 + 1][0] = r[1]; bh[nh * 2 + 1][1] = r[3];
                ldmx4(r, sBl + (uint32_t)((wn + nh * 16 + lr) * 40 + kcol) * 2);
                bl[nh * 2][0] = r[0]; bl[nh * 2][1] = r[2];
                bl[nh * 2 + 1][0] = r[1]; bl[nh * 2 + 1][1] = r[3];
            }
            #pragma unroll
            for (int mi = 0; mi < MT; mi++)
                #pragma unroll
                for (int ni = 0; ni < 8; ni++) {
                    mma16816(c[mi][ni], a[mi], bh[ni]);
                    mma16816(c[mi][ni], a[mi], bl[ni]);
                }
            #pragma unroll
            for (int mi = 0; mi < MT; mi++)
                ldmx4(a[mi], sAl + (uint32_t)((wm + mi * 16 + lr) * 40 + kcol) * 2);
            #pragma unroll
            for (int mi = 0; mi < MT; mi++)
                #pragma unroll
                for (int ni = 0; ni < 8; ni++)
                    mma16816(c[mi][ni], a[mi], bh[ni]);
        }
    }

    int row0 = bm + wm + (lane >> 2);
    int col0 = bn + wn + (lane & 3) * 2;
    #pragma unroll
    for (int mi = 0; mi < MT; mi++) {
        #pragma unroll
        for (int hh = 0; hh < 2; hh++) {
            int r = row0 + mi * 16 + hh * 8;
            if (r >= M) continue;
            #pragma unroll
            for (int ni = 0; ni < 8; ni++) {
                int col = col0 + ni * 8;
                if (MODE == 0) {
                    float2 v = make_float2(c[mi][ni][hh * 2], c[mi][ni][hh * 2 + 1]);
                    if (BIAS) { v.x += bias[col]; v.y += bias[col + 1]; }
                    if (RES) {
                        float2 rr = *reinterpret_cast<const float2*>(res + (size_t)r * N + col);
                        v.x += rr.x; v.y += rr.y;
                    }
                    *reinterpret_cast<float2*>(C + (size_t)r * N + col) = v;
                } else {
                    int j = col >> 1;
                    float a = c[mi][ni][hh * 2]     + bias[j];
                    float g = c[mi][ni][hh * 2 + 1] + bias[j + 2048];
                    float ge = 0.5f * g * (1.f + erff(g * 0.7071067811865476f));
                    float v = a * ge;
                    __nv_bfloat16 hi, lo;
                    split2(v, hi, lo);
                    g_hg_hi[(size_t)r * 2048 + j] = hi;
                    g_hg_lo[(size_t)r * 2048 + j] = lo;
                }
            }
        }
    }
}

// ---------------- fp32 SGEMM (tiny head GEMM only) ----------------
template<int BIAS, int RES>
__global__ __launch_bounds__(256) void k_sgemm(
    const float* __restrict__ A, const float* __restrict__ B,
    const float* __restrict__ bias, const float* __restrict__ res,
    float* __restrict__ C, int M, int N, int K)
{
    __shared__ float As[8][128];
    __shared__ float Bs[8][128];
    int tid = threadIdx.x;
    int bm = blockIdx.y * 128;
    int bn = blockIdx.x * 128;
    int tx = tid & 15, ty = tid >> 4;
    int ar = tid >> 1, ac = (tid & 1) * 4;
    int br = tid >> 5, bc = (tid & 31) * 4;

    float acc[8][8];
    #pragma unroll
    for (int i = 0; i < 8; i++)
        #pragma unroll
        for (int j = 0; j < 8; j++) acc[i][j] = 0.f;

    bool aval = (bm + ar) < M;
    const float* Aptr = A + (size_t)(bm + ar) * K + ac;
    const float* Bptr = B + (size_t)br * N + bn + bc;

    for (int k0 = 0; k0 < K; k0 += 8) {
        float4 av = make_float4(0.f, 0.f, 0.f, 0.f);
        if (aval) av = *reinterpret_cast<const float4*>(Aptr + k0);
        As[ac + 0][ar] = av.x; As[ac + 1][ar] = av.y;
        As[ac + 2][ar] = av.z; As[ac + 3][ar] = av.w;
        float4 bv = *reinterpret_cast<const float4*>(Bptr + (size_t)k0 * N);
        *reinterpret_cast<float4*>(&Bs[br][bc]) = bv;
        __syncthreads();
        #pragma unroll
        for (int kk = 0; kk < 8; kk++) {
            float af[8], bf[8];
            *reinterpret_cast<float4*>(&af[0]) = *reinterpret_cast<const float4*>(&As[kk][ty * 4]);
            *reinterpret_cast<float4*>(&af[4]) = *reinterpret_cast<const float4*>(&As[kk][64 + ty * 4]);
            *reinterpret_cast<float4*>(&bf[0]) = *reinterpret_cast<const float4*>(&Bs[kk][tx * 4]);
            *reinterpret_cast<float4*>(&bf[4]) = *reinterpret_cast<const float4*>(&Bs[kk][64 + tx * 4]);
            #pragma unroll
            for (int i = 0; i < 8; i++)
                #pragma unroll
                for (int j = 0; j < 8; j++)
                    acc[i][j] = fmaf(af[i], bf[j], acc[i][j]);
        }
        __syncthreads();
    }

    #pragma unroll
    for (int i = 0; i < 8; i++) {
        int row = bm + ((i < 4) ? (ty * 4 + i) : (64 + ty * 4 + i - 4));
        if (row >= M) continue;
        #pragma unroll
        for (int jh = 0; jh < 2; jh++) {
            int col = bn + ((jh == 0) ? (tx * 4) : (64 + tx * 4));
            float4 v;
            v.x = acc[i][jh * 4 + 0]; v.y = acc[i][jh * 4 + 1];
            v.z = acc[i][jh * 4 + 2]; v.w = acc[i][jh * 4 + 3];
            if (BIAS) {
                float4 b4 = *reinterpret_cast<const float4*>(bias + col);
                v.x += b4.x; v.y += b4.y; v.z += b4.z; v.w += b4.w;
            }
            if (RES) {
                float4 r4 = *reinterpret_cast<const float4*>(res + (size_t)row * N + col);
                v.x += r4.x; v.y += r4.y; v.z += r4.z; v.w += r4.w;
            }
            *reinterpret_cast<float4*>(C + (size_t)row * N + col) = v;
        }
    }
}

// ---------------- rotary tables ----------------
__global__ void k_sincos() {
    int idx = blockIdx.x * blockDim.x + threadIdx.x;
    if (idx >= NPATCH * 32) return;
    int p = idx >> 5, s = idx & 31;
    int ph = p / 14, pw = p % 14;
    int ss = (s < 16) ? s : (s - 16);
    float scale = exp2f((float)ss * (2.321928094887362f / 15.f));
    int pos_i = (s < 16) ? ph : pw;
    float pos = -1.f + 2.f * (float)pos_i / 13.f;
    float ang = pos * scale * 3.14159265358979323846f;
    g_sin[idx] = sinf(ang);
    g_cos[idx] = cosf(ang);
}

// ---------------- patch extraction (im2col, writes bf16 hi/lo) ----------------
__global__ void k_im2col(const float* __restrict__ video) {
    size_t idx = (size_t)blockIdx.x * blockDim.x + threadIdx.x;
    if (idx >= (size_t)B_ * NSP * DIMC) return;
    int e = (int)(idx & 511);
    size_t r = idx >> 9;
    int bb = (int)(r / NSP); int t = (int)(r % NSP);
    int fr = t / NPATCH; int pp = t % NPATCH;
    int ph = pp / 14, pw = pp % 14;
    int py = e >> 5, px = (e >> 1) & 15, cc = e & 1;
    size_t vidx = ((((size_t)(bb * F_ + fr) * 2 + cc) * 224 + (ph * 16 + py)) * 224 + (pw * 16 + px));
    float v = video[vidx];
    __nv_bfloat16 hi, lo;
    split2(v, hi, lo);
    g_pat_hi[idx] = hi; g_pat_lo[idx] = lo;
}

// ---------------- token assembly ----------------
__global__ void k_assemble(const float* __restrict__ joints_token) {
    size_t idx = (size_t)blockIdx.x * blockDim.x + threadIdx.x;
    if (idx >= (size_t)B_ * NTOK * DIMC) return;
    int col = (int)(idx & 511);
    size_t r = idx >> 9;
    int bb = (int)(r / NTOK); int i = (int)(r % NTOK);
    g_x[idx] = (i < NJx) ? joints_token[i * DIMC + col]
                         : g_tok[((size_t)bb * NSP + (i - NJx)) * DIMC + col];
}

// ---------------- LayerNorm (fused bf16 hi/lo split output) ----------------
__global__ __launch_bounds__(256) void k_ln(const float* __restrict__ in,
                                            const float* __restrict__ w,
                                            const float* __restrict__ b,
                                            __nv_bfloat16* __restrict__ ohi,
                                            __nv_bfloat16* __restrict__ olo) {
    __shared__ float red[32];
    int row = blockIdx.x;
    int t = threadIdx.x;
    const float* ri = in + (size_t)row * DIMC;
    float v0 = ri[t], v1 = ri[t + 256];
    float mean = block_sum(v0 + v1, red) * (1.f / 512.f);
    float d0 = v0 - mean, d1 = v1 - mean;
    float var = block_sum(d0 * d0 + d1 * d1, red) * (1.f / 512.f);
    float rs = rsqrtf(var + 1e-5f);
    float y0 = d0 * rs * w[t] + b[t];
    float y1 = d1 * rs * w[t + 256] + b[t + 256];
    size_t base = (size_t)row * DIMC;
    __nv_bfloat16 h, l;
    split2(y0, h, l); ohi[base + t] = h;       olo[base + t] = l;
    split2(y1, h, l); ohi[base + t + 256] = h; olo[base + t + 256] = l;
}

// final LN on joint tokens (fp32 out, tiny head)
__global__ __launch_bounds__(256) void k_ln_gather(const float* __restrict__ w,
                                                   const float* __restrict__ b) {
    __shared__ float red[32];
    int row = blockIdx.x;
    int bb = row / NJx, i = row % NJx;
    int t = threadIdx.x;
    const float* ri = g_x + ((size_t)bb * NTOK + i) * DIMC;
    float v0 = ri[t], v1 = ri[t + 256];
    float mean = block_sum(v0 + v1, red) * (1.f / 512.f);
    float d0 = v0 - mean, d1 = v1 - mean;
    float var = block_sum(d0 * d0 + d1 * d1, red) * (1.f / 512.f);
    float rs = rsqrtf(var + 1e-5f);
    float* ro = g_jt + (size_t)row * DIMC;
    ro[t]       = d0 * rs * w[t]       + b[t];
    ro[t + 256] = d1 * rs * w[t + 256] + b[t + 256];
}

// ---------------- joints attention: 4 queries/block, raw (pre-rope) qkv ----------------
#define JA_FLOATS (256 + 4*NTOK + 32 + 1024)
#define JA_BYTES  (JA_FLOATS*4)
__global__ __launch_bounds__(256, 1) void k_joints_attn() {
    extern __shared__ float js[];
    float* sq   = js;                  // 4 x 64
    float* s    = js + 256;            // 4 x NTOK
    float* red  = js + 256 + 4*NTOK;   // 32
    float* sacc = red + 32;            // 4 x 4 x 64
    int qc = blockIdx.x;
    int g  = blockIdx.y; int h = g & 7, bb = g >> 3;
    int t = threadIdx.x;
    {
        int q = t >> 6, d = t & 63;
        int jq = qc * 4 + q;
        sq[t] = g_qkv[((size_t)(bb * NTOK + jq)) * 1536 + h * 64 + d] * 0.125f;
    }
    __syncthreads();
    for (int j = t; j < NTOK; j += 256) {
        const float* kp = g_qkv + ((size_t)(bb * NTOK + j)) * 1536 + 512 + h * 64;
        float a0 = 0.f, a1 = 0.f, a2 = 0.f, a3 = 0.f;
        #pragma unroll
        for (int d = 0; d < 64; d += 4) {
            float4 kv = *reinterpret_cast<const float4*>(kp + d);
            a0 += sq[d] * kv.x + sq[d+1] * kv.y + sq[d+2] * kv.z + sq[d+3] * kv.w;
            a1 += sq[64+d] * kv.x + sq[64+d+1] * kv.y + sq[64+d+2] * kv.z + sq[64+d+3] * kv.w;
            a2 += sq[128+d] * kv.x + sq[128+d+1] * kv.y + sq[128+d+2] * kv.z + sq[128+d+3] * kv.w;
            a3 += sq[192+d] * kv.x + sq[192+d+1] * kv.y + sq[192+d+2] * kv.z + sq[192+d+3] * kv.w;
        }
        s[0*NTOK + j] = a0; s[1*NTOK + j] = a1;
        s[2*NTOK + j] = a2; s[3*NTOK + j] = a3;
    }
    __syncthreads();
    float inv[4];
    #pragma unroll
    for (int q = 0; q < 4; q++) {
        float m = -INFINITY;
        for (int j = t; j < NTOK; j += 256) m = fmaxf(m, s[q*NTOK + j]);
        m = block_max(m, red);
        float ls = 0.f;
        for (int j = t; j < NTOK; j += 256) {
            float e = expf(s[q*NTOK + j] - m); s[q*NTOK + j] = e; ls += e;
        }
        inv[q] = 1.f / block_sum(ls, red);
    }
    int d = t & 63, cc = t >> 6;
    float acc0 = 0.f, acc1 = 0.f, acc2 = 0.f, acc3 = 0.f;
    for (int j = cc; j < NTOK; j += 4) {
        float v = g_qkv[((size_t)(bb * NTOK + j)) * 1536 + 1024 + h * 64 + d];
        acc0 += s[0*NTOK + j] * v; acc1 += s[1*NTOK + j] * v;
        acc2 += s[2*NTOK + j] * v; acc3 += s[3*NTOK + j] * v;
    }
    sacc[(0*4 + cc)*64 + d] = acc0; sacc[(1*4 + cc)*64 + d] = acc1;
    sacc[(2*4 + cc)*64 + d] = acc2; sacc[(3*4 + cc)*64 + d] = acc3;
    __syncthreads();
    if (t < 64) {
        #pragma unroll
        for (int q = 0; q < 4; q++) {
            float o = (sacc[(q*4+0)*64+t] + sacc[(q*4+1)*64+t] +
                       sacc[(q*4+2)*64+t] + sacc[(q*4+3)*64+t]) * inv[q];
            int jq = qc * 4 + q;
            size_t off = ((size_t)(bb * NTOK + jq)) * 512 + h * 64 + t;
            __nv_bfloat16 hi, lo;
            split2(o, hi, lo);
            g_attn_hi[off] = hi; g_attn_lo[off] = lo;
        }
    }
}

// ---------------- frame attention v3: register-tiled, float4 smem ----------------
// grid (7, 256): x = 28-query chunk, y = group (bb,h,fr). Fused rope + q-scale.
// smem floats: Ks[224*68]=15232, Vs[224*68]=15232, Qs[28*68]=1904,
//              S[28*224]=6272, sinv[28]+pad  -> 38672 floats = 154688 B
#define FA3_BYTES (38672*4)
__global__ __launch_bounds__(256, 1) void k_frame_attn() {
    extern __shared__ float fs[];
    float* Ks   = fs;
    float* Vs   = fs + 15232;
    float* Qs   = fs + 30464;
    float* S    = fs + 32368;
    float* sinv = fs + 38640;
    int g = blockIdx.y;
    int fr = g & 15;
    int bh = g >> 4;
    int h = bh & 7, bb = bh >> 3;
    int qbase = blockIdx.x * 28;
    int t = threadIdx.x, lane = t & 31, wid = t >> 5;

    // stage K (rope'd) and V, pitch 68
    for (int i = t; i < 220 * 32; i += 256) {
        int j = i >> 5, sx = i & 31;
        int tj = (j < NJx) ? j : NJx + fr * NPATCH + (j - NJx);
        size_t base = ((size_t)(bb * NTOK + tj)) * 1536 + h * 64 + 2 * sx;
        float k0 = g_qkv[base + 512], k1 = g_qkv[base + 513];
        if (j >= NJx) {
            int p = j - NJx;
            float c = g_cos[p * 32 + sx], sn = g_sin[p * 32 + sx];
            float nk0 = k0 * c - k1 * sn, nk1 = k1 * c + k0 * sn;
            k0 = nk0; k1 = nk1;
        }
        Ks[j * 68 + 2 * sx]     = k0;
        Ks[j * 68 + 2 * sx + 1] = k1;
        Vs[j * 68 + 2 * sx]     = g_qkv[base + 1024];
        Vs[j * 68 + 2 * sx + 1] = g_qkv[base + 1025];
    }
    // stage Q chunk (rope + scale), pitch 68
    for (int i = t; i < 28 * 32; i += 256) {
        int q = i >> 5, sx = i & 31;
        int ti = NJx + fr * NPATCH + qbase + q;
        size_t base = ((size_t)(bb * NTOK + ti)) * 1536 + h * 64 + 2 * sx;
        float q0 = g_qkv[base] * 0.125f, q1 = g_qkv[base + 1] * 0.125f;
        int p = qbase + q;
        float c = g_cos[p * 32 + sx], sn = g_sin[p * 32 + sx];
        Qs[q * 68 + 2 * sx]     = q0 * c - q1 * sn;
        Qs[q * 68 + 2 * sx + 1] = q1 * c + q0 * sn;
    }
    __syncthreads();

    // QK: thread (qy = t>>5 in [0,7), kx = t&31): 4 queries x 7 strided keys
    if (t < 224) {
        int qy = t >> 5, kx = t & 31;
        float acc[4][7];
        #pragma unroll
        for (int qi = 0; qi < 4; qi++)
            #pragma unroll
            for (int ki = 0; ki < 7; ki++) acc[qi][ki] = 0.f;
        #pragma unroll
        for (int d4 = 0; d4 < 16; d4++) {
            float4 qv[4], kv[7];
            #pragma unroll
            for (int qi = 0; qi < 4; qi++)
                qv[qi] = *reinterpret_cast<const float4*>(&Qs[(qy * 4 + qi) * 68 + d4 * 4]);
            #pragma unroll
            for (int ki = 0; ki < 7; ki++)
                kv[ki] = *reinterpret_cast<const float4*>(&Ks[(kx + 32 * ki) * 68 + d4 * 4]);
            #pragma unroll
            for (int qi = 0; qi < 4; qi++)
                #pragma unroll
                for (int ki = 0; ki < 7; ki++) {
                    acc[qi][ki] += qv[qi].x * kv[ki].x + qv[qi].y * kv[ki].y
                                 + qv[qi].z * kv[ki].z + qv[qi].w * kv[ki].w;
                }
        }
        #pragma unroll
        for (int qi = 0; qi < 4; qi++)
            #pragma unroll
            for (int ki = 0; ki < 7; ki++) {
                int k = kx + 32 * ki;
                if (k < 220) S[(qy * 4 + qi) * 224 + k] = acc[qi][ki];
            }
    }
    __syncthreads();

    // softmax per row (warp-level), store exp in S and 1/sum in sinv
    for (int r = wid; r < 28; r += 8) {
        float m = -INFINITY;
        for (int j = lane; j < 220; j += 32) m = fmaxf(m, S[r * 224 + j]);
        m = warp_max(m);
        float ls = 0.f;
        for (int j = lane; j < 220; j += 32) {
            float e = expf(S[r * 224 + j] - m);
            S[r * 224 + j] = e; ls += e;
        }
        ls = warp_sum(ls);
        if (lane == 0) sinv[r] = 1.f / ls;
    }
    __syncthreads();

    // PV: thread (qy = t>>4 in [0,14), dx = t&15): 2 queries x 4 dims
    if (t < 224) {
        int qy = t >> 4, dx = t & 15;
        float a00 = 0.f, a01 = 0.f, a02 = 0.f, a03 = 0.f;
        float a10 = 0.f, a11 = 0.f, a12 = 0.f, a13 = 0.f;
        const float* S0 = S + (qy * 2) * 224;
        const float* S1 = S0 + 224;
        #pragma unroll 4
        for (int j = 0; j < 220; j++) {
            float4 v = *reinterpret_cast<const float4*>(&Vs[j * 68 + dx * 4]);
            float p0 = S0[j], p1 = S1[j];
            a00 += p0 * v.x; a01 += p0 * v.y; a02 += p0 * v.z; a03 += p0 * v.w;
            a10 += p1 * v.x; a11 += p1 * v.y; a12 += p1 * v.z; a13 += p1 * v.w;
        }
        float i0 = sinv[qy * 2], i1 = sinv[qy * 2 + 1];
        int ti0 = NJx + fr * NPATCH + qbase + qy * 2;
        size_t o0 = ((size_t)(bb * NTOK + ti0)) * 512 + h * 64 + dx * 4;
        size_t o1 = o0 + 512;
        __nv_bfloat16 hi, lo;
        split2(a00 * i0, hi, lo); g_attn_hi[o0+0] = hi; g_attn_lo[o0+0] = lo;
        split2(a01 * i0, hi, lo); g_attn_hi[o0+1] = hi; g_attn_lo[o0+1] = lo;
        split2(a02 * i0, hi, lo); g_attn_hi[o0+2] = hi; g_attn_lo[o0+2] = lo;
        split2(a03 * i0, hi, lo); g_attn_hi[o0+3] = hi; g_attn_lo[o0+3] = lo;
        split2(a10 * i1, hi, lo); g_attn_hi[o1+0] = hi; g_attn_lo[o1+0] = lo;
        split2(a11 * i1, hi, lo); g_attn_hi[o1+1] = hi; g_attn_lo[o1+1] = lo;
        split2(a12 * i1, hi, lo); g_attn_hi[o1+2] = hi; g_attn_lo[o1+2] = lo;
        split2(a13 * i1, hi, lo); g_attn_hi[o1+3] = hi; g_attn_lo[o1+3] = lo;
    }
}

// ---------------- host helpers ----------------
template<int MT, int MODE>
static void launch_mma_t(const __nv_bfloat16* Ah, const __nv_bfloat16* Al,
                         const __nv_bfloat16* Bh, const __nv_bfloat16* Bl,
                         const float* bias, const float* res, float* C,
                         int M, int N, int K, int BIAS, int RES) {
    constexpr int SMEM = 3 * (MT * 5120 + 40960);
    dim3 grid(N / 256, (M + MT * 32 - 1) / (MT * 32));
    k_mma_gemm<MT, MODE><<<grid, 256, SMEM>>>(Ah, Al, Bh, Bl, bias, res, C, M, N, K, BIAS, RES);
}

extern "C" void kernel_launch(void* const* d_in, const int* in_sizes, int n_in,
                              void* d_out, int out_size) {
    const float* video        = (const float*)d_in[0];
    const float* patch_w      = (const float*)d_in[1];
    const float* patch_b      = (const float*)d_in[2];
    const float* joints_token = (const float*)d_in[3];
    const float* ln_attn_w    = (const float*)d_in[4];
    const float* ln_attn_b    = (const float*)d_in[5];
    const float* qkv_w        = (const float*)d_in[6];
    const float* attn_out_w   = (const float*)d_in[7];
    const float* attn_out_b   = (const float*)d_in[8];
    const float* ln_ff_w      = (const float*)d_in[9];
    const float* ln_ff_b      = (const float*)d_in[10];
    const float* ff1_w        = (const float*)d_in[11];
    const float* ff1_b        = (const float*)d_in[12];
    const float* ff2_w        = (const float*)d_in[13];
    const float* ff2_b        = (const float*)d_in[14];
    const float* ln_out_w     = (const float*)d_in[15];
    const float* ln_out_b     = (const float*)d_in[16];
    const float* out_w        = (const float*)d_in[17];
    const float* out_b        = (const float*)d_in[18];

    static bool attr_set = false;
    if (!attr_set) {
        cudaFuncSetAttribute(k_mma_gemm<4,0>, cudaFuncAttributeMaxDynamicSharedMemorySize, 3*(4*5120+40960));
        cudaFuncSetAttribute(k_mma_gemm<4,1>, cudaFuncAttributeMaxDynamicSharedMemorySize, 3*(4*5120+40960));
        cudaFuncSetAttribute(k_mma_gemm<2,0>, cudaFuncAttributeMaxDynamicSharedMemorySize, 3*(2*5120+40960));
        cudaFuncSetAttribute(k_frame_attn, cudaFuncAttributeMaxDynamicSharedMemorySize, FA3_BYTES);
        cudaFuncSetAttribute(k_joints_attn, cudaFuncAttributeMaxDynamicSharedMemorySize, JA_BYTES);
        attr_set = true;
    }

    float *px, *pqkv, *ptok, *pjt;
    cudaGetSymbolAddress((void**)&px,    g_x);
    cudaGetSymbolAddress((void**)&pqkv,  g_qkv);
    cudaGetSymbolAddress((void**)&ptok,  g_tok);
    cudaGetSymbolAddress((void**)&pjt,   g_jt);

    __nv_bfloat16 *xnh, *xnl, *hgh, *hgl, *pth, *ptl;
    __nv_bfloat16 *ath, *atl;
    cudaGetSymbolAddress((void**)&xnh, g_xn_hi);
    cudaGetSymbolAddress((void**)&xnl, g_xn_lo);
    cudaGetSymbolAddress((void**)&ath, g_attn_hi);
    cudaGetSymbolAddress((void**)&atl, g_attn_lo);
    cudaGetSymbolAddress((void**)&hgh, g_hg_hi);
    cudaGetSymbolAddress((void**)&hgl, g_hg_lo);
    cudaGetSymbolAddress((void**)&pth, g_pat_hi);
    cudaGetSymbolAddress((void**)&ptl, g_pat_lo);

    __nv_bfloat16 *patchThi, *patchTlo, *qkvThi, *qkvTlo, *outThi, *outTlo,
                  *ff1Thi, *ff1Tlo, *ff2Thi, *ff2Tlo;
    cudaGetSymbolAddress((void**)&patchThi, g_patchT_hi);
    cudaGetSymbolAddress((void**)&patchTlo, g_patchT_lo);
    cudaGetSymbolAddress((void**)&qkvThi,   g_qkvT_hi);
    cudaGetSymbolAddress((void**)&qkvTlo,   g_qkvT_lo);
    cudaGetSymbolAddress((void**)&outThi,   g_outT_hi);
    cudaGetSymbolAddress((void**)&outTlo,   g_outT_lo);
    cudaGetSymbolAddress((void**)&ff1Thi,   g_ff1T_hi);
    cudaGetSymbolAddress((void**)&ff1Tlo,   g_ff1T_lo);
    cudaGetSymbolAddress((void**)&ff2Thi,   g_ff2T_hi);
    cudaGetSymbolAddress((void**)&ff2Tlo,   g_ff2T_lo);

    // ---- weight prep (batched over layers) ----
    k_wprep<<<dim3(16, 16, 1), 256>>>(patch_w, patchThi, patchTlo, 512, 512);
    k_wprep<<<dim3(48, 16, 12), 256>>>(qkv_w, qkvThi, qkvTlo, 512, 1536);
    k_wprep<<<dim3(16, 16, 12), 256>>>(attn_out_w, outThi, outTlo, 512, 512);
    k_wprep_ff1<<<dim3(128, 16, 12), 256>>>(ff1_w, ff1Thi, ff1Tlo);
    k_wprep<<<dim3(16, 64, 12), 256>>>(ff2_w, ff2Thi, ff2Tlo, 2048, 512);

    // ---- setup ----
    k_sincos<<<(NPATCH * 32 + 255) / 256, 256>>>();
    k_im2col<<<(int)(((size_t)B_ * NSP * DIMC + 255) / 256), 256>>>(video);
    launch_mma_t<4,0>(pth, ptl, patchThi, patchTlo, patch_b, nullptr, ptok,
                      B_ * NSP, DIMC, DIMC, 1, 0);
    k_assemble<<<(int)(((size_t)B_ * NTOK * DIMC + 255) / 256), 256>>>(joints_token);

    for (int l = 0; l < 12; l++) {
        k_ln<<<ROWS, 256>>>(px, ln_attn_w + l * 512, ln_attn_b + l * 512, xnh, xnl);
        launch_mma_t<4,0>(xnh, xnl, qkvThi + (size_t)l * 1536 * 512, qkvTlo + (size_t)l * 1536 * 512,
                          nullptr, nullptr, pqkv, ROWS, 1536, 512, 0, 0);
        k_joints_attn<<<dim3(6, 16), 256, JA_BYTES>>>();
        k_frame_attn<<<dim3(7, 256), 256, FA3_BYTES>>>();
        launch_mma_t<2,0>(ath, atl, outThi + (size_t)l * 512 * 512, outTlo + (size_t)l * 512 * 512,
                          attn_out_b + l * 512, px, px, ROWS, 512, 512, 1, 1);
        k_ln<<<ROWS, 256>>>(px, ln_ff_w + l * 512, ln_ff_b + l * 512, xnh, xnl);
        launch_mma_t<4,1>(xnh, xnl, ff1Thi + (size_t)l * 4096 * 512, ff1Tlo + (size_t)l * 4096 * 512,
                          ff1_b + (size_t)l * 4096, nullptr, nullptr, ROWS, 4096, 512, 1, 0);
        launch_mma_t<2,0>(hgh, hgl, ff2Thi + (size_t)l * 512 * 2048, ff2Tlo + (size_t)l * 512 * 2048,
                          ff2_b + l * 512, px, px, ROWS, 512, 2048, 1, 1);
    }

    // ---- head ----
    k_ln_gather<<<48, 256>>>(ln_out_w, ln_out_b);
    {
        dim3 grid(384 / 128, 1);
        k_sgemm<1, 0><<<grid, 256>>>(pjt, out_w, out_b, nullptr, (float*)d_out, 48, 384, 512);
    }
}